// round 1
// baseline (speedup 1.0000x reference)
#include <cuda_runtime.h>
#include <cstdint>

#define BATCH 32
#define NN    1024
#define DD    128
#define LL    2
#define MTOT  (BATCH * NN)          // 32768
#define BN_EPS 1e-5f

// ---------------- scratch (no allocation allowed) ----------------
__device__ float g_bufP[BATCH * NN * DD];   // pooled / y
__device__ float g_bufZ[BATCH * NN * DD];   // z
__device__ float g_bufH[BATCH * NN * DD];   // h between layers
#define BN_BLOCKS 128                       // 32768 / 256 rows per block
__device__ float g_partS[BN_BLOCKS * DD];
__device__ float g_partQ[BN_BLOCKS * DD];
__device__ float g_scale[DD];
__device__ float g_shift[DD];

// ---------------- GEMM 1: pooled[b] = adj[b] @ h[b] ----------------
// adj: [B, N, N] row-major, h: [B, N, D]. M=N=1024 rows, K=1024, 128 cols.
// Block: 64 rows x 128 cols, 256 threads, each thread 8x4 micro-tile. BK=32.
__global__ __launch_bounds__(256)
void gemm_pool_kernel(const float* __restrict__ adj,
                      const float* __restrict__ hin,
                      float* __restrict__ out) {
    const int b    = blockIdx.y;
    const int row0 = blockIdx.x * 64;

    const float* A  = adj + (size_t)b * NN * NN;
    const float* Bm = hin + (size_t)b * NN * DD;

    __shared__ float sA[64][32];
    __shared__ float sB[32][DD];

    const int tid = threadIdx.x;
    const int tc  = tid & 31;   // col group (4 cols each)
    const int tr  = tid >> 5;   // row group (8 rows each) -- constant per warp

    float acc[8][4];
#pragma unroll
    for (int i = 0; i < 8; i++)
#pragma unroll
        for (int j = 0; j < 4; j++) acc[i][j] = 0.f;

    for (int k0 = 0; k0 < NN; k0 += 32) {
        // A tile 64x32: 2048 floats, 8 per thread, coalesced
#pragma unroll
        for (int t = 0; t < 8; t++) {
            int idx = tid + t * 256;
            sA[idx >> 5][idx & 31] = A[(size_t)(row0 + (idx >> 5)) * NN + k0 + (idx & 31)];
        }
        // B tile 32x128: 4096 floats, 16 per thread, coalesced
#pragma unroll
        for (int t = 0; t < 16; t++) {
            int idx = tid + t * 256;
            sB[idx >> 7][idx & 127] = Bm[(size_t)(k0 + (idx >> 7)) * DD + (idx & 127)];
        }
        __syncthreads();

#pragma unroll
        for (int k = 0; k < 32; k++) {
            float a[8];
#pragma unroll
            for (int i = 0; i < 8; i++) a[i] = sA[tr * 8 + i][k];  // broadcast in warp
            float4 bv = *reinterpret_cast<const float4*>(&sB[k][tc * 4]);
#pragma unroll
            for (int i = 0; i < 8; i++) {
                acc[i][0] = fmaf(a[i], bv.x, acc[i][0]);
                acc[i][1] = fmaf(a[i], bv.y, acc[i][1]);
                acc[i][2] = fmaf(a[i], bv.z, acc[i][2]);
                acc[i][3] = fmaf(a[i], bv.w, acc[i][3]);
            }
        }
        __syncthreads();
    }

    float* O = out + (size_t)b * NN * DD;
#pragma unroll
    for (int i = 0; i < 8; i++) {
        float4 v = make_float4(acc[i][0], acc[i][1], acc[i][2], acc[i][3]);
        *reinterpret_cast<float4*>(&O[(size_t)(row0 + tr * 8 + i) * DD + tc * 4]) = v;
    }
}

// ---------------- GEMM 2: out = in @ W + bias ----------------
// in: [MTOT, 128], W: [128, 128], bias: [128]. Same tiling, K=128.
__global__ __launch_bounds__(256)
void gemm_w_kernel(const float* __restrict__ in,
                   const float* __restrict__ W,
                   const float* __restrict__ bias,
                   float* __restrict__ out) {
    const int row0 = blockIdx.x * 64;

    __shared__ float sA[64][32];
    __shared__ float sB[32][DD];

    const int tid = threadIdx.x;
    const int tc  = tid & 31;
    const int tr  = tid >> 5;

    float acc[8][4];
#pragma unroll
    for (int i = 0; i < 8; i++)
#pragma unroll
        for (int j = 0; j < 4; j++) acc[i][j] = 0.f;

    for (int k0 = 0; k0 < DD; k0 += 32) {
#pragma unroll
        for (int t = 0; t < 8; t++) {
            int idx = tid + t * 256;
            sA[idx >> 5][idx & 31] = in[(size_t)(row0 + (idx >> 5)) * DD + k0 + (idx & 31)];
        }
#pragma unroll
        for (int t = 0; t < 16; t++) {
            int idx = tid + t * 256;
            sB[idx >> 7][idx & 127] = W[(size_t)(k0 + (idx >> 7)) * DD + (idx & 127)];
        }
        __syncthreads();

#pragma unroll
        for (int k = 0; k < 32; k++) {
            float a[8];
#pragma unroll
            for (int i = 0; i < 8; i++) a[i] = sA[tr * 8 + i][k];
            float4 bv = *reinterpret_cast<const float4*>(&sB[k][tc * 4]);
#pragma unroll
            for (int i = 0; i < 8; i++) {
                acc[i][0] = fmaf(a[i], bv.x, acc[i][0]);
                acc[i][1] = fmaf(a[i], bv.y, acc[i][1]);
                acc[i][2] = fmaf(a[i], bv.z, acc[i][2]);
                acc[i][3] = fmaf(a[i], bv.w, acc[i][3]);
            }
        }
        __syncthreads();
    }

    float4 bb = *reinterpret_cast<const float4*>(&bias[tc * 4]);
#pragma unroll
    for (int i = 0; i < 8; i++) {
        float4 v = make_float4(acc[i][0] + bb.x, acc[i][1] + bb.y,
                               acc[i][2] + bb.z, acc[i][3] + bb.w);
        *reinterpret_cast<float4*>(&out[(size_t)(row0 + tr * 8 + i) * DD + tc * 4]) = v;
    }
}

// ---------------- BN stage 1: per-block partial column sums ----------------
// grid = BN_BLOCKS blocks of 128 threads; block p handles rows [p*256, p*256+256).
__global__ __launch_bounds__(128)
void bn_partial_kernel(const float* __restrict__ x) {
    const int col = threadIdx.x;
    const int p   = blockIdx.x;
    const int r0  = p * (MTOT / BN_BLOCKS);
    float s = 0.f, q = 0.f;
#pragma unroll 4
    for (int r = 0; r < MTOT / BN_BLOCKS; r++) {
        float v = x[(size_t)(r0 + r) * DD + col];
        s += v;
        q = fmaf(v, v, q);
    }
    g_partS[p * DD + col] = s;
    g_partQ[p * DD + col] = q;
}

// ---------------- BN stage 2: finalize scale/shift (deterministic) ----------
__global__ __launch_bounds__(128)
void bn_finalize_kernel(const float* __restrict__ gamma,
                        const float* __restrict__ beta) {
    const int col = threadIdx.x;
    float s = 0.f, q = 0.f;
#pragma unroll 8
    for (int p = 0; p < BN_BLOCKS; p++) {
        s += g_partS[p * DD + col];
        q += g_partQ[p * DD + col];
    }
    const float inv_m = 1.0f / (float)MTOT;
    float mean = s * inv_m;
    float var  = q * inv_m - mean * mean;
    float sc   = gamma[col] * rsqrtf(var + BN_EPS);
    g_scale[col] = sc;
    g_shift[col] = beta[col] - mean * sc;
}

// ---------------- BN apply + ReLU ----------------
__global__ __launch_bounds__(256)
void bn_apply_kernel(const float* __restrict__ x, float* __restrict__ out) {
    const int idx = blockIdx.x * 256 + threadIdx.x;     // float4 index
    const int c4  = idx & 31;                           // float4 column group
    float4 v  = reinterpret_cast<const float4*>(x)[idx];
    float4 sc = reinterpret_cast<const float4*>(g_scale)[c4];
    float4 sh = reinterpret_cast<const float4*>(g_shift)[c4];
    float4 r;
    r.x = fmaxf(fmaf(v.x, sc.x, sh.x), 0.f);
    r.y = fmaxf(fmaf(v.y, sc.y, sh.y), 0.f);
    r.z = fmaxf(fmaf(v.z, sc.z, sh.z), 0.f);
    r.w = fmaxf(fmaf(v.w, sc.w, sh.w), 0.f);
    reinterpret_cast<float4*>(out)[idx] = r;
}

// ---------------- launch ----------------
extern "C" void kernel_launch(void* const* d_in, const int* in_sizes, int n_in,
                              void* d_out, int out_size) {
    const float* x    = (const float*)d_in[0];
    // d_in[1] = padded_nei (int64) -- unused by reference math
    const float* adj  = (const float*)d_in[2];
    const float* W1   = (const float*)d_in[3];
    const float* b1   = (const float*)d_in[4];
    const float* W2   = (const float*)d_in[5];
    const float* b2   = (const float*)d_in[6];
    const float* g_in  = (const float*)d_in[7];
    const float* be_in = (const float*)d_in[8];
    const float* g_out = (const float*)d_in[9];
    const float* be_out= (const float*)d_in[10];
    float* out = (float*)d_out;

    float *bufP, *bufZ, *bufH;
    cudaGetSymbolAddress((void**)&bufP, g_bufP);
    cudaGetSymbolAddress((void**)&bufZ, g_bufZ);
    cudaGetSymbolAddress((void**)&bufH, g_bufH);

    const dim3 gridPool(NN / 64, BATCH);
    const int  gridW   = MTOT / 64;
    const int  gridApp = (MTOT * DD) / (256 * 4);

    for (int l = 0; l < LL; l++) {
        const float* hin = (l == 0) ? x : bufH;
        float* hout      = (l == LL - 1) ? out : bufH;

        // pooled = adj @ h
        gemm_pool_kernel<<<gridPool, 256>>>(adj, hin, bufP);
        // z = pooled @ W1[l] + b1[l]
        gemm_w_kernel<<<gridW, 256>>>(bufP, W1 + (size_t)l * DD * DD, b1 + (size_t)l * DD, bufZ);
        // inner BN + ReLU -> bufP (reused as y)
        bn_partial_kernel<<<BN_BLOCKS, 128>>>(bufZ);
        bn_finalize_kernel<<<1, 128>>>(g_in + (size_t)l * DD, be_in + (size_t)l * DD);
        bn_apply_kernel<<<gridApp, 256>>>(bufZ, bufP);
        // z2 = y @ W2[l] + b2[l]
        gemm_w_kernel<<<gridW, 256>>>(bufP, W2 + (size_t)l * DD * DD, b2 + (size_t)l * DD, bufZ);
        // outer BN + ReLU -> h (or final output)
        bn_partial_kernel<<<BN_BLOCKS, 128>>>(bufZ);
        bn_finalize_kernel<<<1, 128>>>(g_out + (size_t)l * DD, be_out + (size_t)l * DD);
        bn_apply_kernel<<<gridApp, 256>>>(bufZ, hout);
    }
}

// round 3
// speedup vs baseline: 1.4118x; 1.4118x over previous
#include <cuda_runtime.h>
#include <cuda_bf16.h>
#include <cstdint>

#define BATCH 32
#define NN    1024
#define DD    128
#define LL    2
#define MTOT  (BATCH * NN)
#define BN_EPS 1e-5f
#define BN_BLOCKS 256

// ---------------- scratch (no allocation allowed) ----------------
__device__ float g_bufP[MTOT * DD];
__device__ float g_bufZ[MTOT * DD];
__device__ float g_bufH[MTOT * DD];
__device__ __nv_bfloat16 g_hT_hi[BATCH * DD * NN];
__device__ __nv_bfloat16 g_hT_lo[BATCH * DD * NN];
__device__ __nv_bfloat16 g_WT_hi[DD * DD];
__device__ __nv_bfloat16 g_WT_lo[DD * DD];
__device__ float g_partS[BN_BLOCKS * DD];
__device__ float g_partQ[BN_BLOCKS * DD];
__device__ float g_scale[DD];
__device__ float g_shift[DD];

// ---------------- helpers ----------------
__device__ __forceinline__ uint32_t smem_u32(const void* p) {
    uint32_t a;
    asm("{ .reg .u64 t; cvta.to.shared.u64 t, %1; cvt.u32.u64 %0, t; }" : "=r"(a) : "l"(p));
    return a;
}
__device__ __forceinline__ void ldsm_x4(uint32_t* r, uint32_t addr) {
    asm volatile("ldmatrix.sync.aligned.m8n8.x4.shared.b16 {%0,%1,%2,%3}, [%4];"
                 : "=r"(r[0]), "=r"(r[1]), "=r"(r[2]), "=r"(r[3]) : "r"(addr));
}
__device__ __forceinline__ void mma_bf16(float* c, const uint32_t* a, const uint32_t* b) {
    asm volatile(
        "mma.sync.aligned.m16n8k16.row.col.f32.bf16.bf16.f32 "
        "{%0,%1,%2,%3}, {%4,%5,%6,%7}, {%8,%9}, {%0,%1,%2,%3};"
        : "+f"(c[0]), "+f"(c[1]), "+f"(c[2]), "+f"(c[3])
        : "r"(a[0]), "r"(a[1]), "r"(a[2]), "r"(a[3]), "r"(b[0]), "r"(b[1]));
}
__device__ __forceinline__ void cp_async16(uint32_t dst, const void* src) {
    asm volatile("cp.async.cg.shared.global [%0], [%1], 16;" :: "r"(dst), "l"(src));
}
#define CP_COMMIT() asm volatile("cp.async.commit_group;" ::: "memory")
#define CP_WAIT0()  asm volatile("cp.async.wait_group 0;"  ::: "memory")

__device__ __forceinline__ uint32_t pack_bf16(float x, float y) {
    __nv_bfloat162 t = __floats2bfloat162_rn(x, y);
    return *reinterpret_cast<uint32_t*>(&t);
}

// SMEM layout (per stage): padded rows of 72 bf16 = 144 bytes
#define ROWB 144
#define OFF_AHI 0
#define OFF_ALO 18432
#define OFF_BHI 36864
#define OFF_BLO 55296
#define STAGE_BYTES 73728
#define GEMM_SMEM (2 * STAGE_BYTES)

// ---------------- transpose + split-bf16 kernel ----------------
__global__ __launch_bounds__(256)
void transpose_split_kernel(const float* __restrict__ in,
                            __nv_bfloat16* __restrict__ ohi,
                            __nv_bfloat16* __restrict__ olo,
                            int R, int C) {
    const int b = blockIdx.z;
    in  += (size_t)b * R * C;
    ohi += (size_t)b * R * C;
    olo += (size_t)b * R * C;
    __shared__ float t[32][33];
    const int r0 = blockIdx.x * 32, c0 = blockIdx.y * 32;
    const int tx = threadIdx.x, ty = threadIdx.y;
#pragma unroll
    for (int i = ty; i < 32; i += 8)
        t[i][tx] = in[(size_t)(r0 + i) * C + c0 + tx];
    __syncthreads();
#pragma unroll
    for (int i = ty; i < 32; i += 8) {
        float v = t[tx][i];
        __nv_bfloat16 hi = __float2bfloat16(v);
        __nv_bfloat16 lo = __float2bfloat16(v - __bfloat162float(hi));
        size_t o = (size_t)(c0 + i) * R + r0 + tx;
        ohi[o] = hi;
        olo[o] = lo;
    }
}

// ---------------- split-bf16 mma.sync GEMM ----------------
// out[m,n] = sum_k A[m,k]*B^T[n,k] (+bias). A fp32 (split on the fly),
// Bhi/Blo bf16 [128, KTOT] n-major (row n, k contiguous).
// CTA 128x128, 512 thr, 16 warps as 4(m) x 4(n), warp tile 32x32, Kc=64.
template <bool POOL>
__global__ __launch_bounds__(512)
void gemm_mma_kernel(const float* __restrict__ A,
                     const __nv_bfloat16* __restrict__ Bhi,
                     const __nv_bfloat16* __restrict__ Blo,
                     const float* __restrict__ bias,
                     float* __restrict__ out) {
    constexpr int KTOT = POOL ? NN : DD;
    constexpr int LDA  = POOL ? NN : DD;
    constexpr int NC   = KTOT / 64;

    if (POOL) {
        A   += (size_t)blockIdx.y * NN * NN + (size_t)blockIdx.x * 128 * NN;
        Bhi += (size_t)blockIdx.y * DD * NN;
        Blo += (size_t)blockIdx.y * DD * NN;
        out += (size_t)blockIdx.y * NN * DD + (size_t)blockIdx.x * 128 * DD;
    } else {
        A   += (size_t)blockIdx.x * 128 * DD;
        out += (size_t)blockIdx.x * 128 * DD;
    }

    extern __shared__ char smem[];
    const uint32_t sbase = smem_u32(smem);

    const int tid  = threadIdx.x;
    const int lane = tid & 31;
    const int wid  = tid >> 5;
    const int wm   = wid & 3;   // warp row (32 rows)
    const int wn   = wid >> 2;  // warp col (32 cols)

    float acc[2][4][4];
#pragma unroll
    for (int i = 0; i < 2; i++)
#pragma unroll
        for (int j = 0; j < 4; j++)
#pragma unroll
            for (int k = 0; k < 4; k++) acc[i][j][k] = 0.f;

    // per-thread A load mapping: 4 x float4, idx = tid + p*512
    const int aRow[4] = { (tid) >> 4, (tid + 512) >> 4, (tid + 1024) >> 4, (tid + 1536) >> 4 };
    const int aSeg = tid & 15;

    // ldmatrix address components
    const int sub   = lane >> 3;
    const int r8    = lane & 7;
    const uint32_t rowA = wm * 32 + (sub & 1) * 8 + r8;
    const uint32_t colA = (sub >> 1) * 8;
    const uint32_t rowBm = wn * 32 + (sub >> 1) * 8 + r8;
    const uint32_t colBm = (sub & 1) * 8;

    // ---- prologue: chunk 0 into stage 0 ----
    {
        const uint32_t st = sbase;
        // B via cp.async
#pragma unroll
        for (int p = 0; p < 4; p++) {
            int i = tid + p * 512;
            int arr = i >> 10, rem = i & 1023, row = rem >> 3, ch = rem & 7;
            const __nv_bfloat16* src = (arr ? Blo : Bhi) + (size_t)row * KTOT + ch * 8;
            cp_async16(st + (arr ? OFF_BLO : OFF_BHI) + row * ROWB + ch * 16, src);
        }
        CP_COMMIT();
        // A via LDG + convert + STS
#pragma unroll
        for (int p = 0; p < 4; p++) {
            float4 v = *reinterpret_cast<const float4*>(A + (size_t)aRow[p] * LDA + aSeg * 4);
            __nv_bfloat16 h0 = __float2bfloat16(v.x), h1 = __float2bfloat16(v.y);
            __nv_bfloat16 h2 = __float2bfloat16(v.z), h3 = __float2bfloat16(v.w);
            uint2 hv, lv;
            hv.x = pack_bf16(v.x, v.y); hv.y = pack_bf16(v.z, v.w);
            lv.x = pack_bf16(v.x - __bfloat162float(h0), v.y - __bfloat162float(h1));
            lv.y = pack_bf16(v.z - __bfloat162float(h2), v.w - __bfloat162float(h3));
            char* d = smem + aRow[p] * ROWB + aSeg * 8;
            *reinterpret_cast<uint2*>(d + OFF_AHI) = hv;
            *reinterpret_cast<uint2*>(d + OFF_ALO) = lv;
        }
        CP_WAIT0();
        __syncthreads();
    }

    for (int c = 0; c < NC; c++) {
        const uint32_t cur = sbase + (uint32_t)(c & 1) * STAGE_BYTES;
        const uint32_t nxtOff = (uint32_t)((c + 1) & 1) * STAGE_BYTES;
        const uint32_t nxt = sbase + nxtOff;

        float4 aN[4];
        if (c + 1 < NC) {
            // issue next-chunk global loads early
#pragma unroll
            for (int p = 0; p < 4; p++)
                aN[p] = *reinterpret_cast<const float4*>(
                    A + (size_t)aRow[p] * LDA + (c + 1) * 64 + aSeg * 4);
#pragma unroll
            for (int p = 0; p < 4; p++) {
                int i = tid + p * 512;
                int arr = i >> 10, rem = i & 1023, row = rem >> 3, ch = rem & 7;
                const __nv_bfloat16* src = (arr ? Blo : Bhi) + (size_t)row * KTOT + (c + 1) * 64 + ch * 8;
                cp_async16(nxt + (arr ? OFF_BLO : OFF_BHI) + row * ROWB + ch * 16, src);
            }
            CP_COMMIT();
        }

        // ---- compute chunk c ----
#pragma unroll
        for (int ks = 0; ks < 4; ks++) {
            uint32_t ah[2][4], al[2][4];
#pragma unroll
            for (int mb = 0; mb < 2; mb++) {
                uint32_t ad = cur + (rowA + mb * 16) * ROWB + (ks * 16 + colA) * 2;
                ldsm_x4(ah[mb], ad + OFF_AHI);
                ldsm_x4(al[mb], ad + OFF_ALO);
            }
            uint32_t bh[2][4], bl[2][4];
#pragma unroll
            for (int nb2 = 0; nb2 < 2; nb2++) {
                uint32_t bd = cur + (rowBm + nb2 * 16) * ROWB + (ks * 16 + colBm) * 2;
                ldsm_x4(bh[nb2], bd + OFF_BHI);
                ldsm_x4(bl[nb2], bd + OFF_BLO);
            }
#pragma unroll
            for (int mb = 0; mb < 2; mb++)
#pragma unroll
                for (int nb = 0; nb < 4; nb++) {
                    const uint32_t* bhp = &bh[nb >> 1][(nb & 1) * 2];
                    const uint32_t* blp = &bl[nb >> 1][(nb & 1) * 2];
                    mma_bf16(acc[mb][nb], ah[mb], bhp);
                    mma_bf16(acc[mb][nb], ah[mb], blp);
                    mma_bf16(acc[mb][nb], al[mb], bhp);
                }
        }

        if (c + 1 < NC) {
            // convert + store next A
#pragma unroll
            for (int p = 0; p < 4; p++) {
                float4 v = aN[p];
                __nv_bfloat16 h0 = __float2bfloat16(v.x), h1 = __float2bfloat16(v.y);
                __nv_bfloat16 h2 = __float2bfloat16(v.z), h3 = __float2bfloat16(v.w);
                uint2 hv, lv;
                hv.x = pack_bf16(v.x, v.y); hv.y = pack_bf16(v.z, v.w);
                lv.x = pack_bf16(v.x - __bfloat162float(h0), v.y - __bfloat162float(h1));
                lv.y = pack_bf16(v.z - __bfloat162float(h2), v.w - __bfloat162float(h3));
                char* d = smem + nxtOff + aRow[p] * ROWB + aSeg * 8;
                *reinterpret_cast<uint2*>(d + OFF_AHI) = hv;
                *reinterpret_cast<uint2*>(d + OFF_ALO) = lv;
            }
        }
        CP_WAIT0();
        __syncthreads();
    }

    // ---- epilogue ----
    const int er = lane >> 2;
    const int ec = (lane & 3) * 2;
#pragma unroll
    for (int mb = 0; mb < 2; mb++)
#pragma unroll
        for (int nb = 0; nb < 4; nb++) {
            int row = wm * 32 + mb * 16 + er;
            int col = wn * 32 + nb * 8 + ec;
            float2 v0 = make_float2(acc[mb][nb][0], acc[mb][nb][1]);
            float2 v1 = make_float2(acc[mb][nb][2], acc[mb][nb][3]);
            if (!POOL) {
                float bx = bias[col], by = bias[col + 1];
                v0.x += bx; v0.y += by; v1.x += bx; v1.y += by;
            }
            *reinterpret_cast<float2*>(out + (size_t)row * DD + col) = v0;
            *reinterpret_cast<float2*>(out + (size_t)(row + 8) * DD + col) = v1;
        }
}

// ---------------- BN stage 1 ----------------
__global__ __launch_bounds__(128)
void bn_partial_kernel(const float* __restrict__ x) {
    const int col = threadIdx.x;
    const int p = blockIdx.x;
    const int r0 = p * (MTOT / BN_BLOCKS);
    float s = 0.f, q = 0.f;
#pragma unroll 8
    for (int r = 0; r < MTOT / BN_BLOCKS; r++) {
        float v = x[(size_t)(r0 + r) * DD + col];
        s += v;
        q = fmaf(v, v, q);
    }
    g_partS[p * DD + col] = s;
    g_partQ[p * DD + col] = q;
}

// ---------------- BN stage 2 ----------------
__global__ __launch_bounds__(1024)
void bn_finalize_kernel(const float* __restrict__ gamma,
                        const float* __restrict__ beta) {
    __shared__ float rs[8][DD], rq[8][DD];
    const int col = threadIdx.x, j = threadIdx.y;
    float s = 0.f, q = 0.f;
#pragma unroll
    for (int p = j; p < BN_BLOCKS; p += 8) {
        s += g_partS[p * DD + col];
        q += g_partQ[p * DD + col];
    }
    rs[j][col] = s;
    rq[j][col] = q;
    __syncthreads();
    if (j == 0) {
#pragma unroll
        for (int jj = 1; jj < 8; jj++) { s += rs[jj][col]; q += rq[jj][col]; }
        const float inv_m = 1.0f / (float)MTOT;
        float mean = s * inv_m;
        float var = q * inv_m - mean * mean;
        float sc = gamma[col] * rsqrtf(var + BN_EPS);
        g_scale[col] = sc;
        g_shift[col] = beta[col] - mean * sc;
    }
}

// ---------------- BN apply + ReLU ----------------
__global__ __launch_bounds__(256)
void bn_apply_kernel(const float* __restrict__ x, float* __restrict__ out) {
    const int idx = blockIdx.x * 256 + threadIdx.x;
    const int c4 = idx & 31;
    float4 v = reinterpret_cast<const float4*>(x)[idx];
    float4 sc = reinterpret_cast<const float4*>(g_scale)[c4];
    float4 sh = reinterpret_cast<const float4*>(g_shift)[c4];
    float4 r;
    r.x = fmaxf(fmaf(v.x, sc.x, sh.x), 0.f);
    r.y = fmaxf(fmaf(v.y, sc.y, sh.y), 0.f);
    r.z = fmaxf(fmaf(v.z, sc.z, sh.z), 0.f);
    r.w = fmaxf(fmaf(v.w, sc.w, sh.w), 0.f);
    reinterpret_cast<float4*>(out)[idx] = r;
}

// ---------------- launch ----------------
extern "C" void kernel_launch(void* const* d_in, const int* in_sizes, int n_in,
                              void* d_out, int out_size) {
    const float* x     = (const float*)d_in[0];
    const float* adj   = (const float*)d_in[2];
    const float* W1    = (const float*)d_in[3];
    const float* b1    = (const float*)d_in[4];
    const float* W2    = (const float*)d_in[5];
    const float* b2    = (const float*)d_in[6];
    const float* g_in   = (const float*)d_in[7];
    const float* be_in  = (const float*)d_in[8];
    const float* g_out  = (const float*)d_in[9];
    const float* be_out = (const float*)d_in[10];
    float* out = (float*)d_out;

    float *bufP, *bufZ, *bufH;
    __nv_bfloat16 *hT_hi, *hT_lo, *WT_hi, *WT_lo;
    cudaGetSymbolAddress((void**)&bufP, g_bufP);
    cudaGetSymbolAddress((void**)&bufZ, g_bufZ);
    cudaGetSymbolAddress((void**)&bufH, g_bufH);
    cudaGetSymbolAddress((void**)&hT_hi, g_hT_hi);
    cudaGetSymbolAddress((void**)&hT_lo, g_hT_lo);
    cudaGetSymbolAddress((void**)&WT_hi, g_WT_hi);
    cudaGetSymbolAddress((void**)&WT_lo, g_WT_lo);

    cudaFuncSetAttribute(gemm_mma_kernel<true>,  cudaFuncAttributeMaxDynamicSharedMemorySize, GEMM_SMEM);
    cudaFuncSetAttribute(gemm_mma_kernel<false>, cudaFuncAttributeMaxDynamicSharedMemorySize, GEMM_SMEM);

    const dim3 tBlk(32, 8);
    const dim3 gridHT(NN / 32, DD / 32, BATCH);
    const dim3 gridWT(DD / 32, DD / 32, 1);
    const dim3 gridPool(NN / 128, BATCH);
    const int  gridW = MTOT / 128;
    const int  gridApp = (MTOT * DD) / (256 * 4);
    const dim3 finBlk(DD, 8);

    for (int l = 0; l < LL; l++) {
        const float* hin = (l == 0) ? x : bufH;
        float* hout = (l == LL - 1) ? out : bufH;

        transpose_split_kernel<<<gridHT, tBlk>>>(hin, hT_hi, hT_lo, NN, DD);
        gemm_mma_kernel<true><<<gridPool, 512, GEMM_SMEM>>>(adj, hT_hi, hT_lo, nullptr, bufP);

        transpose_split_kernel<<<gridWT, tBlk>>>(W1 + (size_t)l * DD * DD, WT_hi, WT_lo, DD, DD);
        gemm_mma_kernel<false><<<gridW, 512, GEMM_SMEM>>>(bufP, WT_hi, WT_lo, b1 + (size_t)l * DD, bufZ);

        bn_partial_kernel<<<BN_BLOCKS, 128>>>(bufZ);
        bn_finalize_kernel<<<1, finBlk>>>(g_in + (size_t)l * DD, be_in + (size_t)l * DD);
        bn_apply_kernel<<<gridApp, 256>>>(bufZ, bufP);

        transpose_split_kernel<<<gridWT, tBlk>>>(W2 + (size_t)l * DD * DD, WT_hi, WT_lo, DD, DD);
        gemm_mma_kernel<false><<<gridW, 512, GEMM_SMEM>>>(bufP, WT_hi, WT_lo, b2 + (size_t)l * DD, bufZ);

        bn_partial_kernel<<<BN_BLOCKS, 128>>>(bufZ);
        bn_finalize_kernel<<<1, finBlk>>>(g_out + (size_t)l * DD, be_out + (size_t)l * DD);
        bn_apply_kernel<<<gridApp, 256>>>(bufZ, hout);
    }
}

// round 5
// speedup vs baseline: 2.1936x; 1.5537x over previous
#include <cuda_runtime.h>
#include <cuda_bf16.h>
#include <cstdint>

#define BATCH 32
#define NN    1024
#define DD    128
#define LL    2
#define MTOT  (BATCH * NN)
#define BN_EPS 1e-5f
#define BN_BLOCKS 256

// ---------------- scratch (no allocation allowed) ----------------
__device__ __nv_bfloat16 g_adjHi[(size_t)BATCH * NN * NN];
__device__ __nv_bfloat16 g_adjLo[(size_t)BATCH * NN * NN];
__device__ __nv_bfloat16 g_hHi[MTOT * DD];
__device__ __nv_bfloat16 g_hLo[MTOT * DD];
__device__ __nv_bfloat16 g_pHi[MTOT * DD];
__device__ __nv_bfloat16 g_pLo[MTOT * DD];
__device__ __nv_bfloat16 g_yHi[MTOT * DD];
__device__ __nv_bfloat16 g_yLo[MTOT * DD];
__device__ __nv_bfloat16 g_W1Hi[LL * DD * DD];
__device__ __nv_bfloat16 g_W1Lo[LL * DD * DD];
__device__ __nv_bfloat16 g_W2Hi[LL * DD * DD];
__device__ __nv_bfloat16 g_W2Lo[LL * DD * DD];
__device__ float g_z[MTOT * DD];
__device__ float g_partS[BN_BLOCKS * DD];
__device__ float g_partQ[BN_BLOCKS * DD];
__device__ float g_scale[DD];
__device__ float g_shift[DD];

// ---------------- helpers ----------------
__device__ __forceinline__ uint32_t smem_u32(const void* p) {
    uint32_t a;
    asm("{ .reg .u64 t; cvta.to.shared.u64 t, %1; cvt.u32.u64 %0, t; }" : "=r"(a) : "l"(p));
    return a;
}
__device__ __forceinline__ void ldsm_x4(uint32_t* r, uint32_t addr) {
    asm volatile("ldmatrix.sync.aligned.m8n8.x4.shared.b16 {%0,%1,%2,%3}, [%4];"
                 : "=r"(r[0]), "=r"(r[1]), "=r"(r[2]), "=r"(r[3]) : "r"(addr));
}
__device__ __forceinline__ void ldsm_x4_t(uint32_t* r, uint32_t addr) {
    asm volatile("ldmatrix.sync.aligned.m8n8.x4.trans.shared.b16 {%0,%1,%2,%3}, [%4];"
                 : "=r"(r[0]), "=r"(r[1]), "=r"(r[2]), "=r"(r[3]) : "r"(addr));
}
__device__ __forceinline__ void mma_bf16(float* c, const uint32_t* a, const uint32_t* b) {
    asm volatile(
        "mma.sync.aligned.m16n8k16.row.col.f32.bf16.bf16.f32 "
        "{%0,%1,%2,%3}, {%4,%5,%6,%7}, {%8,%9}, {%0,%1,%2,%3};"
        : "+f"(c[0]), "+f"(c[1]), "+f"(c[2]), "+f"(c[3])
        : "r"(a[0]), "r"(a[1]), "r"(a[2]), "r"(a[3]), "r"(b[0]), "r"(b[1]));
}
__device__ __forceinline__ void cp_async16(uint32_t dst, const void* src) {
    asm volatile("cp.async.cg.shared.global [%0], [%1], 16;" :: "r"(dst), "l"(src));
}
#define CP_COMMIT() asm volatile("cp.async.commit_group;" ::: "memory")
#define CP_WAIT1()  asm volatile("cp.async.wait_group 1;"  ::: "memory")

__device__ __forceinline__ uint32_t pack_bf16(float x, float y) {
    __nv_bfloat162 t = __floats2bfloat162_rn(x, y);
    return *reinterpret_cast<uint32_t*>(&t);
}

// ---------------- unified split-bf16 mma.sync GEMM ----------------
// out[m,n] = sum_k A[m,k]*B[k,n] (+bias). A: [.,KA] bf16 hi(/lo), row stride KA.
// B: [KA,128] bf16 hi(/lo), row stride 128 (k-major; loaded w/ ldmatrix.trans).
// CTA 128x128, 512 thr, warps 4(m)x4(n), warp tile 32x32, K-chunk 64, 3-stage cp.async.
template <int KA, int NTERMS, bool BIASED>
__global__ __launch_bounds__(512)
void gemm_bf16(const __nv_bfloat16* __restrict__ Ahi, const __nv_bfloat16* __restrict__ Alo,
               const __nv_bfloat16* __restrict__ Bhi, const __nv_bfloat16* __restrict__ Blo,
               const float* __restrict__ bias,
               float* __restrict__ outF,
               __nv_bfloat16* __restrict__ outHi, __nv_bfloat16* __restrict__ outLo) {
    constexpr int NC  = KA / 64;
    constexpr int NH  = (NTERMS == 3) ? 2 : 1;
    constexpr int A_SEC = 128 * 144;
    constexpr int B_SEC = 64 * 272;
    constexpr int OFF_B = NH * A_SEC;
    constexpr int STAGE = OFF_B + NH * B_SEC;

    size_t aOff, bOff, oOff;
    if (KA == NN) {                               // pool: grid (8, 32)
        aOff = (size_t)blockIdx.y * NN * NN + (size_t)blockIdx.x * 128 * NN;
        bOff = (size_t)blockIdx.y * NN * DD;
        oOff = (size_t)blockIdx.y * NN * DD + (size_t)blockIdx.x * 128 * DD;
    } else {                                      // weight: grid 256
        aOff = (size_t)blockIdx.x * 128 * DD;
        bOff = 0;
        oOff = (size_t)blockIdx.x * 128 * DD;
    }
    Ahi += aOff; if (NTERMS == 3) Alo += aOff;
    Bhi += bOff; if (NTERMS == 3) Blo += bOff;

    extern __shared__ char smem[];
    const uint32_t sbase = smem_u32(smem);

    const int tid  = threadIdx.x;
    const int lane = tid & 31;
    const int wid  = tid >> 5;
    const int wm   = wid & 3;
    const int wn   = wid >> 2;
    const int sub  = lane >> 3;
    const int r8   = lane & 7;

    const uint32_t rowA  = wm * 32 + (sub & 1) * 8 + r8;
    const uint32_t colA  = (sub >> 1) * 8;
    const uint32_t rowB8 = (sub & 1) * 8 + r8;
    const uint32_t colB  = wn * 32 + (sub >> 1) * 8;

    float acc[2][4][4];
#pragma unroll
    for (int i = 0; i < 2; i++)
#pragma unroll
        for (int j = 0; j < 4; j++)
#pragma unroll
            for (int k = 0; k < 4; k++) acc[i][j][k] = 0.f;

    auto issue = [&](int c, int stg) {
        if (c < NC) {
            const uint32_t sb = sbase + (uint32_t)stg * STAGE;
            const int k0 = c * 64;
#pragma unroll
            for (int p = 0; p < 2 * NH; p++) {
                int i = tid + p * 512;
                int half = i >> 10, rem = i & 1023, row = rem >> 3, ch = rem & 7;
                const __nv_bfloat16* s = (half ? Alo : Ahi) + (size_t)row * KA + k0 + ch * 8;
                cp_async16(sb + half * A_SEC + row * 144 + ch * 16, s);
            }
#pragma unroll
            for (int p = 0; p < 2 * NH; p++) {
                int i = tid + p * 512;
                int half = i >> 10, rem = i & 1023, row = rem >> 4, ch = rem & 15;
                const __nv_bfloat16* s = (half ? Blo : Bhi) + (size_t)(k0 + row) * DD + ch * 8;
                cp_async16(sb + OFF_B + half * B_SEC + row * 272 + ch * 16, s);
            }
        }
        CP_COMMIT();
    };

    issue(0, 0);
    issue(1, 1);
    CP_WAIT1();
    __syncthreads();

    for (int c = 0; c < NC; c++) {
        issue(c + 2, (c + 2) % 3);
        const uint32_t st = sbase + (uint32_t)(c % 3) * STAGE;

#pragma unroll
        for (int ks = 0; ks < 4; ks++) {
            uint32_t ah[2][4], al[2][4], bh[2][4], bl[2][4];
#pragma unroll
            for (int mb = 0; mb < 2; mb++) {
                uint32_t ad = st + (rowA + mb * 16) * 144 + (ks * 16 + colA) * 2;
                ldsm_x4(ah[mb], ad);
                if (NTERMS == 3) ldsm_x4(al[mb], ad + A_SEC);
            }
#pragma unroll
            for (int g = 0; g < 2; g++) {
                uint32_t bd = st + OFF_B + (ks * 16 + rowB8) * 272 + (colB + g * 16) * 2;
                ldsm_x4_t(bh[g], bd);
                if (NTERMS == 3) ldsm_x4_t(bl[g], bd + B_SEC);
            }
#pragma unroll
            for (int mb = 0; mb < 2; mb++)
#pragma unroll
                for (int nb = 0; nb < 4; nb++)
                    mma_bf16(acc[mb][nb], ah[mb], &bh[nb >> 1][(nb & 1) * 2]);
            if (NTERMS == 3) {
#pragma unroll
                for (int mb = 0; mb < 2; mb++)
#pragma unroll
                    for (int nb = 0; nb < 4; nb++)
                        mma_bf16(acc[mb][nb], ah[mb], &bl[nb >> 1][(nb & 1) * 2]);
#pragma unroll
                for (int mb = 0; mb < 2; mb++)
#pragma unroll
                    for (int nb = 0; nb < 4; nb++)
                        mma_bf16(acc[mb][nb], al[mb], &bh[nb >> 1][(nb & 1) * 2]);
            }
        }
        CP_WAIT1();
        __syncthreads();
    }

    const int er = lane >> 2;
    const int ec = (lane & 3) * 2;
#pragma unroll
    for (int mb = 0; mb < 2; mb++)
#pragma unroll
        for (int nb = 0; nb < 4; nb++) {
            int row = wm * 32 + mb * 16 + er;
            int col = wn * 32 + nb * 8 + ec;
            float2 v0 = make_float2(acc[mb][nb][0], acc[mb][nb][1]);
            float2 v1 = make_float2(acc[mb][nb][2], acc[mb][nb][3]);
            if (BIASED) {
                float bx = bias[col], by = bias[col + 1];
                v0.x += bx; v0.y += by; v1.x += bx; v1.y += by;
                *reinterpret_cast<float2*>(outF + oOff + (size_t)row * DD + col) = v0;
                *reinterpret_cast<float2*>(outF + oOff + (size_t)(row + 8) * DD + col) = v1;
            } else {
                __nv_bfloat16 h0 = __float2bfloat16(v0.x), h1 = __float2bfloat16(v0.y);
                __nv_bfloat16 h2 = __float2bfloat16(v1.x), h3 = __float2bfloat16(v1.y);
                uint32_t hi0 = pack_bf16(v0.x, v0.y);
                uint32_t hi1 = pack_bf16(v1.x, v1.y);
                uint32_t lo0 = pack_bf16(v0.x - __bfloat162float(h0), v0.y - __bfloat162float(h1));
                uint32_t lo1 = pack_bf16(v1.x - __bfloat162float(h2), v1.y - __bfloat162float(h3));
                *reinterpret_cast<uint32_t*>(outHi + oOff + (size_t)row * DD + col) = hi0;
                *reinterpret_cast<uint32_t*>(outLo + oOff + (size_t)row * DD + col) = lo0;
                *reinterpret_cast<uint32_t*>(outHi + oOff + (size_t)(row + 8) * DD + col) = hi1;
                *reinterpret_cast<uint32_t*>(outLo + oOff + (size_t)(row + 8) * DD + col) = lo1;
            }
        }
}

// ---------------- elementwise fp32 -> (hi, lo) bf16 split ----------------
__global__ __launch_bounds__(256)
void split_kernel(const float* __restrict__ src,
                  __nv_bfloat16* __restrict__ hi, __nv_bfloat16* __restrict__ lo) {
    const size_t idx = (size_t)blockIdx.x * 256 + threadIdx.x;
    float4 v = reinterpret_cast<const float4*>(src)[idx];
    __nv_bfloat16 h0 = __float2bfloat16(v.x), h1 = __float2bfloat16(v.y);
    __nv_bfloat16 h2 = __float2bfloat16(v.z), h3 = __float2bfloat16(v.w);
    uint2 hv, lv;
    hv.x = pack_bf16(v.x, v.y); hv.y = pack_bf16(v.z, v.w);
    lv.x = pack_bf16(v.x - __bfloat162float(h0), v.y - __bfloat162float(h1));
    lv.y = pack_bf16(v.z - __bfloat162float(h2), v.w - __bfloat162float(h3));
    reinterpret_cast<uint2*>(hi)[idx] = hv;
    reinterpret_cast<uint2*>(lo)[idx] = lv;
}

// ---------------- BN stage 1 ----------------
__global__ __launch_bounds__(128)
void bn_partial_kernel(const float* __restrict__ x) {
    const int col = threadIdx.x;
    const int p = blockIdx.x;
    const int r0 = p * (MTOT / BN_BLOCKS);
    float s = 0.f, q = 0.f;
#pragma unroll 8
    for (int r = 0; r < MTOT / BN_BLOCKS; r++) {
        float v = x[(size_t)(r0 + r) * DD + col];
        s += v;
        q = fmaf(v, v, q);
    }
    g_partS[p * DD + col] = s;
    g_partQ[p * DD + col] = q;
}

// ---------------- BN stage 2 ----------------
__global__ __launch_bounds__(1024)
void bn_finalize_kernel(const float* __restrict__ gamma,
                        const float* __restrict__ beta) {
    __shared__ float rs[8][DD], rq[8][DD];
    const int col = threadIdx.x, j = threadIdx.y;
    float s = 0.f, q = 0.f;
#pragma unroll
    for (int p = j; p < BN_BLOCKS; p += 8) {
        s += g_partS[p * DD + col];
        q += g_partQ[p * DD + col];
    }
    rs[j][col] = s;
    rq[j][col] = q;
    __syncthreads();
    if (j == 0) {
#pragma unroll
        for (int jj = 1; jj < 8; jj++) { s += rs[jj][col]; q += rq[jj][col]; }
        const float inv_m = 1.0f / (float)MTOT;
        float mean = s * inv_m;
        float var = q * inv_m - mean * mean;
        float sc = gamma[col] * rsqrtf(var + BN_EPS);
        g_scale[col] = sc;
        g_shift[col] = beta[col] - mean * sc;
    }
}

// ---------------- BN apply + ReLU -> split bf16 pair ----------------
__global__ __launch_bounds__(256)
void bn_apply_split_kernel(const float* __restrict__ x,
                           __nv_bfloat16* __restrict__ yhi,
                           __nv_bfloat16* __restrict__ ylo) {
    const int idx = blockIdx.x * 256 + threadIdx.x;
    const int c4 = idx & 31;
    float4 v = reinterpret_cast<const float4*>(x)[idx];
    float4 sc = reinterpret_cast<const float4*>(g_scale)[c4];
    float4 sh = reinterpret_cast<const float4*>(g_shift)[c4];
    float4 r;
    r.x = fmaxf(fmaf(v.x, sc.x, sh.x), 0.f);
    r.y = fmaxf(fmaf(v.y, sc.y, sh.y), 0.f);
    r.z = fmaxf(fmaf(v.z, sc.z, sh.z), 0.f);
    r.w = fmaxf(fmaf(v.w, sc.w, sh.w), 0.f);
    __nv_bfloat16 h0 = __float2bfloat16(r.x), h1 = __float2bfloat16(r.y);
    __nv_bfloat16 h2 = __float2bfloat16(r.z), h3 = __float2bfloat16(r.w);
    uint2 hv, lv;
    hv.x = pack_bf16(r.x, r.y); hv.y = pack_bf16(r.z, r.w);
    lv.x = pack_bf16(r.x - __bfloat162float(h0), r.y - __bfloat162float(h1));
    lv.y = pack_bf16(r.z - __bfloat162float(h2), r.w - __bfloat162float(h3));
    reinterpret_cast<uint2*>(yhi)[idx] = hv;
    reinterpret_cast<uint2*>(ylo)[idx] = lv;
}

// ---------------- BN apply + ReLU -> fp32 (final) ----------------
__global__ __launch_bounds__(256)
void bn_apply_final_kernel(const float* __restrict__ x, float* __restrict__ out) {
    const int idx = blockIdx.x * 256 + threadIdx.x;
    const int c4 = idx & 31;
    float4 v = reinterpret_cast<const float4*>(x)[idx];
    float4 sc = reinterpret_cast<const float4*>(g_scale)[c4];
    float4 sh = reinterpret_cast<const float4*>(g_shift)[c4];
    float4 r;
    r.x = fmaxf(fmaf(v.x, sc.x, sh.x), 0.f);
    r.y = fmaxf(fmaf(v.y, sc.y, sh.y), 0.f);
    r.z = fmaxf(fmaf(v.z, sc.z, sh.z), 0.f);
    r.w = fmaxf(fmaf(v.w, sc.w, sh.w), 0.f);
    reinterpret_cast<float4*>(out)[idx] = r;
}

// ---------------- launch ----------------
extern "C" void kernel_launch(void* const* d_in, const int* in_sizes, int n_in,
                              void* d_out, int out_size) {
    const float* x     = (const float*)d_in[0];
    const float* adj   = (const float*)d_in[2];
    const float* W1    = (const float*)d_in[3];
    const float* b1    = (const float*)d_in[4];
    const float* W2    = (const float*)d_in[5];
    const float* b2    = (const float*)d_in[6];
    const float* g_in   = (const float*)d_in[7];
    const float* be_in  = (const float*)d_in[8];
    const float* g_out  = (const float*)d_in[9];
    const float* be_out = (const float*)d_in[10];
    float* out = (float*)d_out;

    __nv_bfloat16 *adjHi, *adjLo, *hHi, *hLo, *pHi, *pLo, *yHi, *yLo;
    __nv_bfloat16 *W1Hi, *W1Lo, *W2Hi, *W2Lo;
    float *z;
    cudaGetSymbolAddress((void**)&adjHi, g_adjHi);
    cudaGetSymbolAddress((void**)&adjLo, g_adjLo);
    cudaGetSymbolAddress((void**)&hHi, g_hHi);
    cudaGetSymbolAddress((void**)&hLo, g_hLo);
    cudaGetSymbolAddress((void**)&pHi, g_pHi);
    cudaGetSymbolAddress((void**)&pLo, g_pLo);
    cudaGetSymbolAddress((void**)&yHi, g_yHi);
    cudaGetSymbolAddress((void**)&yLo, g_yLo);
    cudaGetSymbolAddress((void**)&W1Hi, g_W1Hi);
    cudaGetSymbolAddress((void**)&W1Lo, g_W1Lo);
    cudaGetSymbolAddress((void**)&W2Hi, g_W2Hi);
    cudaGetSymbolAddress((void**)&W2Lo, g_W2Lo);
    cudaGetSymbolAddress((void**)&z, g_z);

    constexpr int SMEM3 = 3 * (2 * 128 * 144 + 2 * 64 * 272);  // 215040
    constexpr int SMEM1 = 3 * (128 * 144 + 64 * 272);          // 107520
    cudaFuncSetAttribute((const void*)gemm_bf16<NN, 3, false>,
                         cudaFuncAttributeMaxDynamicSharedMemorySize, SMEM3);
    cudaFuncSetAttribute((const void*)gemm_bf16<NN, 1, false>,
                         cudaFuncAttributeMaxDynamicSharedMemorySize, SMEM1);
    cudaFuncSetAttribute((const void*)gemm_bf16<DD, 3, true>,
                         cudaFuncAttributeMaxDynamicSharedMemorySize, SMEM3);

    // one-time operand splits
    split_kernel<<<(int)((size_t)BATCH * NN * NN / 1024), 256>>>(adj, adjHi, adjLo);
    split_kernel<<<MTOT * DD / 1024, 256>>>(x, hHi, hLo);
    split_kernel<<<LL * DD * DD / 1024, 256>>>(W1, W1Hi, W1Lo);
    split_kernel<<<LL * DD * DD / 1024, 256>>>(W2, W2Hi, W2Lo);

    const dim3 gridPool(NN / 128, BATCH);
    const int  gridW = MTOT / 128;
    const int  gridApp = (MTOT * DD) / (256 * 4);
    const dim3 finBlk(DD, 8);

    for (int l = 0; l < LL; l++) {
        if (l == 0)
            gemm_bf16<NN, 3, false><<<gridPool, 512, SMEM3>>>(
                adjHi, adjLo, hHi, hLo, nullptr, nullptr, pHi, pLo);
        else
            gemm_bf16<NN, 1, false><<<gridPool, 512, SMEM1>>>(
                adjHi, nullptr, hHi, nullptr, nullptr, nullptr, pHi, pLo);

        gemm_bf16<DD, 3, true><<<gridW, 512, SMEM3>>>(
            pHi, pLo, W1Hi + (size_t)l * DD * DD, W1Lo + (size_t)l * DD * DD,
            b1 + (size_t)l * DD, z, nullptr, nullptr);

        bn_partial_kernel<<<BN_BLOCKS, 128>>>(z);
        bn_finalize_kernel<<<1, finBlk>>>(g_in + (size_t)l * DD, be_in + (size_t)l * DD);
        bn_apply_split_kernel<<<gridApp, 256>>>(z, yHi, yLo);

        gemm_bf16<DD, 3, true><<<gridW, 512, SMEM3>>>(
            yHi, yLo, W2Hi + (size_t)l * DD * DD, W2Lo + (size_t)l * DD * DD,
            b2 + (size_t)l * DD, z, nullptr, nullptr);

        bn_partial_kernel<<<BN_BLOCKS, 128>>>(z);
        bn_finalize_kernel<<<1, finBlk>>>(g_out + (size_t)l * DD, be_out + (size_t)l * DD);
        if (l == LL - 1)
            bn_apply_final_kernel<<<gridApp, 256>>>(z, out);
        else
            bn_apply_split_kernel<<<gridApp, 256>>>(z, hHi, hLo);
    }
}

// round 6
// speedup vs baseline: 2.6450x; 1.2058x over previous
#include <cuda_runtime.h>
#include <cuda_bf16.h>
#include <cstdint>

#define BATCH 32
#define NN    1024
#define DD    128
#define LL    2
#define MTOT  (BATCH * NN)
#define BN_EPS 1e-5f
#define BN_BLOCKS 256

// ---------------- scratch (no allocation allowed) ----------------
__device__ __nv_bfloat16 g_adjHi[(size_t)BATCH * NN * NN];
__device__ __nv_bfloat16 g_hHi[MTOT * DD];
__device__ __nv_bfloat16 g_hLo[MTOT * DD];
__device__ __nv_bfloat16 g_pHi[MTOT * DD];
__device__ __nv_bfloat16 g_pLo[MTOT * DD];
__device__ __nv_bfloat16 g_yHi[MTOT * DD];
__device__ __nv_bfloat16 g_yLo[MTOT * DD];
__device__ __nv_bfloat16 g_W1Hi[LL * DD * DD];
__device__ __nv_bfloat16 g_W1Lo[LL * DD * DD];
__device__ __nv_bfloat16 g_W2Hi[LL * DD * DD];
__device__ __nv_bfloat16 g_W2Lo[LL * DD * DD];
__device__ float g_z[MTOT * DD];
__device__ float g_partS[BN_BLOCKS * DD];
__device__ float g_partQ[BN_BLOCKS * DD];
__device__ float g_scale[DD];
__device__ float g_shift[DD];

// ---------------- helpers ----------------
__device__ __forceinline__ uint32_t smem_u32(const void* p) {
    uint32_t a;
    asm("{ .reg .u64 t; cvta.to.shared.u64 t, %1; cvt.u32.u64 %0, t; }" : "=r"(a) : "l"(p));
    return a;
}
__device__ __forceinline__ void ldsm_x4(uint32_t* r, uint32_t addr) {
    asm volatile("ldmatrix.sync.aligned.m8n8.x4.shared.b16 {%0,%1,%2,%3}, [%4];"
                 : "=r"(r[0]), "=r"(r[1]), "=r"(r[2]), "=r"(r[3]) : "r"(addr));
}
__device__ __forceinline__ void ldsm_x4_t(uint32_t* r, uint32_t addr) {
    asm volatile("ldmatrix.sync.aligned.m8n8.x4.trans.shared.b16 {%0,%1,%2,%3}, [%4];"
                 : "=r"(r[0]), "=r"(r[1]), "=r"(r[2]), "=r"(r[3]) : "r"(addr));
}
__device__ __forceinline__ void mma_bf16(float* c, const uint32_t* a, const uint32_t* b) {
    asm volatile(
        "mma.sync.aligned.m16n8k16.row.col.f32.bf16.bf16.f32 "
        "{%0,%1,%2,%3}, {%4,%5,%6,%7}, {%8,%9}, {%0,%1,%2,%3};"
        : "+f"(c[0]), "+f"(c[1]), "+f"(c[2]), "+f"(c[3])
        : "r"(a[0]), "r"(a[1]), "r"(a[2]), "r"(a[3]), "r"(b[0]), "r"(b[1]));
}
__device__ __forceinline__ void cp_async16(uint32_t dst, const void* src) {
    asm volatile("cp.async.cg.shared.global [%0], [%1], 16;" :: "r"(dst), "l"(src));
}
#define CP_COMMIT() asm volatile("cp.async.commit_group;" ::: "memory")
#define CP_WAIT1()  asm volatile("cp.async.wait_group 1;"  ::: "memory")

__device__ __forceinline__ uint32_t pack_bf16(float x, float y) {
    __nv_bfloat162 t = __floats2bfloat162_rn(x, y);
    return *reinterpret_cast<uint32_t*>(&t);
}

// =================================================================
// Pool layer-1 GEMM with fused adj fp32->bf16(hi/lo) conversion.
// out = adj @ h, 3-term split. Also writes adjHi to gmem for layer 2.
// CTA 128x128, 512 thr, K-chunk 64. fp32 A: 2-stage; B: 3-stage; bf16 A: 1 buf.
// =================================================================
#define PC_AF_SEC 32768
#define PC_AH_OFF 65536
#define PC_AL_OFF 83968
#define PC_B_OFF  102400
#define PC_B_SEC  17408
#define PC_B_STG  34816
#define POOL_SMEM 206848   // 65536 + 36864 + 104448

__global__ __launch_bounds__(512)
void gemm_pool_convert(const float* __restrict__ A,
                       const __nv_bfloat16* __restrict__ Bhi,
                       const __nv_bfloat16* __restrict__ Blo,
                       __nv_bfloat16* __restrict__ adjHiOut,
                       __nv_bfloat16* __restrict__ outHi,
                       __nv_bfloat16* __restrict__ outLo) {
    constexpr int NC = NN / 64;

    const size_t aOff = (size_t)blockIdx.y * NN * NN + (size_t)blockIdx.x * 128 * NN;
    const size_t bOff = (size_t)blockIdx.y * NN * DD;
    const size_t oOff = (size_t)blockIdx.y * NN * DD + (size_t)blockIdx.x * 128 * DD;
    A += aOff;
    adjHiOut += aOff;
    Bhi += bOff; Blo += bOff;

    extern __shared__ char smem[];
    const uint32_t sbase = smem_u32(smem);

    const int tid  = threadIdx.x;
    const int lane = tid & 31;
    const int wid  = tid >> 5;
    const int wm   = wid & 3;
    const int wn   = wid >> 2;
    const int sub  = lane >> 3;
    const int r8   = lane & 7;

    const uint32_t rowA  = wm * 32 + (sub & 1) * 8 + r8;
    const uint32_t colA  = (sub >> 1) * 8;
    const uint32_t rowB8 = (sub & 1) * 8 + r8;
    const uint32_t colB  = wn * 32 + (sub >> 1) * 8;

    float acc[2][4][4];
#pragma unroll
    for (int i = 0; i < 2; i++)
#pragma unroll
        for (int j = 0; j < 4; j++)
#pragma unroll
            for (int k = 0; k < 4; k++) acc[i][j][k] = 0.f;

    auto issueA = [&](int c) {
        const uint32_t sb = sbase + (uint32_t)(c & 1) * PC_AF_SEC;
#pragma unroll
        for (int p = 0; p < 4; p++) {
            int idx = tid + p * 512;
            int row = idx >> 4, seg = idx & 15;
            cp_async16(sb + idx * 16, A + (size_t)row * NN + c * 64 + seg * 4);
        }
    };
    auto issueB = [&](int c) {
        const uint32_t sb = sbase + PC_B_OFF + (uint32_t)(c % 3) * PC_B_STG;
#pragma unroll
        for (int p = 0; p < 4; p++) {
            int i = tid + p * 512;
            int half = i >> 10, rem = i & 1023, row = rem >> 4, ch = rem & 15;
            const __nv_bfloat16* s = (half ? Blo : Bhi) + (size_t)(c * 64 + row) * DD + ch * 8;
            cp_async16(sb + half * PC_B_SEC + row * 272 + ch * 16, s);
        }
    };

    issueA(0); issueB(0); CP_COMMIT();
    issueA(1); issueB(1); CP_COMMIT();

    for (int c = 0; c < NC; c++) {
        CP_WAIT1();
        __syncthreads();

        // ---- convert fp32 stage (c&1) -> bf16 hi/lo buffers + STG hi ----
        {
            const char* fsrc = smem + (c & 1) * PC_AF_SEC;
#pragma unroll
            for (int p = 0; p < 4; p++) {
                int idx = tid + p * 512;
                int row = idx >> 4, seg = idx & 15;
                float4 v = *reinterpret_cast<const float4*>(fsrc + idx * 16);
                __nv_bfloat16 h0 = __float2bfloat16(v.x), h1 = __float2bfloat16(v.y);
                __nv_bfloat16 h2 = __float2bfloat16(v.z), h3 = __float2bfloat16(v.w);
                uint2 hv, lv;
                hv.x = pack_bf16(v.x, v.y); hv.y = pack_bf16(v.z, v.w);
                lv.x = pack_bf16(v.x - __bfloat162float(h0), v.y - __bfloat162float(h1));
                lv.y = pack_bf16(v.z - __bfloat162float(h2), v.w - __bfloat162float(h3));
                char* d = smem + row * 144 + seg * 8;
                *reinterpret_cast<uint2*>(d + PC_AH_OFF) = hv;
                *reinterpret_cast<uint2*>(d + PC_AL_OFF) = lv;
                *reinterpret_cast<uint2*>(adjHiOut + (size_t)row * NN + c * 64 + seg * 4) = hv;
            }
        }
        __syncthreads();

        if (c + 2 < NC) { issueA(c + 2); issueB(c + 2); }
        CP_COMMIT();

        // ---- MMA on chunk c ----
        const uint32_t stB = sbase + PC_B_OFF + (uint32_t)(c % 3) * PC_B_STG;
#pragma unroll
        for (int ks = 0; ks < 4; ks++) {
            uint32_t ah[2][4], al[2][4], bh[2][4], bl[2][4];
#pragma unroll
            for (int mb = 0; mb < 2; mb++) {
                uint32_t ad = sbase + (rowA + mb * 16) * 144 + (ks * 16 + colA) * 2;
                ldsm_x4(ah[mb], ad + PC_AH_OFF);
                ldsm_x4(al[mb], ad + PC_AL_OFF);
            }
#pragma unroll
            for (int g = 0; g < 2; g++) {
                uint32_t bd = stB + (ks * 16 + rowB8) * 272 + (colB + g * 16) * 2;
                ldsm_x4_t(bh[g], bd);
                ldsm_x4_t(bl[g], bd + PC_B_SEC);
            }
#pragma unroll
            for (int mb = 0; mb < 2; mb++)
#pragma unroll
                for (int nb = 0; nb < 4; nb++)
                    mma_bf16(acc[mb][nb], ah[mb], &bh[nb >> 1][(nb & 1) * 2]);
#pragma unroll
            for (int mb = 0; mb < 2; mb++)
#pragma unroll
                for (int nb = 0; nb < 4; nb++)
                    mma_bf16(acc[mb][nb], ah[mb], &bl[nb >> 1][(nb & 1) * 2]);
#pragma unroll
            for (int mb = 0; mb < 2; mb++)
#pragma unroll
                for (int nb = 0; nb < 4; nb++)
                    mma_bf16(acc[mb][nb], al[mb], &bh[nb >> 1][(nb & 1) * 2]);
        }
    }

    // ---- epilogue: split hi/lo bf16 out ----
    const int er = lane >> 2;
    const int ec = (lane & 3) * 2;
#pragma unroll
    for (int mb = 0; mb < 2; mb++)
#pragma unroll
        for (int nb = 0; nb < 4; nb++) {
            int row = wm * 32 + mb * 16 + er;
            int col = wn * 32 + nb * 8 + ec;
            float2 v0 = make_float2(acc[mb][nb][0], acc[mb][nb][1]);
            float2 v1 = make_float2(acc[mb][nb][2], acc[mb][nb][3]);
            __nv_bfloat16 h0 = __float2bfloat16(v0.x), h1 = __float2bfloat16(v0.y);
            __nv_bfloat16 h2 = __float2bfloat16(v1.x), h3 = __float2bfloat16(v1.y);
            uint32_t hi0 = pack_bf16(v0.x, v0.y);
            uint32_t hi1 = pack_bf16(v1.x, v1.y);
            uint32_t lo0 = pack_bf16(v0.x - __bfloat162float(h0), v0.y - __bfloat162float(h1));
            uint32_t lo1 = pack_bf16(v1.x - __bfloat162float(h2), v1.y - __bfloat162float(h3));
            *reinterpret_cast<uint32_t*>(outHi + oOff + (size_t)row * DD + col) = hi0;
            *reinterpret_cast<uint32_t*>(outLo + oOff + (size_t)row * DD + col) = lo0;
            *reinterpret_cast<uint32_t*>(outHi + oOff + (size_t)(row + 8) * DD + col) = hi1;
            *reinterpret_cast<uint32_t*>(outLo + oOff + (size_t)(row + 8) * DD + col) = lo1;
        }
}

// =================================================================
// Unified split-bf16 GEMM (as R5). BIASED variant additionally computes
// per-CTA BatchNorm partial sums (deterministic) into g_partS/g_partQ.
// =================================================================
template <int KA, int NTERMS, bool BIASED>
__global__ __launch_bounds__(512)
void gemm_bf16(const __nv_bfloat16* __restrict__ Ahi, const __nv_bfloat16* __restrict__ Alo,
               const __nv_bfloat16* __restrict__ Bhi, const __nv_bfloat16* __restrict__ Blo,
               const float* __restrict__ bias,
               float* __restrict__ outF,
               __nv_bfloat16* __restrict__ outHi, __nv_bfloat16* __restrict__ outLo) {
    constexpr int NC  = KA / 64;
    constexpr int NH  = (NTERMS == 3) ? 2 : 1;
    constexpr int A_SEC = 128 * 144;
    constexpr int B_SEC = 64 * 272;
    constexpr int OFF_B = NH * A_SEC;
    constexpr int STAGE = OFF_B + NH * B_SEC;
    constexpr int SBUF_OFF = 3 * STAGE;        // reduction scratch (BIASED only)

    size_t aOff, bOff, oOff;
    if (KA == NN) {
        aOff = (size_t)blockIdx.y * NN * NN + (size_t)blockIdx.x * 128 * NN;
        bOff = (size_t)blockIdx.y * NN * DD;
        oOff = (size_t)blockIdx.y * NN * DD + (size_t)blockIdx.x * 128 * DD;
    } else {
        aOff = (size_t)blockIdx.x * 128 * DD;
        bOff = 0;
        oOff = (size_t)blockIdx.x * 128 * DD;
    }
    Ahi += aOff; if (NTERMS == 3) Alo += aOff;
    Bhi += bOff; if (NTERMS == 3) Blo += bOff;

    extern __shared__ char smem[];
    const uint32_t sbase = smem_u32(smem);

    const int tid  = threadIdx.x;
    const int lane = tid & 31;
    const int wid  = tid >> 5;
    const int wm   = wid & 3;
    const int wn   = wid >> 2;
    const int sub  = lane >> 3;
    const int r8   = lane & 7;

    const uint32_t rowA  = wm * 32 + (sub & 1) * 8 + r8;
    const uint32_t colA  = (sub >> 1) * 8;
    const uint32_t rowB8 = (sub & 1) * 8 + r8;
    const uint32_t colB  = wn * 32 + (sub >> 1) * 8;

    float acc[2][4][4];
#pragma unroll
    for (int i = 0; i < 2; i++)
#pragma unroll
        for (int j = 0; j < 4; j++)
#pragma unroll
            for (int k = 0; k < 4; k++) acc[i][j][k] = 0.f;

    auto issue = [&](int c, int stg) {
        if (c < NC) {
            const uint32_t sb = sbase + (uint32_t)stg * STAGE;
            const int k0 = c * 64;
#pragma unroll
            for (int p = 0; p < 2 * NH; p++) {
                int i = tid + p * 512;
                int half = i >> 10, rem = i & 1023, row = rem >> 3, ch = rem & 7;
                const __nv_bfloat16* s = (half ? Alo : Ahi) + (size_t)row * KA + k0 + ch * 8;
                cp_async16(sb + half * A_SEC + row * 144 + ch * 16, s);
            }
#pragma unroll
            for (int p = 0; p < 2 * NH; p++) {
                int i = tid + p * 512;
                int half = i >> 10, rem = i & 1023, row = rem >> 4, ch = rem & 15;
                const __nv_bfloat16* s = (half ? Blo : Bhi) + (size_t)(k0 + row) * DD + ch * 8;
                cp_async16(sb + OFF_B + half * B_SEC + row * 272 + ch * 16, s);
            }
        }
        CP_COMMIT();
    };

    issue(0, 0);
    issue(1, 1);
    CP_WAIT1();
    __syncthreads();

    for (int c = 0; c < NC; c++) {
        issue(c + 2, (c + 2) % 3);
        const uint32_t st = sbase + (uint32_t)(c % 3) * STAGE;

#pragma unroll
        for (int ks = 0; ks < 4; ks++) {
            uint32_t ah[2][4], al[2][4], bh[2][4], bl[2][4];
#pragma unroll
            for (int mb = 0; mb < 2; mb++) {
                uint32_t ad = st + (rowA + mb * 16) * 144 + (ks * 16 + colA) * 2;
                ldsm_x4(ah[mb], ad);
                if (NTERMS == 3) ldsm_x4(al[mb], ad + A_SEC);
            }
#pragma unroll
            for (int g = 0; g < 2; g++) {
                uint32_t bd = st + OFF_B + (ks * 16 + rowB8) * 272 + (colB + g * 16) * 2;
                ldsm_x4_t(bh[g], bd);
                if (NTERMS == 3) ldsm_x4_t(bl[g], bd + B_SEC);
            }
#pragma unroll
            for (int mb = 0; mb < 2; mb++)
#pragma unroll
                for (int nb = 0; nb < 4; nb++)
                    mma_bf16(acc[mb][nb], ah[mb], &bh[nb >> 1][(nb & 1) * 2]);
            if (NTERMS == 3) {
#pragma unroll
                for (int mb = 0; mb < 2; mb++)
#pragma unroll
                    for (int nb = 0; nb < 4; nb++)
                        mma_bf16(acc[mb][nb], ah[mb], &bl[nb >> 1][(nb & 1) * 2]);
#pragma unroll
                for (int mb = 0; mb < 2; mb++)
#pragma unroll
                    for (int nb = 0; nb < 4; nb++)
                        mma_bf16(acc[mb][nb], al[mb], &bh[nb >> 1][(nb & 1) * 2]);
            }
        }
        CP_WAIT1();
        __syncthreads();
    }

    const int er = lane >> 2;
    const int ec = (lane & 3) * 2;
    float s8[8], q8[8];
    if (BIASED) {
#pragma unroll
        for (int i = 0; i < 8; i++) { s8[i] = 0.f; q8[i] = 0.f; }
    }
#pragma unroll
    for (int mb = 0; mb < 2; mb++)
#pragma unroll
        for (int nb = 0; nb < 4; nb++) {
            int row = wm * 32 + mb * 16 + er;
            int col = wn * 32 + nb * 8 + ec;
            float2 v0 = make_float2(acc[mb][nb][0], acc[mb][nb][1]);
            float2 v1 = make_float2(acc[mb][nb][2], acc[mb][nb][3]);
            if (BIASED) {
                float bx = bias[col], by = bias[col + 1];
                v0.x += bx; v0.y += by; v1.x += bx; v1.y += by;
                s8[nb * 2 + 0] += v0.x + v1.x;
                s8[nb * 2 + 1] += v0.y + v1.y;
                q8[nb * 2 + 0] += v0.x * v0.x + v1.x * v1.x;
                q8[nb * 2 + 1] += v0.y * v0.y + v1.y * v1.y;
                *reinterpret_cast<float2*>(outF + oOff + (size_t)row * DD + col) = v0;
                *reinterpret_cast<float2*>(outF + oOff + (size_t)(row + 8) * DD + col) = v1;
            } else {
                __nv_bfloat16 h0 = __float2bfloat16(v0.x), h1 = __float2bfloat16(v0.y);
                __nv_bfloat16 h2 = __float2bfloat16(v1.x), h3 = __float2bfloat16(v1.y);
                uint32_t hi0 = pack_bf16(v0.x, v0.y);
                uint32_t hi1 = pack_bf16(v1.x, v1.y);
                uint32_t lo0 = pack_bf16(v0.x - __bfloat162float(h0), v0.y - __bfloat162float(h1));
                uint32_t lo1 = pack_bf16(v1.x - __bfloat162float(h2), v1.y - __bfloat162float(h3));
                *reinterpret_cast<uint32_t*>(outHi + oOff + (size_t)row * DD + col) = hi0;
                *reinterpret_cast<uint32_t*>(outLo + oOff + (size_t)row * DD + col) = lo0;
                *reinterpret_cast<uint32_t*>(outHi + oOff + (size_t)(row + 8) * DD + col) = hi1;
                *reinterpret_cast<uint32_t*>(outLo + oOff + (size_t)(row + 8) * DD + col) = lo1;
            }
        }

    if (BIASED) {
        // reduce across er lanes (bits 2..4 of lane)
#pragma unroll
        for (int off = 4; off < 32; off <<= 1) {
#pragma unroll
            for (int i = 0; i < 8; i++) {
                s8[i] += __shfl_xor_sync(0xFFFFFFFF, s8[i], off);
                q8[i] += __shfl_xor_sync(0xFFFFFFFF, q8[i], off);
            }
        }
        float* sBuf = reinterpret_cast<float*>(smem + SBUF_OFF);
        float* qBuf = sBuf + 4 * DD;
        if (lane < 4) {
#pragma unroll
            for (int nb = 0; nb < 4; nb++) {
#pragma unroll
                for (int j = 0; j < 2; j++) {
                    int col = wn * 32 + nb * 8 + lane * 2 + j;
                    sBuf[wm * DD + col] = s8[nb * 2 + j];
                    qBuf[wm * DD + col] = q8[nb * 2 + j];
                }
            }
        }
        __syncthreads();
        if (tid < DD) {
            float s = sBuf[tid] + sBuf[DD + tid] + sBuf[2 * DD + tid] + sBuf[3 * DD + tid];
            float q = qBuf[tid] + qBuf[DD + tid] + qBuf[2 * DD + tid] + qBuf[3 * DD + tid];
            g_partS[blockIdx.x * DD + tid] = s;
            g_partQ[blockIdx.x * DD + tid] = q;
        }
    }
}

// ---------------- elementwise fp32 -> (hi, lo) bf16 split ----------------
__global__ __launch_bounds__(256)
void split_kernel(const float* __restrict__ src,
                  __nv_bfloat16* __restrict__ hi, __nv_bfloat16* __restrict__ lo) {
    const size_t idx = (size_t)blockIdx.x * 256 + threadIdx.x;
    float4 v = reinterpret_cast<const float4*>(src)[idx];
    __nv_bfloat16 h0 = __float2bfloat16(v.x), h1 = __float2bfloat16(v.y);
    __nv_bfloat16 h2 = __float2bfloat16(v.z), h3 = __float2bfloat16(v.w);
    uint2 hv, lv;
    hv.x = pack_bf16(v.x, v.y); hv.y = pack_bf16(v.z, v.w);
    lv.x = pack_bf16(v.x - __bfloat162float(h0), v.y - __bfloat162float(h1));
    lv.y = pack_bf16(v.z - __bfloat162float(h2), v.w - __bfloat162float(h3));
    reinterpret_cast<uint2*>(hi)[idx] = hv;
    reinterpret_cast<uint2*>(lo)[idx] = lv;
}

// ---------------- BN finalize ----------------
__global__ __launch_bounds__(1024)
void bn_finalize_kernel(const float* __restrict__ gamma,
                        const float* __restrict__ beta) {
    __shared__ float rs[8][DD], rq[8][DD];
    const int col = threadIdx.x, j = threadIdx.y;
    float s = 0.f, q = 0.f;
#pragma unroll
    for (int p = j; p < BN_BLOCKS; p += 8) {
        s += g_partS[p * DD + col];
        q += g_partQ[p * DD + col];
    }
    rs[j][col] = s;
    rq[j][col] = q;
    __syncthreads();
    if (j == 0) {
#pragma unroll
        for (int jj = 1; jj < 8; jj++) { s += rs[jj][col]; q += rq[jj][col]; }
        const float inv_m = 1.0f / (float)MTOT;
        float mean = s * inv_m;
        float var = q * inv_m - mean * mean;
        float sc = gamma[col] * rsqrtf(var + BN_EPS);
        g_scale[col] = sc;
        g_shift[col] = beta[col] - mean * sc;
    }
}

// ---------------- BN apply + ReLU -> split bf16 pair ----------------
__global__ __launch_bounds__(256)
void bn_apply_split_kernel(const float* __restrict__ x,
                           __nv_bfloat16* __restrict__ yhi,
                           __nv_bfloat16* __restrict__ ylo) {
    const int idx = blockIdx.x * 256 + threadIdx.x;
    const int c4 = idx & 31;
    float4 v = reinterpret_cast<const float4*>(x)[idx];
    float4 sc = reinterpret_cast<const float4*>(g_scale)[c4];
    float4 sh = reinterpret_cast<const float4*>(g_shift)[c4];
    float4 r;
    r.x = fmaxf(fmaf(v.x, sc.x, sh.x), 0.f);
    r.y = fmaxf(fmaf(v.y, sc.y, sh.y), 0.f);
    r.z = fmaxf(fmaf(v.z, sc.z, sh.z), 0.f);
    r.w = fmaxf(fmaf(v.w, sc.w, sh.w), 0.f);
    __nv_bfloat16 h0 = __float2bfloat16(r.x), h1 = __float2bfloat16(r.y);
    __nv_bfloat16 h2 = __float2bfloat16(r.z), h3 = __float2bfloat16(r.w);
    uint2 hv, lv;
    hv.x = pack_bf16(r.x, r.y); hv.y = pack_bf16(r.z, r.w);
    lv.x = pack_bf16(r.x - __bfloat162float(h0), r.y - __bfloat162float(h1));
    lv.y = pack_bf16(r.z - __bfloat162float(h2), r.w - __bfloat162float(h3));
    reinterpret_cast<uint2*>(yhi)[idx] = hv;
    reinterpret_cast<uint2*>(ylo)[idx] = lv;
}

// ---------------- BN apply + ReLU -> fp32 (final) ----------------
__global__ __launch_bounds__(256)
void bn_apply_final_kernel(const float* __restrict__ x, float* __restrict__ out) {
    const int idx = blockIdx.x * 256 + threadIdx.x;
    const int c4 = idx & 31;
    float4 v = reinterpret_cast<const float4*>(x)[idx];
    float4 sc = reinterpret_cast<const float4*>(g_scale)[c4];
    float4 sh = reinterpret_cast<const float4*>(g_shift)[c4];
    float4 r;
    r.x = fmaxf(fmaf(v.x, sc.x, sh.x), 0.f);
    r.y = fmaxf(fmaf(v.y, sc.y, sh.y), 0.f);
    r.z = fmaxf(fmaf(v.z, sc.z, sh.z), 0.f);
    r.w = fmaxf(fmaf(v.w, sc.w, sh.w), 0.f);
    reinterpret_cast<float4*>(out)[idx] = r;
}

// ---------------- launch ----------------
extern "C" void kernel_launch(void* const* d_in, const int* in_sizes, int n_in,
                              void* d_out, int out_size) {
    const float* x     = (const float*)d_in[0];
    const float* adj   = (const float*)d_in[2];
    const float* W1    = (const float*)d_in[3];
    const float* b1    = (const float*)d_in[4];
    const float* W2    = (const float*)d_in[5];
    const float* b2    = (const float*)d_in[6];
    const float* g_in   = (const float*)d_in[7];
    const float* be_in  = (const float*)d_in[8];
    const float* g_out  = (const float*)d_in[9];
    const float* be_out = (const float*)d_in[10];
    float* out = (float*)d_out;

    __nv_bfloat16 *adjHi, *hHi, *hLo, *pHi, *pLo, *yHi, *yLo;
    __nv_bfloat16 *W1Hi, *W1Lo, *W2Hi, *W2Lo;
    float *z;
    cudaGetSymbolAddress((void**)&adjHi, g_adjHi);
    cudaGetSymbolAddress((void**)&hHi, g_hHi);
    cudaGetSymbolAddress((void**)&hLo, g_hLo);
    cudaGetSymbolAddress((void**)&pHi, g_pHi);
    cudaGetSymbolAddress((void**)&pLo, g_pLo);
    cudaGetSymbolAddress((void**)&yHi, g_yHi);
    cudaGetSymbolAddress((void**)&yLo, g_yLo);
    cudaGetSymbolAddress((void**)&W1Hi, g_W1Hi);
    cudaGetSymbolAddress((void**)&W1Lo, g_W1Lo);
    cudaGetSymbolAddress((void**)&W2Hi, g_W2Hi);
    cudaGetSymbolAddress((void**)&W2Lo, g_W2Lo);
    cudaGetSymbolAddress((void**)&z, g_z);

    constexpr int SMEM3B = 3 * (2 * 128 * 144 + 2 * 64 * 272) + 4096;  // 219136
    constexpr int SMEM1  = 3 * (128 * 144 + 64 * 272);                 // 107520
    cudaFuncSetAttribute((const void*)gemm_pool_convert,
                         cudaFuncAttributeMaxDynamicSharedMemorySize, POOL_SMEM);
    cudaFuncSetAttribute((const void*)gemm_bf16<NN, 1, false>,
                         cudaFuncAttributeMaxDynamicSharedMemorySize, SMEM1);
    cudaFuncSetAttribute((const void*)gemm_bf16<DD, 3, true>,
                         cudaFuncAttributeMaxDynamicSharedMemorySize, SMEM3B);

    // small one-time operand splits
    split_kernel<<<MTOT * DD / 1024, 256>>>(x, hHi, hLo);
    split_kernel<<<LL * DD * DD / 1024, 256>>>(W1, W1Hi, W1Lo);
    split_kernel<<<LL * DD * DD / 1024, 256>>>(W2, W2Hi, W2Lo);

    const dim3 gridPool(NN / 128, BATCH);
    const int  gridW = MTOT / 128;
    const int  gridApp = (MTOT * DD) / (256 * 4);
    const dim3 finBlk(DD, 8);

    for (int l = 0; l < LL; l++) {
        if (l == 0)
            gemm_pool_convert<<<gridPool, 512, POOL_SMEM>>>(
                adj, hHi, hLo, adjHi, pHi, pLo);
        else
            gemm_bf16<NN, 1, false><<<gridPool, 512, SMEM1>>>(
                adjHi, nullptr, hHi, nullptr, nullptr, nullptr, pHi, pLo);

        gemm_bf16<DD, 3, true><<<gridW, 512, SMEM3B>>>(
            pHi, pLo, W1Hi + (size_t)l * DD * DD, W1Lo + (size_t)l * DD * DD,
            b1 + (size_t)l * DD, z, nullptr, nullptr);

        bn_finalize_kernel<<<1, finBlk>>>(g_in + (size_t)l * DD, be_in + (size_t)l * DD);
        bn_apply_split_kernel<<<gridApp, 256>>>(z, yHi, yLo);

        gemm_bf16<DD, 3, true><<<gridW, 512, SMEM3B>>>(
            yHi, yLo, W2Hi + (size_t)l * DD * DD, W2Lo + (size_t)l * DD * DD,
            b2 + (size_t)l * DD, z, nullptr, nullptr);

        bn_finalize_kernel<<<1, finBlk>>>(g_out + (size_t)l * DD, be_out + (size_t)l * DD);
        if (l == LL - 1)
            bn_apply_final_kernel<<<gridApp, 256>>>(z, out);
        else
            bn_apply_split_kernel<<<gridApp, 256>>>(z, hHi, hLo);
    }
}

// round 7
// speedup vs baseline: 2.6662x; 1.0080x over previous
#include <cuda_runtime.h>
#include <cuda_bf16.h>
#include <cstdint>

#define BATCH 32
#define NN    1024
#define DD    128
#define LL    2
#define MTOT  (BATCH * NN)
#define BN_EPS 1e-5f
#define BN_BLOCKS 256

// ---------------- scratch (no allocation allowed) ----------------
__device__ __nv_bfloat16 g_adjHi[(size_t)BATCH * NN * NN];
__device__ __nv_bfloat16 g_hHi[MTOT * DD];
__device__ __nv_bfloat16 g_hLo[MTOT * DD];
__device__ __nv_bfloat16 g_pHi[MTOT * DD];
__device__ __nv_bfloat16 g_pLo[MTOT * DD];
__device__ __nv_bfloat16 g_yHi[MTOT * DD];
__device__ __nv_bfloat16 g_yLo[MTOT * DD];
__device__ __nv_bfloat16 g_W1Hi[LL * DD * DD];
__device__ __nv_bfloat16 g_W1Lo[LL * DD * DD];
__device__ __nv_bfloat16 g_W2Hi[LL * DD * DD];
__device__ __nv_bfloat16 g_W2Lo[LL * DD * DD];
__device__ float g_z[MTOT * DD];
__device__ float g_partS[BN_BLOCKS * DD];
__device__ float g_partQ[BN_BLOCKS * DD];

// ---------------- helpers ----------------
__device__ __forceinline__ uint32_t smem_u32(const void* p) {
    uint32_t a;
    asm("{ .reg .u64 t; cvta.to.shared.u64 t, %1; cvt.u32.u64 %0, t; }" : "=r"(a) : "l"(p));
    return a;
}
__device__ __forceinline__ void ldsm_x4(uint32_t* r, uint32_t addr) {
    asm volatile("ldmatrix.sync.aligned.m8n8.x4.shared.b16 {%0,%1,%2,%3}, [%4];"
                 : "=r"(r[0]), "=r"(r[1]), "=r"(r[2]), "=r"(r[3]) : "r"(addr));
}
__device__ __forceinline__ void ldsm_x4_t(uint32_t* r, uint32_t addr) {
    asm volatile("ldmatrix.sync.aligned.m8n8.x4.trans.shared.b16 {%0,%1,%2,%3}, [%4];"
                 : "=r"(r[0]), "=r"(r[1]), "=r"(r[2]), "=r"(r[3]) : "r"(addr));
}
__device__ __forceinline__ void mma_bf16(float* c, const uint32_t* a, const uint32_t* b) {
    asm volatile(
        "mma.sync.aligned.m16n8k16.row.col.f32.bf16.bf16.f32 "
        "{%0,%1,%2,%3}, {%4,%5,%6,%7}, {%8,%9}, {%0,%1,%2,%3};"
        : "+f"(c[0]), "+f"(c[1]), "+f"(c[2]), "+f"(c[3])
        : "r"(a[0]), "r"(a[1]), "r"(a[2]), "r"(a[3]), "r"(b[0]), "r"(b[1]));
}
__device__ __forceinline__ void cp_async16(uint32_t dst, const void* src) {
    asm volatile("cp.async.cg.shared.global [%0], [%1], 16;" :: "r"(dst), "l"(src));
}
#define CP_COMMIT() asm volatile("cp.async.commit_group;" ::: "memory")
#define CP_WAIT1()  asm volatile("cp.async.wait_group 1;"  ::: "memory")

__device__ __forceinline__ uint32_t pack_bf16(float x, float y) {
    __nv_bfloat162 t = __floats2bfloat162_rn(x, y);
    return *reinterpret_cast<uint32_t*>(&t);
}

// =================================================================
// Pool layer-1 GEMM, convert pipelined WITH the MMA (convert(c+1) || MMA(c)).
// fp32 A: 2 stages (thread-private access). bf16 A: 2 buffers. B: 2 stages.
// Also streams adjHi to gmem for layer-2's single-term pool.
// =================================================================
#define PF_STAGE 32768
#define AB_OFF   65536
#define AB_BUF   36864      // hi(18432) + lo(18432)
#define PB_OFF   139264
#define PB_STG   34816      // hi(17408) + lo(17408)
#define POOL_SMEM 208896

__global__ __launch_bounds__(512)
void gemm_pool_convert(const float* __restrict__ A,
                       const __nv_bfloat16* __restrict__ Bhi,
                       const __nv_bfloat16* __restrict__ Blo,
                       __nv_bfloat16* __restrict__ adjHiOut,
                       __nv_bfloat16* __restrict__ outHi,
                       __nv_bfloat16* __restrict__ outLo) {
    constexpr int NC = NN / 64;

    const size_t aOff = (size_t)blockIdx.y * NN * NN + (size_t)blockIdx.x * 128 * NN;
    const size_t bOff = (size_t)blockIdx.y * NN * DD;
    const size_t oOff = (size_t)blockIdx.y * NN * DD + (size_t)blockIdx.x * 128 * DD;
    A += aOff;
    adjHiOut += aOff;
    Bhi += bOff; Blo += bOff;

    extern __shared__ char smem[];
    const uint32_t sbase = smem_u32(smem);

    const int tid  = threadIdx.x;
    const int lane = tid & 31;
    const int wid  = tid >> 5;
    const int wm   = wid & 3;
    const int wn   = wid >> 2;
    const int sub  = lane >> 3;
    const int r8   = lane & 7;

    const uint32_t rowA  = wm * 32 + (sub & 1) * 8 + r8;
    const uint32_t colA  = (sub >> 1) * 8;
    const uint32_t rowB8 = (sub & 1) * 8 + r8;
    const uint32_t colB  = wn * 32 + (sub >> 1) * 8;

    float acc[2][4][4];
#pragma unroll
    for (int i = 0; i < 2; i++)
#pragma unroll
        for (int j = 0; j < 4; j++)
#pragma unroll
            for (int k = 0; k < 4; k++) acc[i][j][k] = 0.f;

    auto issueA = [&](int c) {
        const uint32_t sb = sbase + (uint32_t)(c & 1) * PF_STAGE;
#pragma unroll
        for (int p = 0; p < 4; p++) {
            int idx = tid + p * 512;
            int row = idx >> 4, seg = idx & 15;
            cp_async16(sb + idx * 16, A + (size_t)row * NN + c * 64 + seg * 4);
        }
    };
    auto issueB = [&](int c) {
        const uint32_t sb = sbase + PB_OFF + (uint32_t)(c & 1) * PB_STG;
#pragma unroll
        for (int p = 0; p < 4; p++) {
            int i = tid + p * 512;
            int half = i >> 10, rem = i & 1023, row = rem >> 4, ch = rem & 15;
            const __nv_bfloat16* s = (half ? Blo : Bhi) + (size_t)(c * 64 + row) * DD + ch * 8;
            cp_async16(sb + half * 17408 + row * 272 + ch * 16, s);
        }
    };
    auto convert = [&](int cc) {
        const char* fsrc = smem + (cc & 1) * PF_STAGE;
        char* dhi = smem + AB_OFF + (cc & 1) * AB_BUF;
        char* dlo = dhi + 18432;
#pragma unroll
        for (int p = 0; p < 4; p++) {
            int idx = tid + p * 512;
            int row = idx >> 4, seg = idx & 15;
            float4 v = *reinterpret_cast<const float4*>(fsrc + idx * 16);
            __nv_bfloat16 h0 = __float2bfloat16(v.x), h1 = __float2bfloat16(v.y);
            __nv_bfloat16 h2 = __float2bfloat16(v.z), h3 = __float2bfloat16(v.w);
            uint2 hv, lv;
            hv.x = pack_bf16(v.x, v.y); hv.y = pack_bf16(v.z, v.w);
            lv.x = pack_bf16(v.x - __bfloat162float(h0), v.y - __bfloat162float(h1));
            lv.y = pack_bf16(v.z - __bfloat162float(h2), v.w - __bfloat162float(h3));
            *reinterpret_cast<uint2*>(dhi + row * 144 + seg * 8) = hv;
            *reinterpret_cast<uint2*>(dlo + row * 144 + seg * 8) = lv;
            *reinterpret_cast<uint2*>(adjHiOut + (size_t)row * NN + cc * 64 + seg * 4) = hv;
        }
    };

    // prologue: G0={fA0}, G1={fA1, B0}; convert(0)
    issueA(0); CP_COMMIT();
    issueA(1); issueB(0); CP_COMMIT();
    CP_WAIT1();                 // G0 done
    __syncthreads();
    convert(0);

    for (int c = 0; c < NC; c++) {
        if (c + 2 < NC) issueA(c + 2);
        if (c + 1 < NC) issueB(c + 1);
        CP_COMMIT();
        CP_WAIT1();             // G(c+1) done: fA(c+1), B(c) ready
        __syncthreads();        // convert(c) & cp.async data visible to all

        if (c + 1 < NC) convert(c + 1);   // overlaps with MMA below

        const uint32_t stA = sbase + AB_OFF + (uint32_t)(c & 1) * AB_BUF;
        const uint32_t stB = sbase + PB_OFF + (uint32_t)(c & 1) * PB_STG;
#pragma unroll
        for (int ks = 0; ks < 4; ks++) {
            uint32_t ah[2][4], al[2][4], bh[2][4], bl[2][4];
#pragma unroll
            for (int mb = 0; mb < 2; mb++) {
                uint32_t ad = stA + (rowA + mb * 16) * 144 + (ks * 16 + colA) * 2;
                ldsm_x4(ah[mb], ad);
                ldsm_x4(al[mb], ad + 18432);
            }
#pragma unroll
            for (int g = 0; g < 2; g++) {
                uint32_t bd = stB + (ks * 16 + rowB8) * 272 + (colB + g * 16) * 2;
                ldsm_x4_t(bh[g], bd);
                ldsm_x4_t(bl[g], bd + 17408);
            }
#pragma unroll
            for (int mb = 0; mb < 2; mb++)
#pragma unroll
                for (int nb = 0; nb < 4; nb++)
                    mma_bf16(acc[mb][nb], ah[mb], &bh[nb >> 1][(nb & 1) * 2]);
#pragma unroll
            for (int mb = 0; mb < 2; mb++)
#pragma unroll
                for (int nb = 0; nb < 4; nb++)
                    mma_bf16(acc[mb][nb], ah[mb], &bl[nb >> 1][(nb & 1) * 2]);
#pragma unroll
            for (int mb = 0; mb < 2; mb++)
#pragma unroll
                for (int nb = 0; nb < 4; nb++)
                    mma_bf16(acc[mb][nb], al[mb], &bh[nb >> 1][(nb & 1) * 2]);
        }
        __syncthreads();        // protect B/bf16A buffer reuse next iter
    }

    const int er = lane >> 2;
    const int ec = (lane & 3) * 2;
#pragma unroll
    for (int mb = 0; mb < 2; mb++)
#pragma unroll
        for (int nb = 0; nb < 4; nb++) {
            int row = wm * 32 + mb * 16 + er;
            int col = wn * 32 + nb * 8 + ec;
            float2 v0 = make_float2(acc[mb][nb][0], acc[mb][nb][1]);
            float2 v1 = make_float2(acc[mb][nb][2], acc[mb][nb][3]);
            __nv_bfloat16 h0 = __float2bfloat16(v0.x), h1 = __float2bfloat16(v0.y);
            __nv_bfloat16 h2 = __float2bfloat16(v1.x), h3 = __float2bfloat16(v1.y);
            uint32_t hi0 = pack_bf16(v0.x, v0.y);
            uint32_t hi1 = pack_bf16(v1.x, v1.y);
            uint32_t lo0 = pack_bf16(v0.x - __bfloat162float(h0), v0.y - __bfloat162float(h1));
            uint32_t lo1 = pack_bf16(v1.x - __bfloat162float(h2), v1.y - __bfloat162float(h3));
            *reinterpret_cast<uint32_t*>(outHi + oOff + (size_t)row * DD + col) = hi0;
            *reinterpret_cast<uint32_t*>(outLo + oOff + (size_t)row * DD + col) = lo0;
            *reinterpret_cast<uint32_t*>(outHi + oOff + (size_t)(row + 8) * DD + col) = hi1;
            *reinterpret_cast<uint32_t*>(outLo + oOff + (size_t)(row + 8) * DD + col) = lo1;
        }
}

// =================================================================
// Unified split-bf16 GEMM (R6). BIASED variant fuses BN partial sums.
// =================================================================
template <int KA, int NTERMS, bool BIASED>
__global__ __launch_bounds__(512)
void gemm_bf16(const __nv_bfloat16* __restrict__ Ahi, const __nv_bfloat16* __restrict__ Alo,
               const __nv_bfloat16* __restrict__ Bhi, const __nv_bfloat16* __restrict__ Blo,
               const float* __restrict__ bias,
               float* __restrict__ outF,
               __nv_bfloat16* __restrict__ outHi, __nv_bfloat16* __restrict__ outLo) {
    constexpr int NC  = KA / 64;
    constexpr int NH  = (NTERMS == 3) ? 2 : 1;
    constexpr int A_SEC = 128 * 144;
    constexpr int B_SEC = 64 * 272;
    constexpr int OFF_B = NH * A_SEC;
    constexpr int STAGE = OFF_B + NH * B_SEC;
    constexpr int SBUF_OFF = 3 * STAGE;

    size_t aOff, bOff, oOff;
    if (KA == NN) {
        aOff = (size_t)blockIdx.y * NN * NN + (size_t)blockIdx.x * 128 * NN;
        bOff = (size_t)blockIdx.y * NN * DD;
        oOff = (size_t)blockIdx.y * NN * DD + (size_t)blockIdx.x * 128 * DD;
    } else {
        aOff = (size_t)blockIdx.x * 128 * DD;
        bOff = 0;
        oOff = (size_t)blockIdx.x * 128 * DD;
    }
    Ahi += aOff; if (NTERMS == 3) Alo += aOff;
    Bhi += bOff; if (NTERMS == 3) Blo += bOff;

    extern __shared__ char smem[];
    const uint32_t sbase = smem_u32(smem);

    const int tid  = threadIdx.x;
    const int lane = tid & 31;
    const int wid  = tid >> 5;
    const int wm   = wid & 3;
    const int wn   = wid >> 2;
    const int sub  = lane >> 3;
    const int r8   = lane & 7;

    const uint32_t rowA  = wm * 32 + (sub & 1) * 8 + r8;
    const uint32_t colA  = (sub >> 1) * 8;
    const uint32_t rowB8 = (sub & 1) * 8 + r8;
    const uint32_t colB  = wn * 32 + (sub >> 1) * 8;

    float acc[2][4][4];
#pragma unroll
    for (int i = 0; i < 2; i++)
#pragma unroll
        for (int j = 0; j < 4; j++)
#pragma unroll
            for (int k = 0; k < 4; k++) acc[i][j][k] = 0.f;

    auto issue = [&](int c, int stg) {
        if (c < NC) {
            const uint32_t sb = sbase + (uint32_t)stg * STAGE;
            const int k0 = c * 64;
#pragma unroll
            for (int p = 0; p < 2 * NH; p++) {
                int i = tid + p * 512;
                int half = i >> 10, rem = i & 1023, row = rem >> 3, ch = rem & 7;
                const __nv_bfloat16* s = (half ? Alo : Ahi) + (size_t)row * KA + k0 + ch * 8;
                cp_async16(sb + half * A_SEC + row * 144 + ch * 16, s);
            }
#pragma unroll
            for (int p = 0; p < 2 * NH; p++) {
                int i = tid + p * 512;
                int half = i >> 10, rem = i & 1023, row = rem >> 4, ch = rem & 15;
                const __nv_bfloat16* s = (half ? Blo : Bhi) + (size_t)(k0 + row) * DD + ch * 8;
                cp_async16(sb + OFF_B + half * B_SEC + row * 272 + ch * 16, s);
            }
        }
        CP_COMMIT();
    };

    issue(0, 0);
    issue(1, 1);
    CP_WAIT1();
    __syncthreads();

    for (int c = 0; c < NC; c++) {
        issue(c + 2, (c + 2) % 3);
        const uint32_t st = sbase + (uint32_t)(c % 3) * STAGE;

#pragma unroll
        for (int ks = 0; ks < 4; ks++) {
            uint32_t ah[2][4], al[2][4], bh[2][4], bl[2][4];
#pragma unroll
            for (int mb = 0; mb < 2; mb++) {
                uint32_t ad = st + (rowA + mb * 16) * 144 + (ks * 16 + colA) * 2;
                ldsm_x4(ah[mb], ad);
                if (NTERMS == 3) ldsm_x4(al[mb], ad + A_SEC);
            }
#pragma unroll
            for (int g = 0; g < 2; g++) {
                uint32_t bd = st + OFF_B + (ks * 16 + rowB8) * 272 + (colB + g * 16) * 2;
                ldsm_x4_t(bh[g], bd);
                if (NTERMS == 3) ldsm_x4_t(bl[g], bd + B_SEC);
            }
#pragma unroll
            for (int mb = 0; mb < 2; mb++)
#pragma unroll
                for (int nb = 0; nb < 4; nb++)
                    mma_bf16(acc[mb][nb], ah[mb], &bh[nb >> 1][(nb & 1) * 2]);
            if (NTERMS == 3) {
#pragma unroll
                for (int mb = 0; mb < 2; mb++)
#pragma unroll
                    for (int nb = 0; nb < 4; nb++)
                        mma_bf16(acc[mb][nb], ah[mb], &bl[nb >> 1][(nb & 1) * 2]);
#pragma unroll
                for (int mb = 0; mb < 2; mb++)
#pragma unroll
                    for (int nb = 0; nb < 4; nb++)
                        mma_bf16(acc[mb][nb], al[mb], &bh[nb >> 1][(nb & 1) * 2]);
            }
        }
        CP_WAIT1();
        __syncthreads();
    }

    const int er = lane >> 2;
    const int ec = (lane & 3) * 2;
    float s8[8], q8[8];
    if (BIASED) {
#pragma unroll
        for (int i = 0; i < 8; i++) { s8[i] = 0.f; q8[i] = 0.f; }
    }
#pragma unroll
    for (int mb = 0; mb < 2; mb++)
#pragma unroll
        for (int nb = 0; nb < 4; nb++) {
            int row = wm * 32 + mb * 16 + er;
            int col = wn * 32 + nb * 8 + ec;
            float2 v0 = make_float2(acc[mb][nb][0], acc[mb][nb][1]);
            float2 v1 = make_float2(acc[mb][nb][2], acc[mb][nb][3]);
            if (BIASED) {
                float bx = bias[col], by = bias[col + 1];
                v0.x += bx; v0.y += by; v1.x += bx; v1.y += by;
                s8[nb * 2 + 0] += v0.x + v1.x;
                s8[nb * 2 + 1] += v0.y + v1.y;
                q8[nb * 2 + 0] += v0.x * v0.x + v1.x * v1.x;
                q8[nb * 2 + 1] += v0.y * v0.y + v1.y * v1.y;
                *reinterpret_cast<float2*>(outF + oOff + (size_t)row * DD + col) = v0;
                *reinterpret_cast<float2*>(outF + oOff + (size_t)(row + 8) * DD + col) = v1;
            } else {
                __nv_bfloat16 h0 = __float2bfloat16(v0.x), h1 = __float2bfloat16(v0.y);
                __nv_bfloat16 h2 = __float2bfloat16(v1.x), h3 = __float2bfloat16(v1.y);
                uint32_t hi0 = pack_bf16(v0.x, v0.y);
                uint32_t hi1 = pack_bf16(v1.x, v1.y);
                uint32_t lo0 = pack_bf16(v0.x - __bfloat162float(h0), v0.y - __bfloat162float(h1));
                uint32_t lo1 = pack_bf16(v1.x - __bfloat162float(h2), v1.y - __bfloat162float(h3));
                *reinterpret_cast<uint32_t*>(outHi + oOff + (size_t)row * DD + col) = hi0;
                *reinterpret_cast<uint32_t*>(outLo + oOff + (size_t)row * DD + col) = lo0;
                *reinterpret_cast<uint32_t*>(outHi + oOff + (size_t)(row + 8) * DD + col) = hi1;
                *reinterpret_cast<uint32_t*>(outLo + oOff + (size_t)(row + 8) * DD + col) = lo1;
            }
        }

    if (BIASED) {
#pragma unroll
        for (int off = 4; off < 32; off <<= 1) {
#pragma unroll
            for (int i = 0; i < 8; i++) {
                s8[i] += __shfl_xor_sync(0xFFFFFFFF, s8[i], off);
                q8[i] += __shfl_xor_sync(0xFFFFFFFF, q8[i], off);
            }
        }
        float* sBuf = reinterpret_cast<float*>(smem + SBUF_OFF);
        float* qBuf = sBuf + 4 * DD;
        if (lane < 4) {
#pragma unroll
            for (int nb = 0; nb < 4; nb++) {
#pragma unroll
                for (int j = 0; j < 2; j++) {
                    int col = wn * 32 + nb * 8 + lane * 2 + j;
                    sBuf[wm * DD + col] = s8[nb * 2 + j];
                    qBuf[wm * DD + col] = q8[nb * 2 + j];
                }
            }
        }
        __syncthreads();
        if (tid < DD) {
            float s = sBuf[tid] + sBuf[DD + tid] + sBuf[2 * DD + tid] + sBuf[3 * DD + tid];
            float q = qBuf[tid] + qBuf[DD + tid] + qBuf[2 * DD + tid] + qBuf[3 * DD + tid];
            g_partS[blockIdx.x * DD + tid] = s;
            g_partQ[blockIdx.x * DD + tid] = q;
        }
    }
}

// ---------------- elementwise fp32 -> (hi, lo) bf16 split ----------------
__global__ __launch_bounds__(256)
void split_kernel(const float* __restrict__ src,
                  __nv_bfloat16* __restrict__ hi, __nv_bfloat16* __restrict__ lo) {
    const size_t idx = (size_t)blockIdx.x * 256 + threadIdx.x;
    float4 v = reinterpret_cast<const float4*>(src)[idx];
    __nv_bfloat16 h0 = __float2bfloat16(v.x), h1 = __float2bfloat16(v.y);
    __nv_bfloat16 h2 = __float2bfloat16(v.z), h3 = __float2bfloat16(v.w);
    uint2 hv, lv;
    hv.x = pack_bf16(v.x, v.y); hv.y = pack_bf16(v.z, v.w);
    lv.x = pack_bf16(v.x - __bfloat162float(h0), v.y - __bfloat162float(h1));
    lv.y = pack_bf16(v.z - __bfloat162float(h2), v.w - __bfloat162float(h3));
    reinterpret_cast<uint2*>(hi)[idx] = hv;
    reinterpret_cast<uint2*>(lo)[idx] = lv;
}

// =================================================================
// Fused BN: every CTA reduces the partial sums (L2-resident, deterministic),
// computes scale/shift, then applies BN+ReLU to its 256-row slice.
// FINAL=false -> split bf16 hi/lo out; FINAL=true -> fp32 out.
// Grid: 128 CTAs x 256 threads.
// =================================================================
template <bool FINAL>
__global__ __launch_bounds__(256)
void bn_stats_apply(const float* __restrict__ gamma, const float* __restrict__ beta,
                    const float* __restrict__ x,
                    float* __restrict__ outF,
                    __nv_bfloat16* __restrict__ yhi, __nv_bfloat16* __restrict__ ylo) {
    __shared__ float sS[2][DD], sQ[2][DD];
    __shared__ float scl[DD], shf[DD];
    const int tid  = threadIdx.x;
    const int col  = tid & 127;
    const int half = tid >> 7;

    float s = 0.f, q = 0.f;
    for (int p = half; p < BN_BLOCKS; p += 2) {
        s += g_partS[p * DD + col];
        q += g_partQ[p * DD + col];
    }
    sS[half][col] = s;
    sQ[half][col] = q;
    __syncthreads();
    if (tid < DD) {
        float S = sS[0][tid] + sS[1][tid];
        float Q = sQ[0][tid] + sQ[1][tid];
        const float inv_m = 1.0f / (float)MTOT;
        float mean = S * inv_m;
        float var  = Q * inv_m - mean * mean;
        float sc   = gamma[tid] * rsqrtf(var + BN_EPS);
        scl[tid] = sc;
        shf[tid] = beta[tid] - mean * sc;
    }
    __syncthreads();

    const int base = blockIdx.x * 8192;   // float4 units: 256 rows x 32
#pragma unroll 8
    for (int i = 0; i < 32; i++) {
        int idx = base + i * 256 + tid;
        int c4  = idx & 31;
        float4 v = reinterpret_cast<const float4*>(x)[idx];
        float4 sc = *reinterpret_cast<const float4*>(&scl[c4 * 4]);
        float4 sh = *reinterpret_cast<const float4*>(&shf[c4 * 4]);
        float4 r;
        r.x = fmaxf(fmaf(v.x, sc.x, sh.x), 0.f);
        r.y = fmaxf(fmaf(v.y, sc.y, sh.y), 0.f);
        r.z = fmaxf(fmaf(v.z, sc.z, sh.z), 0.f);
        r.w = fmaxf(fmaf(v.w, sc.w, sh.w), 0.f);
        if (FINAL) {
            reinterpret_cast<float4*>(outF)[idx] = r;
        } else {
            __nv_bfloat16 h0 = __float2bfloat16(r.x), h1 = __float2bfloat16(r.y);
            __nv_bfloat16 h2 = __float2bfloat16(r.z), h3 = __float2bfloat16(r.w);
            uint2 hv, lv;
            hv.x = pack_bf16(r.x, r.y); hv.y = pack_bf16(r.z, r.w);
            lv.x = pack_bf16(r.x - __bfloat162float(h0), r.y - __bfloat162float(h1));
            lv.y = pack_bf16(r.z - __bfloat162float(h2), r.w - __bfloat162float(h3));
            reinterpret_cast<uint2*>(yhi)[idx] = hv;
            reinterpret_cast<uint2*>(ylo)[idx] = lv;
        }
    }
}

// ---------------- launch ----------------
extern "C" void kernel_launch(void* const* d_in, const int* in_sizes, int n_in,
                              void* d_out, int out_size) {
    const float* x     = (const float*)d_in[0];
    const float* adj   = (const float*)d_in[2];
    const float* W1    = (const float*)d_in[3];
    const float* b1    = (const float*)d_in[4];
    const float* W2    = (const float*)d_in[5];
    const float* b2    = (const float*)d_in[6];
    const float* g_in   = (const float*)d_in[7];
    const float* be_in  = (const float*)d_in[8];
    const float* g_out  = (const float*)d_in[9];
    const float* be_out = (const float*)d_in[10];
    float* out = (float*)d_out;

    __nv_bfloat16 *adjHi, *hHi, *hLo, *pHi, *pLo, *yHi, *yLo;
    __nv_bfloat16 *W1Hi, *W1Lo, *W2Hi, *W2Lo;
    float *z;
    cudaGetSymbolAddress((void**)&adjHi, g_adjHi);
    cudaGetSymbolAddress((void**)&hHi, g_hHi);
    cudaGetSymbolAddress((void**)&hLo, g_hLo);
    cudaGetSymbolAddress((void**)&pHi, g_pHi);
    cudaGetSymbolAddress((void**)&pLo, g_pLo);
    cudaGetSymbolAddress((void**)&yHi, g_yHi);
    cudaGetSymbolAddress((void**)&yLo, g_yLo);
    cudaGetSymbolAddress((void**)&W1Hi, g_W1Hi);
    cudaGetSymbolAddress((void**)&W1Lo, g_W1Lo);
    cudaGetSymbolAddress((void**)&W2Hi, g_W2Hi);
    cudaGetSymbolAddress((void**)&W2Lo, g_W2Lo);
    cudaGetSymbolAddress((void**)&z, g_z);

    constexpr int SMEM3B = 3 * (2 * 128 * 144 + 2 * 64 * 272) + 4096;  // 219136
    constexpr int SMEM1  = 3 * (128 * 144 + 64 * 272);                 // 107520
    cudaFuncSetAttribute((const void*)gemm_pool_convert,
                         cudaFuncAttributeMaxDynamicSharedMemorySize, POOL_SMEM);
    cudaFuncSetAttribute((const void*)gemm_bf16<NN, 1, false>,
                         cudaFuncAttributeMaxDynamicSharedMemorySize, SMEM1);
    cudaFuncSetAttribute((const void*)gemm_bf16<DD, 3, true>,
                         cudaFuncAttributeMaxDynamicSharedMemorySize, SMEM3B);

    // small one-time operand splits
    split_kernel<<<MTOT * DD / 1024, 256>>>(x, hHi, hLo);
    split_kernel<<<LL * DD * DD / 1024, 256>>>(W1, W1Hi, W1Lo);
    split_kernel<<<LL * DD * DD / 1024, 256>>>(W2, W2Hi, W2Lo);

    const dim3 gridPool(NN / 128, BATCH);
    const int  gridW = MTOT / 128;

    for (int l = 0; l < LL; l++) {
        if (l == 0)
            gemm_pool_convert<<<gridPool, 512, POOL_SMEM>>>(
                adj, hHi, hLo, adjHi, pHi, pLo);
        else
            gemm_bf16<NN, 1, false><<<gridPool, 512, SMEM1>>>(
                adjHi, nullptr, hHi, nullptr, nullptr, nullptr, pHi, pLo);

        gemm_bf16<DD, 3, true><<<gridW, 512, SMEM3B>>>(
            pHi, pLo, W1Hi + (size_t)l * DD * DD, W1Lo + (size_t)l * DD * DD,
            b1 + (size_t)l * DD, z, nullptr, nullptr);

        bn_stats_apply<false><<<128, 256>>>(
            g_in + (size_t)l * DD, be_in + (size_t)l * DD, z, nullptr, yHi, yLo);

        gemm_bf16<DD, 3, true><<<gridW, 512, SMEM3B>>>(
            yHi, yLo, W2Hi + (size_t)l * DD * DD, W2Lo + (size_t)l * DD * DD,
            b2 + (size_t)l * DD, z, nullptr, nullptr);

        if (l == LL - 1)
            bn_stats_apply<true><<<128, 256>>>(
                g_out + (size_t)l * DD, be_out + (size_t)l * DD, z, out, nullptr, nullptr);
        else
            bn_stats_apply<false><<<128, 256>>>(
                g_out + (size_t)l * DD, be_out + (size_t)l * DD, z, nullptr, hHi, hLo);
    }
}

// round 8
// speedup vs baseline: 2.7995x; 1.0500x over previous
#include <cuda_runtime.h>
#include <cuda_bf16.h>
#include <cstdint>

#define BATCH 32
#define NN    1024
#define DD    128
#define LL    2
#define MTOT  (BATCH * NN)
#define BN_EPS 1e-5f
#define BN_BLOCKS 256

// ---------------- scratch (no allocation allowed) ----------------
__device__ __nv_bfloat16 g_adjHi[(size_t)BATCH * NN * NN];
__device__ __nv_bfloat16 g_hHi[MTOT * DD];
__device__ __nv_bfloat16 g_hLo[MTOT * DD];
__device__ __nv_bfloat16 g_pHi[MTOT * DD];
__device__ __nv_bfloat16 g_pLo[MTOT * DD];
__device__ __nv_bfloat16 g_yHi[MTOT * DD];
__device__ __nv_bfloat16 g_yLo[MTOT * DD];
__device__ __nv_bfloat16 g_W1Hi[LL * DD * DD];
__device__ __nv_bfloat16 g_W1Lo[LL * DD * DD];
__device__ __nv_bfloat16 g_W2Hi[LL * DD * DD];
__device__ __nv_bfloat16 g_W2Lo[LL * DD * DD];
__device__ float g_z[MTOT * DD];
__device__ float g_partS[BN_BLOCKS * DD];
__device__ float g_partQ[BN_BLOCKS * DD];

// ---------------- helpers ----------------
__device__ __forceinline__ uint32_t smem_u32(const void* p) {
    uint32_t a;
    asm("{ .reg .u64 t; cvta.to.shared.u64 t, %1; cvt.u32.u64 %0, t; }" : "=r"(a) : "l"(p));
    return a;
}
__device__ __forceinline__ void ldsm_x4(uint32_t* r, uint32_t addr) {
    asm volatile("ldmatrix.sync.aligned.m8n8.x4.shared.b16 {%0,%1,%2,%3}, [%4];"
                 : "=r"(r[0]), "=r"(r[1]), "=r"(r[2]), "=r"(r[3]) : "r"(addr));
}
__device__ __forceinline__ void ldsm_x4_t(uint32_t* r, uint32_t addr) {
    asm volatile("ldmatrix.sync.aligned.m8n8.x4.trans.shared.b16 {%0,%1,%2,%3}, [%4];"
                 : "=r"(r[0]), "=r"(r[1]), "=r"(r[2]), "=r"(r[3]) : "r"(addr));
}
__device__ __forceinline__ void mma_bf16(float* c, const uint32_t* a, const uint32_t* b) {
    asm volatile(
        "mma.sync.aligned.m16n8k16.row.col.f32.bf16.bf16.f32 "
        "{%0,%1,%2,%3}, {%4,%5,%6,%7}, {%8,%9}, {%0,%1,%2,%3};"
        : "+f"(c[0]), "+f"(c[1]), "+f"(c[2]), "+f"(c[3])
        : "r"(a[0]), "r"(a[1]), "r"(a[2]), "r"(a[3]), "r"(b[0]), "r"(b[1]));
}
__device__ __forceinline__ void cp_async16(uint32_t dst, const void* src) {
    asm volatile("cp.async.cg.shared.global [%0], [%1], 16;" :: "r"(dst), "l"(src));
}
#define CP_COMMIT() asm volatile("cp.async.commit_group;" ::: "memory")
#define CP_WAIT1()  asm volatile("cp.async.wait_group 1;"  ::: "memory")

__device__ __forceinline__ uint32_t pack_bf16(float x, float y) {
    __nv_bfloat162 t = __floats2bfloat162_rn(x, y);
    return *reinterpret_cast<uint32_t*>(&t);
}

// =================================================================
// Pool layer-1 GEMM, register-staged adj conversion.
// adj chunk (c+1) loaded via LDG.128 into registers (latency hidden by MMA(c)),
// converted to bf16 hi/lo smem AFTER the MMA. No fp32 smem round-trip.
// bf16 A: 2 buffers. B: 3-stage cp.async. Streams adjHi to gmem for layer 2.
// =================================================================
#define AB_BUF   36864      // hi(18432) + lo(18432)
#define PB_OFF   73728
#define PB_STG   34816      // hi(17408) + lo(17408)
#define POOL_SMEM 178176

__global__ __launch_bounds__(512)
void gemm_pool_convert(const float* __restrict__ A,
                       const __nv_bfloat16* __restrict__ Bhi,
                       const __nv_bfloat16* __restrict__ Blo,
                       __nv_bfloat16* __restrict__ adjHiOut,
                       __nv_bfloat16* __restrict__ outHi,
                       __nv_bfloat16* __restrict__ outLo) {
    constexpr int NC = NN / 64;

    const size_t aOff = (size_t)blockIdx.y * NN * NN + (size_t)blockIdx.x * 128 * NN;
    const size_t bOff = (size_t)blockIdx.y * NN * DD;
    const size_t oOff = (size_t)blockIdx.y * NN * DD + (size_t)blockIdx.x * 128 * DD;
    A += aOff;
    adjHiOut += aOff;
    Bhi += bOff; Blo += bOff;

    extern __shared__ char smem[];
    const uint32_t sbase = smem_u32(smem);

    const int tid  = threadIdx.x;
    const int lane = tid & 31;
    const int wid  = tid >> 5;
    const int wm   = wid & 3;
    const int wn   = wid >> 2;
    const int sub  = lane >> 3;
    const int r8   = lane & 7;

    const uint32_t rowA  = wm * 32 + (sub & 1) * 8 + r8;
    const uint32_t colA  = (sub >> 1) * 8;
    const uint32_t rowB8 = (sub & 1) * 8 + r8;
    const uint32_t colB  = wn * 32 + (sub >> 1) * 8;

    // per-thread A mapping: 4 x float4 per 128x64 chunk
    const int aRow[4] = { (tid) >> 4, (tid + 512) >> 4, (tid + 1024) >> 4, (tid + 1536) >> 4 };
    const int aSeg = tid & 15;

    float acc[2][4][4];
#pragma unroll
    for (int i = 0; i < 2; i++)
#pragma unroll
        for (int j = 0; j < 4; j++)
#pragma unroll
            for (int k = 0; k < 4; k++) acc[i][j][k] = 0.f;

    auto issueB = [&](int c) {
        const uint32_t sb = sbase + PB_OFF + (uint32_t)(c % 3) * PB_STG;
#pragma unroll
        for (int p = 0; p < 4; p++) {
            int i = tid + p * 512;
            int half = i >> 10, rem = i & 1023, row = rem >> 4, ch = rem & 15;
            const __nv_bfloat16* s = (half ? Blo : Bhi) + (size_t)(c * 64 + row) * DD + ch * 8;
            cp_async16(sb + half * 17408 + row * 272 + ch * 16, s);
        }
    };
    float4 aR[4];
    auto loadA = [&](int c) {
#pragma unroll
        for (int p = 0; p < 4; p++)
            aR[p] = *reinterpret_cast<const float4*>(A + (size_t)aRow[p] * NN + c * 64 + aSeg * 4);
    };
    auto convert = [&](int cc) {   // regs -> bf16 smem buf (cc&1) + STG adjHi
        char* dhi = smem + (cc & 1) * AB_BUF;
        char* dlo = dhi + 18432;
#pragma unroll
        for (int p = 0; p < 4; p++) {
            float4 v = aR[p];
            __nv_bfloat16 h0 = __float2bfloat16(v.x), h1 = __float2bfloat16(v.y);
            __nv_bfloat16 h2 = __float2bfloat16(v.z), h3 = __float2bfloat16(v.w);
            uint2 hv, lv;
            hv.x = pack_bf16(v.x, v.y); hv.y = pack_bf16(v.z, v.w);
            lv.x = pack_bf16(v.x - __bfloat162float(h0), v.y - __bfloat162float(h1));
            lv.y = pack_bf16(v.z - __bfloat162float(h2), v.w - __bfloat162float(h3));
            *reinterpret_cast<uint2*>(dhi + aRow[p] * 144 + aSeg * 8) = hv;
            *reinterpret_cast<uint2*>(dlo + aRow[p] * 144 + aSeg * 8) = lv;
            *reinterpret_cast<uint2*>(adjHiOut + (size_t)aRow[p] * NN + cc * 64 + aSeg * 4) = hv;
        }
    };

    // prologue
    loadA(0);
    issueB(0); CP_COMMIT();
    issueB(1); CP_COMMIT();
    convert(0);                 // buf0
    CP_WAIT1();                 // B(0) ready
    __syncthreads();            // convert(0) visible

    for (int c = 0; c < NC; c++) {
        if (c + 1 < NC) loadA(c + 1);        // LDG in flight during MMA
        if (c + 2 < NC) issueB(c + 2);
        CP_COMMIT();

        // ---- MMA(c) on bf16A buf(c&1), B stage (c%3) ----
        const uint32_t stA = sbase + (uint32_t)(c & 1) * AB_BUF;
        const uint32_t stB = sbase + PB_OFF + (uint32_t)(c % 3) * PB_STG;
#pragma unroll
        for (int ks = 0; ks < 4; ks++) {
            uint32_t ah[2][4], al[2][4], bh[2][4], bl[2][4];
#pragma unroll
            for (int mb = 0; mb < 2; mb++) {
                uint32_t ad = stA + (rowA + mb * 16) * 144 + (ks * 16 + colA) * 2;
                ldsm_x4(ah[mb], ad);
                ldsm_x4(al[mb], ad + 18432);
            }
#pragma unroll
            for (int g = 0; g < 2; g++) {
                uint32_t bd = stB + (ks * 16 + rowB8) * 272 + (colB + g * 16) * 2;
                ldsm_x4_t(bh[g], bd);
                ldsm_x4_t(bl[g], bd + 17408);
            }
#pragma unroll
            for (int mb = 0; mb < 2; mb++)
#pragma unroll
                for (int nb = 0; nb < 4; nb++)
                    mma_bf16(acc[mb][nb], ah[mb], &bh[nb >> 1][(nb & 1) * 2]);
#pragma unroll
            for (int mb = 0; mb < 2; mb++)
#pragma unroll
                for (int nb = 0; nb < 4; nb++)
                    mma_bf16(acc[mb][nb], ah[mb], &bl[nb >> 1][(nb & 1) * 2]);
#pragma unroll
            for (int mb = 0; mb < 2; mb++)
#pragma unroll
                for (int nb = 0; nb < 4; nb++)
                    mma_bf16(acc[mb][nb], al[mb], &bh[nb >> 1][(nb & 1) * 2]);
        }

        if (c + 1 < NC) convert(c + 1);      // writes buf((c+1)&1); regs ready by now

        CP_WAIT1();                          // B(c+1) ready
        __syncthreads();                     // convert visible; MMA done before next overwrite
    }

    // ---- epilogue: split hi/lo bf16 out ----
    const int er = lane >> 2;
    const int ec = (lane & 3) * 2;
#pragma unroll
    for (int mb = 0; mb < 2; mb++)
#pragma unroll
        for (int nb = 0; nb < 4; nb++) {
            int row = wm * 32 + mb * 16 + er;
            int col = wn * 32 + nb * 8 + ec;
            float2 v0 = make_float2(acc[mb][nb][0], acc[mb][nb][1]);
            float2 v1 = make_float2(acc[mb][nb][2], acc[mb][nb][3]);
            __nv_bfloat16 h0 = __float2bfloat16(v0.x), h1 = __float2bfloat16(v0.y);
            __nv_bfloat16 h2 = __float2bfloat16(v1.x), h3 = __float2bfloat16(v1.y);
            uint32_t hi0 = pack_bf16(v0.x, v0.y);
            uint32_t hi1 = pack_bf16(v1.x, v1.y);
            uint32_t lo0 = pack_bf16(v0.x - __bfloat162float(h0), v0.y - __bfloat162float(h1));
            uint32_t lo1 = pack_bf16(v1.x - __bfloat162float(h2), v1.y - __bfloat162float(h3));
            *reinterpret_cast<uint32_t*>(outHi + oOff + (size_t)row * DD + col) = hi0;
            *reinterpret_cast<uint32_t*>(outLo + oOff + (size_t)row * DD + col) = lo0;
            *reinterpret_cast<uint32_t*>(outHi + oOff + (size_t)(row + 8) * DD + col) = hi1;
            *reinterpret_cast<uint32_t*>(outLo + oOff + (size_t)(row + 8) * DD + col) = lo1;
        }
}

// =================================================================
// Unified split-bf16 GEMM. BIASED variant fuses BN partial sums.
// =================================================================
template <int KA, int NTERMS, bool BIASED>
__global__ __launch_bounds__(512)
void gemm_bf16(const __nv_bfloat16* __restrict__ Ahi, const __nv_bfloat16* __restrict__ Alo,
               const __nv_bfloat16* __restrict__ Bhi, const __nv_bfloat16* __restrict__ Blo,
               const float* __restrict__ bias,
               float* __restrict__ outF,
               __nv_bfloat16* __restrict__ outHi, __nv_bfloat16* __restrict__ outLo) {
    constexpr int NC  = KA / 64;
    constexpr int NH  = (NTERMS == 3) ? 2 : 1;
    constexpr int A_SEC = 128 * 144;
    constexpr int B_SEC = 64 * 272;
    constexpr int OFF_B = NH * A_SEC;
    constexpr int STAGE = OFF_B + NH * B_SEC;
    constexpr int SBUF_OFF = 3 * STAGE;

    size_t aOff, bOff, oOff;
    if (KA == NN) {
        aOff = (size_t)blockIdx.y * NN * NN + (size_t)blockIdx.x * 128 * NN;
        bOff = (size_t)blockIdx.y * NN * DD;
        oOff = (size_t)blockIdx.y * NN * DD + (size_t)blockIdx.x * 128 * DD;
    } else {
        aOff = (size_t)blockIdx.x * 128 * DD;
        bOff = 0;
        oOff = (size_t)blockIdx.x * 128 * DD;
    }
    Ahi += aOff; if (NTERMS == 3) Alo += aOff;
    Bhi += bOff; if (NTERMS == 3) Blo += bOff;

    extern __shared__ char smem[];
    const uint32_t sbase = smem_u32(smem);

    const int tid  = threadIdx.x;
    const int lane = tid & 31;
    const int wid  = tid >> 5;
    const int wm   = wid & 3;
    const int wn   = wid >> 2;
    const int sub  = lane >> 3;
    const int r8   = lane & 7;

    const uint32_t rowA  = wm * 32 + (sub & 1) * 8 + r8;
    const uint32_t colA  = (sub >> 1) * 8;
    const uint32_t rowB8 = (sub & 1) * 8 + r8;
    const uint32_t colB  = wn * 32 + (sub >> 1) * 8;

    float acc[2][4][4];
#pragma unroll
    for (int i = 0; i < 2; i++)
#pragma unroll
        for (int j = 0; j < 4; j++)
#pragma unroll
            for (int k = 0; k < 4; k++) acc[i][j][k] = 0.f;

    auto issue = [&](int c, int stg) {
        if (c < NC) {
            const uint32_t sb = sbase + (uint32_t)stg * STAGE;
            const int k0 = c * 64;
#pragma unroll
            for (int p = 0; p < 2 * NH; p++) {
                int i = tid + p * 512;
                int half = i >> 10, rem = i & 1023, row = rem >> 3, ch = rem & 7;
                const __nv_bfloat16* s = (half ? Alo : Ahi) + (size_t)row * KA + k0 + ch * 8;
                cp_async16(sb + half * A_SEC + row * 144 + ch * 16, s);
            }
#pragma unroll
            for (int p = 0; p < 2 * NH; p++) {
                int i = tid + p * 512;
                int half = i >> 10, rem = i & 1023, row = rem >> 4, ch = rem & 15;
                const __nv_bfloat16* s = (half ? Blo : Bhi) + (size_t)(k0 + row) * DD + ch * 8;
                cp_async16(sb + OFF_B + half * B_SEC + row * 272 + ch * 16, s);
            }
        }
        CP_COMMIT();
    };

    issue(0, 0);
    issue(1, 1);
    CP_WAIT1();
    __syncthreads();

    for (int c = 0; c < NC; c++) {
        issue(c + 2, (c + 2) % 3);
        const uint32_t st = sbase + (uint32_t)(c % 3) * STAGE;

#pragma unroll
        for (int ks = 0; ks < 4; ks++) {
            uint32_t ah[2][4], al[2][4], bh[2][4], bl[2][4];
#pragma unroll
            for (int mb = 0; mb < 2; mb++) {
                uint32_t ad = st + (rowA + mb * 16) * 144 + (ks * 16 + colA) * 2;
                ldsm_x4(ah[mb], ad);
                if (NTERMS == 3) ldsm_x4(al[mb], ad + A_SEC);
            }
#pragma unroll
            for (int g = 0; g < 2; g++) {
                uint32_t bd = st + OFF_B + (ks * 16 + rowB8) * 272 + (colB + g * 16) * 2;
                ldsm_x4_t(bh[g], bd);
                if (NTERMS == 3) ldsm_x4_t(bl[g], bd + B_SEC);
            }
#pragma unroll
            for (int mb = 0; mb < 2; mb++)
#pragma unroll
                for (int nb = 0; nb < 4; nb++)
                    mma_bf16(acc[mb][nb], ah[mb], &bh[nb >> 1][(nb & 1) * 2]);
            if (NTERMS == 3) {
#pragma unroll
                for (int mb = 0; mb < 2; mb++)
#pragma unroll
                    for (int nb = 0; nb < 4; nb++)
                        mma_bf16(acc[mb][nb], ah[mb], &bl[nb >> 1][(nb & 1) * 2]);
#pragma unroll
                for (int mb = 0; mb < 2; mb++)
#pragma unroll
                    for (int nb = 0; nb < 4; nb++)
                        mma_bf16(acc[mb][nb], al[mb], &bh[nb >> 1][(nb & 1) * 2]);
            }
        }
        CP_WAIT1();
        __syncthreads();
    }

    const int er = lane >> 2;
    const int ec = (lane & 3) * 2;
    float s8[8], q8[8];
    if (BIASED) {
#pragma unroll
        for (int i = 0; i < 8; i++) { s8[i] = 0.f; q8[i] = 0.f; }
    }
#pragma unroll
    for (int mb = 0; mb < 2; mb++)
#pragma unroll
        for (int nb = 0; nb < 4; nb++) {
            int row = wm * 32 + mb * 16 + er;
            int col = wn * 32 + nb * 8 + ec;
            float2 v0 = make_float2(acc[mb][nb][0], acc[mb][nb][1]);
            float2 v1 = make_float2(acc[mb][nb][2], acc[mb][nb][3]);
            if (BIASED) {
                float bx = bias[col], by = bias[col + 1];
                v0.x += bx; v0.y += by; v1.x += bx; v1.y += by;
                s8[nb * 2 + 0] += v0.x + v1.x;
                s8[nb * 2 + 1] += v0.y + v1.y;
                q8[nb * 2 + 0] += v0.x * v0.x + v1.x * v1.x;
                q8[nb * 2 + 1] += v0.y * v0.y + v1.y * v1.y;
                *reinterpret_cast<float2*>(outF + oOff + (size_t)row * DD + col) = v0;
                *reinterpret_cast<float2*>(outF + oOff + (size_t)(row + 8) * DD + col) = v1;
            } else {
                __nv_bfloat16 h0 = __float2bfloat16(v0.x), h1 = __float2bfloat16(v0.y);
                __nv_bfloat16 h2 = __float2bfloat16(v1.x), h3 = __float2bfloat16(v1.y);
                uint32_t hi0 = pack_bf16(v0.x, v0.y);
                uint32_t hi1 = pack_bf16(v1.x, v1.y);
                uint32_t lo0 = pack_bf16(v0.x - __bfloat162float(h0), v0.y - __bfloat162float(h1));
                uint32_t lo1 = pack_bf16(v1.x - __bfloat162float(h2), v1.y - __bfloat162float(h3));
                *reinterpret_cast<uint32_t*>(outHi + oOff + (size_t)row * DD + col) = hi0;
                *reinterpret_cast<uint32_t*>(outLo + oOff + (size_t)row * DD + col) = lo0;
                *reinterpret_cast<uint32_t*>(outHi + oOff + (size_t)(row + 8) * DD + col) = hi1;
                *reinterpret_cast<uint32_t*>(outLo + oOff + (size_t)(row + 8) * DD + col) = lo1;
            }
        }

    if (BIASED) {
#pragma unroll
        for (int off = 4; off < 32; off <<= 1) {
#pragma unroll
            for (int i = 0; i < 8; i++) {
                s8[i] += __shfl_xor_sync(0xFFFFFFFF, s8[i], off);
                q8[i] += __shfl_xor_sync(0xFFFFFFFF, q8[i], off);
            }
        }
        float* sBuf = reinterpret_cast<float*>(smem + SBUF_OFF);
        float* qBuf = sBuf + 4 * DD;
        if (lane < 4) {
#pragma unroll
            for (int nb = 0; nb < 4; nb++) {
#pragma unroll
                for (int j = 0; j < 2; j++) {
                    int col = wn * 32 + nb * 8 + lane * 2 + j;
                    sBuf[wm * DD + col] = s8[nb * 2 + j];
                    qBuf[wm * DD + col] = q8[nb * 2 + j];
                }
            }
        }
        __syncthreads();
        if (tid < DD) {
            float s = sBuf[tid] + sBuf[DD + tid] + sBuf[2 * DD + tid] + sBuf[3 * DD + tid];
            float q = qBuf[tid] + qBuf[DD + tid] + qBuf[2 * DD + tid] + qBuf[3 * DD + tid];
            g_partS[blockIdx.x * DD + tid] = s;
            g_partQ[blockIdx.x * DD + tid] = q;
        }
    }
}

// ---------------- elementwise fp32 -> (hi, lo) bf16 split ----------------
__global__ __launch_bounds__(256)
void split_kernel(const float* __restrict__ src,
                  __nv_bfloat16* __restrict__ hi, __nv_bfloat16* __restrict__ lo) {
    const size_t idx = (size_t)blockIdx.x * 256 + threadIdx.x;
    float4 v = reinterpret_cast<const float4*>(src)[idx];
    __nv_bfloat16 h0 = __float2bfloat16(v.x), h1 = __float2bfloat16(v.y);
    __nv_bfloat16 h2 = __float2bfloat16(v.z), h3 = __float2bfloat16(v.w);
    uint2 hv, lv;
    hv.x = pack_bf16(v.x, v.y); hv.y = pack_bf16(v.z, v.w);
    lv.x = pack_bf16(v.x - __bfloat162float(h0), v.y - __bfloat162float(h1));
    lv.y = pack_bf16(v.z - __bfloat162float(h2), v.w - __bfloat162float(h3));
    reinterpret_cast<uint2*>(hi)[idx] = hv;
    reinterpret_cast<uint2*>(lo)[idx] = lv;
}

// =================================================================
// Fused BN: reduce partials (L2-resident), compute scale/shift, apply.
// =================================================================
template <bool FINAL>
__global__ __launch_bounds__(256)
void bn_stats_apply(const float* __restrict__ gamma, const float* __restrict__ beta,
                    const float* __restrict__ x,
                    float* __restrict__ outF,
                    __nv_bfloat16* __restrict__ yhi, __nv_bfloat16* __restrict__ ylo) {
    __shared__ float sS[2][DD], sQ[2][DD];
    __shared__ float scl[DD], shf[DD];
    const int tid  = threadIdx.x;
    const int col  = tid & 127;
    const int half = tid >> 7;

    float s = 0.f, q = 0.f;
    for (int p = half; p < BN_BLOCKS; p += 2) {
        s += g_partS[p * DD + col];
        q += g_partQ[p * DD + col];
    }
    sS[half][col] = s;
    sQ[half][col] = q;
    __syncthreads();
    if (tid < DD) {
        float S = sS[0][tid] + sS[1][tid];
        float Q = sQ[0][tid] + sQ[1][tid];
        const float inv_m = 1.0f / (float)MTOT;
        float mean = S * inv_m;
        float var  = Q * inv_m - mean * mean;
        float sc   = gamma[tid] * rsqrtf(var + BN_EPS);
        scl[tid] = sc;
        shf[tid] = beta[tid] - mean * sc;
    }
    __syncthreads();

    const int base = blockIdx.x * 8192;
#pragma unroll 8
    for (int i = 0; i < 32; i++) {
        int idx = base + i * 256 + tid;
        int c4  = idx & 31;
        float4 v = reinterpret_cast<const float4*>(x)[idx];
        float4 sc = *reinterpret_cast<const float4*>(&scl[c4 * 4]);
        float4 sh = *reinterpret_cast<const float4*>(&shf[c4 * 4]);
        float4 r;
        r.x = fmaxf(fmaf(v.x, sc.x, sh.x), 0.f);
        r.y = fmaxf(fmaf(v.y, sc.y, sh.y), 0.f);
        r.z = fmaxf(fmaf(v.z, sc.z, sh.z), 0.f);
        r.w = fmaxf(fmaf(v.w, sc.w, sh.w), 0.f);
        if (FINAL) {
            reinterpret_cast<float4*>(outF)[idx] = r;
        } else {
            __nv_bfloat16 h0 = __float2bfloat16(r.x), h1 = __float2bfloat16(r.y);
            __nv_bfloat16 h2 = __float2bfloat16(r.z), h3 = __float2bfloat16(r.w);
            uint2 hv, lv;
            hv.x = pack_bf16(r.x, r.y); hv.y = pack_bf16(r.z, r.w);
            lv.x = pack_bf16(r.x - __bfloat162float(h0), r.y - __bfloat162float(h1));
            lv.y = pack_bf16(r.z - __bfloat162float(h2), r.w - __bfloat162float(h3));
            reinterpret_cast<uint2*>(yhi)[idx] = hv;
            reinterpret_cast<uint2*>(ylo)[idx] = lv;
        }
    }
}

// ---------------- launch ----------------
extern "C" void kernel_launch(void* const* d_in, const int* in_sizes, int n_in,
                              void* d_out, int out_size) {
    const float* x     = (const float*)d_in[0];
    const float* adj   = (const float*)d_in[2];
    const float* W1    = (const float*)d_in[3];
    const float* b1    = (const float*)d_in[4];
    const float* W2    = (const float*)d_in[5];
    const float* b2    = (const float*)d_in[6];
    const float* g_in   = (const float*)d_in[7];
    const float* be_in  = (const float*)d_in[8];
    const float* g_out  = (const float*)d_in[9];
    const float* be_out = (const float*)d_in[10];
    float* out = (float*)d_out;

    __nv_bfloat16 *adjHi, *hHi, *hLo, *pHi, *pLo, *yHi, *yLo;
    __nv_bfloat16 *W1Hi, *W1Lo, *W2Hi, *W2Lo;
    float *z;
    cudaGetSymbolAddress((void**)&adjHi, g_adjHi);
    cudaGetSymbolAddress((void**)&hHi, g_hHi);
    cudaGetSymbolAddress((void**)&hLo, g_hLo);
    cudaGetSymbolAddress((void**)&pHi, g_pHi);
    cudaGetSymbolAddress((void**)&pLo, g_pLo);
    cudaGetSymbolAddress((void**)&yHi, g_yHi);
    cudaGetSymbolAddress((void**)&yLo, g_yLo);
    cudaGetSymbolAddress((void**)&W1Hi, g_W1Hi);
    cudaGetSymbolAddress((void**)&W1Lo, g_W1Lo);
    cudaGetSymbolAddress((void**)&W2Hi, g_W2Hi);
    cudaGetSymbolAddress((void**)&W2Lo, g_W2Lo);
    cudaGetSymbolAddress((void**)&z, g_z);

    constexpr int SMEM3B = 3 * (2 * 128 * 144 + 2 * 64 * 272) + 4096;  // 219136
    constexpr int SMEM1  = 3 * (128 * 144 + 64 * 272);                 // 107520
    cudaFuncSetAttribute((const void*)gemm_pool_convert,
                         cudaFuncAttributeMaxDynamicSharedMemorySize, POOL_SMEM);
    cudaFuncSetAttribute((const void*)gemm_bf16<NN, 1, false>,
                         cudaFuncAttributeMaxDynamicSharedMemorySize, SMEM1);
    cudaFuncSetAttribute((const void*)gemm_bf16<DD, 3, true>,
                         cudaFuncAttributeMaxDynamicSharedMemorySize, SMEM3B);

    split_kernel<<<MTOT * DD / 1024, 256>>>(x, hHi, hLo);
    split_kernel<<<LL * DD * DD / 1024, 256>>>(W1, W1Hi, W1Lo);
    split_kernel<<<LL * DD * DD / 1024, 256>>>(W2, W2Hi, W2Lo);

    const dim3 gridPool(NN / 128, BATCH);
    const int  gridW = MTOT / 128;

    for (int l = 0; l < LL; l++) {
        if (l == 0)
            gemm_pool_convert<<<gridPool, 512, POOL_SMEM>>>(
                adj, hHi, hLo, adjHi, pHi, pLo);
        else
            gemm_bf16<NN, 1, false><<<gridPool, 512, SMEM1>>>(
                adjHi, nullptr, hHi, nullptr, nullptr, nullptr, pHi, pLo);

        gemm_bf16<DD, 3, true><<<gridW, 512, SMEM3B>>>(
            pHi, pLo, W1Hi + (size_t)l * DD * DD, W1Lo + (size_t)l * DD * DD,
            b1 + (size_t)l * DD, z, nullptr, nullptr);

        bn_stats_apply<false><<<128, 256>>>(
            g_in + (size_t)l * DD, be_in + (size_t)l * DD, z, nullptr, yHi, yLo);

        gemm_bf16<DD, 3, true><<<gridW, 512, SMEM3B>>>(
            yHi, yLo, W2Hi + (size_t)l * DD * DD, W2Lo + (size_t)l * DD * DD,
            b2 + (size_t)l * DD, z, nullptr, nullptr);

        if (l == LL - 1)
            bn_stats_apply<true><<<128, 256>>>(
                g_out + (size_t)l * DD, be_out + (size_t)l * DD, z, out, nullptr, nullptr);
        else
            bn_stats_apply<false><<<128, 256>>>(
                g_out + (size_t)l * DD, be_out + (size_t)l * DD, z, nullptr, hHi, hLo);
    }
}

// round 9
// speedup vs baseline: 3.0190x; 1.0784x over previous
#include <cuda_runtime.h>
#include <cuda_bf16.h>
#include <cstdint>

#define BATCH 32
#define NN    1024
#define DD    128
#define LL    2
#define MTOT  (BATCH * NN)
#define BN_EPS 1e-5f
#define BN_BLOCKS 256

// ---------------- scratch ----------------
__device__ __nv_bfloat16 g_adjHi[(size_t)BATCH * NN * NN];
__device__ __nv_bfloat16 g_hHi[MTOT * DD];
__device__ __nv_bfloat16 g_hLo[MTOT * DD];
__device__ __nv_bfloat16 g_pHi[MTOT * DD];
__device__ __nv_bfloat16 g_pLo[MTOT * DD];
__device__ __nv_bfloat16 g_W1Hi[LL * DD * DD];
__device__ __nv_bfloat16 g_W1Lo[LL * DD * DD];
__device__ __nv_bfloat16 g_W2Hi[LL * DD * DD];
__device__ __nv_bfloat16 g_W2Lo[LL * DD * DD];
__device__ float g_z[MTOT * DD];
__device__ float g_partS1[BN_BLOCKS * DD];
__device__ float g_partQ1[BN_BLOCKS * DD];
__device__ float g_partS2[BN_BLOCKS * DD];
__device__ float g_partQ2[BN_BLOCKS * DD];

// ---------------- helpers ----------------
__device__ __forceinline__ uint32_t smem_u32(const void* p) {
    uint32_t a;
    asm("{ .reg .u64 t; cvta.to.shared.u64 t, %1; cvt.u32.u64 %0, t; }" : "=r"(a) : "l"(p));
    return a;
}
__device__ __forceinline__ void ldsm_x4(uint32_t* r, uint32_t addr) {
    asm volatile("ldmatrix.sync.aligned.m8n8.x4.shared.b16 {%0,%1,%2,%3}, [%4];"
                 : "=r"(r[0]), "=r"(r[1]), "=r"(r[2]), "=r"(r[3]) : "r"(addr));
}
__device__ __forceinline__ void ldsm_x4_t(uint32_t* r, uint32_t addr) {
    asm volatile("ldmatrix.sync.aligned.m8n8.x4.trans.shared.b16 {%0,%1,%2,%3}, [%4];"
                 : "=r"(r[0]), "=r"(r[1]), "=r"(r[2]), "=r"(r[3]) : "r"(addr));
}
__device__ __forceinline__ void mma_bf16(float* c, const uint32_t* a, const uint32_t* b) {
    asm volatile(
        "mma.sync.aligned.m16n8k16.row.col.f32.bf16.bf16.f32 "
        "{%0,%1,%2,%3}, {%4,%5,%6,%7}, {%8,%9}, {%0,%1,%2,%3};"
        : "+f"(c[0]), "+f"(c[1]), "+f"(c[2]), "+f"(c[3])
        : "r"(a[0]), "r"(a[1]), "r"(a[2]), "r"(a[3]), "r"(b[0]), "r"(b[1]));
}
__device__ __forceinline__ void cp_async16(uint32_t dst, const void* src) {
    asm volatile("cp.async.cg.shared.global [%0], [%1], 16;" :: "r"(dst), "l"(src));
}
#define CP_COMMIT() asm volatile("cp.async.commit_group;" ::: "memory")
#define CP_WAIT1()  asm volatile("cp.async.wait_group 1;"  ::: "memory")
#define CP_WAIT0()  asm volatile("cp.async.wait_group 0;"  ::: "memory")

__device__ __forceinline__ uint32_t pack_bf16(float x, float y) {
    __nv_bfloat162 t = __floats2bfloat162_rn(x, y);
    return *reinterpret_cast<uint32_t*>(&t);
}

// =================================================================
// Pool layer-1 GEMM, register-staged adj conversion (R8, unchanged).
// =================================================================
#define AB_BUF   36864
#define PB_OFF   73728
#define PB_STG   34816
#define POOL_SMEM 178176

__global__ __launch_bounds__(512)
void gemm_pool_convert(const float* __restrict__ A,
                       const __nv_bfloat16* __restrict__ Bhi,
                       const __nv_bfloat16* __restrict__ Blo,
                       __nv_bfloat16* __restrict__ adjHiOut,
                       __nv_bfloat16* __restrict__ outHi,
                       __nv_bfloat16* __restrict__ outLo) {
    constexpr int NC = NN / 64;

    const size_t aOff = (size_t)blockIdx.y * NN * NN + (size_t)blockIdx.x * 128 * NN;
    const size_t bOff = (size_t)blockIdx.y * NN * DD;
    const size_t oOff = (size_t)blockIdx.y * NN * DD + (size_t)blockIdx.x * 128 * DD;
    A += aOff;
    adjHiOut += aOff;
    Bhi += bOff; Blo += bOff;

    extern __shared__ char smem[];
    const uint32_t sbase = smem_u32(smem);

    const int tid  = threadIdx.x;
    const int lane = tid & 31;
    const int wid  = tid >> 5;
    const int wm   = wid & 3;
    const int wn   = wid >> 2;
    const int sub  = lane >> 3;
    const int r8   = lane & 7;

    const uint32_t rowA  = wm * 32 + (sub & 1) * 8 + r8;
    const uint32_t colA  = (sub >> 1) * 8;
    const uint32_t rowB8 = (sub & 1) * 8 + r8;
    const uint32_t colB  = wn * 32 + (sub >> 1) * 8;

    const int aRow[4] = { (tid) >> 4, (tid + 512) >> 4, (tid + 1024) >> 4, (tid + 1536) >> 4 };
    const int aSeg = tid & 15;

    float acc[2][4][4];
#pragma unroll
    for (int i = 0; i < 2; i++)
#pragma unroll
        for (int j = 0; j < 4; j++)
#pragma unroll
            for (int k = 0; k < 4; k++) acc[i][j][k] = 0.f;

    auto issueB = [&](int c) {
        const uint32_t sb = sbase + PB_OFF + (uint32_t)(c % 3) * PB_STG;
#pragma unroll
        for (int p = 0; p < 4; p++) {
            int i = tid + p * 512;
            int half = i >> 10, rem = i & 1023, row = rem >> 4, ch = rem & 15;
            const __nv_bfloat16* s = (half ? Blo : Bhi) + (size_t)(c * 64 + row) * DD + ch * 8;
            cp_async16(sb + half * 17408 + row * 272 + ch * 16, s);
        }
    };
    float4 aR[4];
    auto loadA = [&](int c) {
#pragma unroll
        for (int p = 0; p < 4; p++)
            aR[p] = *reinterpret_cast<const float4*>(A + (size_t)aRow[p] * NN + c * 64 + aSeg * 4);
    };
    auto convert = [&](int cc) {
        char* dhi = smem + (cc & 1) * AB_BUF;
        char* dlo = dhi + 18432;
#pragma unroll
        for (int p = 0; p < 4; p++) {
            float4 v = aR[p];
            __nv_bfloat16 h0 = __float2bfloat16(v.x), h1 = __float2bfloat16(v.y);
            __nv_bfloat16 h2 = __float2bfloat16(v.z), h3 = __float2bfloat16(v.w);
            uint2 hv, lv;
            hv.x = pack_bf16(v.x, v.y); hv.y = pack_bf16(v.z, v.w);
            lv.x = pack_bf16(v.x - __bfloat162float(h0), v.y - __bfloat162float(h1));
            lv.y = pack_bf16(v.z - __bfloat162float(h2), v.w - __bfloat162float(h3));
            *reinterpret_cast<uint2*>(dhi + aRow[p] * 144 + aSeg * 8) = hv;
            *reinterpret_cast<uint2*>(dlo + aRow[p] * 144 + aSeg * 8) = lv;
            *reinterpret_cast<uint2*>(adjHiOut + (size_t)aRow[p] * NN + cc * 64 + aSeg * 4) = hv;
        }
    };

    loadA(0);
    issueB(0); CP_COMMIT();
    issueB(1); CP_COMMIT();
    convert(0);
    CP_WAIT1();
    __syncthreads();

    for (int c = 0; c < NC; c++) {
        if (c + 1 < NC) loadA(c + 1);
        if (c + 2 < NC) issueB(c + 2);
        CP_COMMIT();

        const uint32_t stA = sbase + (uint32_t)(c & 1) * AB_BUF;
        const uint32_t stB = sbase + PB_OFF + (uint32_t)(c % 3) * PB_STG;
#pragma unroll
        for (int ks = 0; ks < 4; ks++) {
            uint32_t ah[2][4], al[2][4], bh[2][4], bl[2][4];
#pragma unroll
            for (int mb = 0; mb < 2; mb++) {
                uint32_t ad = stA + (rowA + mb * 16) * 144 + (ks * 16 + colA) * 2;
                ldsm_x4(ah[mb], ad);
                ldsm_x4(al[mb], ad + 18432);
            }
#pragma unroll
            for (int g = 0; g < 2; g++) {
                uint32_t bd = stB + (ks * 16 + rowB8) * 272 + (colB + g * 16) * 2;
                ldsm_x4_t(bh[g], bd);
                ldsm_x4_t(bl[g], bd + 17408);
            }
#pragma unroll
            for (int mb = 0; mb < 2; mb++)
#pragma unroll
                for (int nb = 0; nb < 4; nb++)
                    mma_bf16(acc[mb][nb], ah[mb], &bh[nb >> 1][(nb & 1) * 2]);
#pragma unroll
            for (int mb = 0; mb < 2; mb++)
#pragma unroll
                for (int nb = 0; nb < 4; nb++)
                    mma_bf16(acc[mb][nb], ah[mb], &bl[nb >> 1][(nb & 1) * 2]);
#pragma unroll
            for (int mb = 0; mb < 2; mb++)
#pragma unroll
                for (int nb = 0; nb < 4; nb++)
                    mma_bf16(acc[mb][nb], al[mb], &bh[nb >> 1][(nb & 1) * 2]);
        }

        if (c + 1 < NC) convert(c + 1);

        CP_WAIT1();
        __syncthreads();
    }

    const int er = lane >> 2;
    const int ec = (lane & 3) * 2;
#pragma unroll
    for (int mb = 0; mb < 2; mb++)
#pragma unroll
        for (int nb = 0; nb < 4; nb++) {
            int row = wm * 32 + mb * 16 + er;
            int col = wn * 32 + nb * 8 + ec;
            float2 v0 = make_float2(acc[mb][nb][0], acc[mb][nb][1]);
            float2 v1 = make_float2(acc[mb][nb][2], acc[mb][nb][3]);
            __nv_bfloat16 h0 = __float2bfloat16(v0.x), h1 = __float2bfloat16(v0.y);
            __nv_bfloat16 h2 = __float2bfloat16(v1.x), h3 = __float2bfloat16(v1.y);
            uint32_t hi0 = pack_bf16(v0.x, v0.y);
            uint32_t hi1 = pack_bf16(v1.x, v1.y);
            uint32_t lo0 = pack_bf16(v0.x - __bfloat162float(h0), v0.y - __bfloat162float(h1));
            uint32_t lo1 = pack_bf16(v1.x - __bfloat162float(h2), v1.y - __bfloat162float(h3));
            *reinterpret_cast<uint32_t*>(outHi + oOff + (size_t)row * DD + col) = hi0;
            *reinterpret_cast<uint32_t*>(outLo + oOff + (size_t)row * DD + col) = lo0;
            *reinterpret_cast<uint32_t*>(outHi + oOff + (size_t)(row + 8) * DD + col) = hi1;
            *reinterpret_cast<uint32_t*>(outLo + oOff + (size_t)(row + 8) * DD + col) = lo1;
        }
}

// =================================================================
// Unified split-bf16 GEMM. BIASED writes fp32 + BN partials (pS/pQ).
// =================================================================
template <int KA, int NTERMS, bool BIASED>
__global__ __launch_bounds__(512)
void gemm_bf16(const __nv_bfloat16* __restrict__ Ahi, const __nv_bfloat16* __restrict__ Alo,
               const __nv_bfloat16* __restrict__ Bhi, const __nv_bfloat16* __restrict__ Blo,
               const float* __restrict__ bias,
               float* __restrict__ outF,
               __nv_bfloat16* __restrict__ outHi, __nv_bfloat16* __restrict__ outLo,
               float* __restrict__ pS, float* __restrict__ pQ) {
    constexpr int NC  = KA / 64;
    constexpr int NH  = (NTERMS == 3) ? 2 : 1;
    constexpr int A_SEC = 128 * 144;
    constexpr int B_SEC = 64 * 272;
    constexpr int OFF_B = NH * A_SEC;
    constexpr int STAGE = OFF_B + NH * B_SEC;
    constexpr int SBUF_OFF = 3 * STAGE;

    size_t aOff, bOff, oOff;
    if (KA == NN) {
        aOff = (size_t)blockIdx.y * NN * NN + (size_t)blockIdx.x * 128 * NN;
        bOff = (size_t)blockIdx.y * NN * DD;
        oOff = (size_t)blockIdx.y * NN * DD + (size_t)blockIdx.x * 128 * DD;
    } else {
        aOff = (size_t)blockIdx.x * 128 * DD;
        bOff = 0;
        oOff = (size_t)blockIdx.x * 128 * DD;
    }
    Ahi += aOff; if (NTERMS == 3) Alo += aOff;
    Bhi += bOff; if (NTERMS == 3) Blo += bOff;

    extern __shared__ char smem[];
    const uint32_t sbase = smem_u32(smem);

    const int tid  = threadIdx.x;
    const int lane = tid & 31;
    const int wid  = tid >> 5;
    const int wm   = wid & 3;
    const int wn   = wid >> 2;
    const int sub  = lane >> 3;
    const int r8   = lane & 7;

    const uint32_t rowA  = wm * 32 + (sub & 1) * 8 + r8;
    const uint32_t colA  = (sub >> 1) * 8;
    const uint32_t rowB8 = (sub & 1) * 8 + r8;
    const uint32_t colB  = wn * 32 + (sub >> 1) * 8;

    float acc[2][4][4];
#pragma unroll
    for (int i = 0; i < 2; i++)
#pragma unroll
        for (int j = 0; j < 4; j++)
#pragma unroll
            for (int k = 0; k < 4; k++) acc[i][j][k] = 0.f;

    auto issue = [&](int c, int stg) {
        if (c < NC) {
            const uint32_t sb = sbase + (uint32_t)stg * STAGE;
            const int k0 = c * 64;
#pragma unroll
            for (int p = 0; p < 2 * NH; p++) {
                int i = tid + p * 512;
                int half = i >> 10, rem = i & 1023, row = rem >> 3, ch = rem & 7;
                const __nv_bfloat16* s = (half ? Alo : Ahi) + (size_t)row * KA + k0 + ch * 8;
                cp_async16(sb + half * A_SEC + row * 144 + ch * 16, s);
            }
#pragma unroll
            for (int p = 0; p < 2 * NH; p++) {
                int i = tid + p * 512;
                int half = i >> 10, rem = i & 1023, row = rem >> 4, ch = rem & 15;
                const __nv_bfloat16* s = (half ? Blo : Bhi) + (size_t)(k0 + row) * DD + ch * 8;
                cp_async16(sb + OFF_B + half * B_SEC + row * 272 + ch * 16, s);
            }
        }
        CP_COMMIT();
    };

    issue(0, 0);
    issue(1, 1);
    CP_WAIT1();
    __syncthreads();

    for (int c = 0; c < NC; c++) {
        issue(c + 2, (c + 2) % 3);
        const uint32_t st = sbase + (uint32_t)(c % 3) * STAGE;

#pragma unroll
        for (int ks = 0; ks < 4; ks++) {
            uint32_t ah[2][4], al[2][4], bh[2][4], bl[2][4];
#pragma unroll
            for (int mb = 0; mb < 2; mb++) {
                uint32_t ad = st + (rowA + mb * 16) * 144 + (ks * 16 + colA) * 2;
                ldsm_x4(ah[mb], ad);
                if (NTERMS == 3) ldsm_x4(al[mb], ad + A_SEC);
            }
#pragma unroll
            for (int g = 0; g < 2; g++) {
                uint32_t bd = st + OFF_B + (ks * 16 + rowB8) * 272 + (colB + g * 16) * 2;
                ldsm_x4_t(bh[g], bd);
                if (NTERMS == 3) ldsm_x4_t(bl[g], bd + B_SEC);
            }
#pragma unroll
            for (int mb = 0; mb < 2; mb++)
#pragma unroll
                for (int nb = 0; nb < 4; nb++)
                    mma_bf16(acc[mb][nb], ah[mb], &bh[nb >> 1][(nb & 1) * 2]);
            if (NTERMS == 3) {
#pragma unroll
                for (int mb = 0; mb < 2; mb++)
#pragma unroll
                    for (int nb = 0; nb < 4; nb++)
                        mma_bf16(acc[mb][nb], ah[mb], &bl[nb >> 1][(nb & 1) * 2]);
#pragma unroll
                for (int mb = 0; mb < 2; mb++)
#pragma unroll
                    for (int nb = 0; nb < 4; nb++)
                        mma_bf16(acc[mb][nb], al[mb], &bh[nb >> 1][(nb & 1) * 2]);
            }
        }
        CP_WAIT1();
        __syncthreads();
    }

    const int er = lane >> 2;
    const int ec = (lane & 3) * 2;
    float s8[8], q8[8];
    if (BIASED) {
#pragma unroll
        for (int i = 0; i < 8; i++) { s8[i] = 0.f; q8[i] = 0.f; }
    }
#pragma unroll
    for (int mb = 0; mb < 2; mb++)
#pragma unroll
        for (int nb = 0; nb < 4; nb++) {
            int row = wm * 32 + mb * 16 + er;
            int col = wn * 32 + nb * 8 + ec;
            float2 v0 = make_float2(acc[mb][nb][0], acc[mb][nb][1]);
            float2 v1 = make_float2(acc[mb][nb][2], acc[mb][nb][3]);
            if (BIASED) {
                float bx = bias[col], by = bias[col + 1];
                v0.x += bx; v0.y += by; v1.x += bx; v1.y += by;
                s8[nb * 2 + 0] += v0.x + v1.x;
                s8[nb * 2 + 1] += v0.y + v1.y;
                q8[nb * 2 + 0] += v0.x * v0.x + v1.x * v1.x;
                q8[nb * 2 + 1] += v0.y * v0.y + v1.y * v1.y;
                *reinterpret_cast<float2*>(outF + oOff + (size_t)row * DD + col) = v0;
                *reinterpret_cast<float2*>(outF + oOff + (size_t)(row + 8) * DD + col) = v1;
            } else {
                __nv_bfloat16 h0 = __float2bfloat16(v0.x), h1 = __float2bfloat16(v0.y);
                __nv_bfloat16 h2 = __float2bfloat16(v1.x), h3 = __float2bfloat16(v1.y);
                uint32_t hi0 = pack_bf16(v0.x, v0.y);
                uint32_t hi1 = pack_bf16(v1.x, v1.y);
                uint32_t lo0 = pack_bf16(v0.x - __bfloat162float(h0), v0.y - __bfloat162float(h1));
                uint32_t lo1 = pack_bf16(v1.x - __bfloat162float(h2), v1.y - __bfloat162float(h3));
                *reinterpret_cast<uint32_t*>(outHi + oOff + (size_t)row * DD + col) = hi0;
                *reinterpret_cast<uint32_t*>(outLo + oOff + (size_t)row * DD + col) = lo0;
                *reinterpret_cast<uint32_t*>(outHi + oOff + (size_t)(row + 8) * DD + col) = hi1;
                *reinterpret_cast<uint32_t*>(outLo + oOff + (size_t)(row + 8) * DD + col) = lo1;
            }
        }

    if (BIASED) {
#pragma unroll
        for (int off = 4; off < 32; off <<= 1) {
#pragma unroll
            for (int i = 0; i < 8; i++) {
                s8[i] += __shfl_xor_sync(0xFFFFFFFF, s8[i], off);
                q8[i] += __shfl_xor_sync(0xFFFFFFFF, q8[i], off);
            }
        }
        float* sBuf = reinterpret_cast<float*>(smem + SBUF_OFF);
        float* qBuf = sBuf + 4 * DD;
        if (lane < 4) {
#pragma unroll
            for (int nb = 0; nb < 4; nb++) {
#pragma unroll
                for (int j = 0; j < 2; j++) {
                    int col = wn * 32 + nb * 8 + lane * 2 + j;
                    sBuf[wm * DD + col] = s8[nb * 2 + j];
                    qBuf[wm * DD + col] = q8[nb * 2 + j];
                }
            }
        }
        __syncthreads();
        if (tid < DD) {
            float s = sBuf[tid] + sBuf[DD + tid] + sBuf[2 * DD + tid] + sBuf[3 * DD + tid];
            float q = qBuf[tid] + qBuf[DD + tid] + qBuf[2 * DD + tid] + qBuf[3 * DD + tid];
            pS[blockIdx.x * DD + tid] = s;
            pQ[blockIdx.x * DD + tid] = q;
        }
    }
}

// =================================================================
// W2 GEMM with fused inner-BN: reads z fp32 + W1's BN partials,
// computes scale/shift CTA-locally, applies BN+ReLU+split in the
// register-staged A path. Epilogue: bias + fp32 out + BN partials (set 2).
// =================================================================
#define W2_AB    36864
#define W2_BOFF  73728
#define W2_BSTG  34816
#define W2_AUX   143360      // scl[128] + shf[128]
#define W2_RED   144384      // 4 KB reduce / epilogue scratch
#define W2_SMEM  148480

__global__ __launch_bounds__(512)
void gemm_w2_fused(const float* __restrict__ Az,
                   const __nv_bfloat16* __restrict__ Bhi,
                   const __nv_bfloat16* __restrict__ Blo,
                   const float* __restrict__ bias,
                   const float* __restrict__ gamma, const float* __restrict__ beta,
                   const float* __restrict__ pSin, const float* __restrict__ pQin,
                   float* __restrict__ outF,
                   float* __restrict__ pSout, float* __restrict__ pQout) {
    const size_t aOff = (size_t)blockIdx.x * 128 * DD;
    Az += aOff;

    extern __shared__ char smem[];
    const uint32_t sbase = smem_u32(smem);

    const int tid  = threadIdx.x;
    const int lane = tid & 31;
    const int wid  = tid >> 5;
    const int wm   = wid & 3;
    const int wn   = wid >> 2;
    const int sub  = lane >> 3;
    const int r8   = lane & 7;

    const uint32_t rowA  = wm * 32 + (sub & 1) * 8 + r8;
    const uint32_t colA  = (sub >> 1) * 8;
    const uint32_t rowB8 = (sub & 1) * 8 + r8;
    const uint32_t colB  = wn * 32 + (sub >> 1) * 8;

    const int aRow[4] = { (tid) >> 4, (tid + 512) >> 4, (tid + 1024) >> 4, (tid + 1536) >> 4 };
    const int aSeg = tid & 15;

    float acc[2][4][4];
#pragma unroll
    for (int i = 0; i < 2; i++)
#pragma unroll
        for (int j = 0; j < 4; j++)
#pragma unroll
            for (int k = 0; k < 4; k++) acc[i][j][k] = 0.f;

    auto issueB = [&](int c) {
        const uint32_t sb = sbase + W2_BOFF + (uint32_t)(c & 1) * W2_BSTG;
#pragma unroll
        for (int p = 0; p < 4; p++) {
            int i = tid + p * 512;
            int half = i >> 10, rem = i & 1023, row = rem >> 4, ch = rem & 15;
            const __nv_bfloat16* s = (half ? Blo : Bhi) + (size_t)(c * 64 + row) * DD + ch * 8;
            cp_async16(sb + half * 17408 + row * 272 + ch * 16, s);
        }
    };
    float4 aR[4];
    auto loadA = [&](int c) {
#pragma unroll
        for (int p = 0; p < 4; p++)
            aR[p] = *reinterpret_cast<const float4*>(Az + (size_t)aRow[p] * DD + c * 64 + aSeg * 4);
    };
    float* scl = reinterpret_cast<float*>(smem + W2_AUX);
    float* shf = scl + DD;
    auto convertBN = [&](int cc) {
        char* dhi = smem + (cc & 1) * W2_AB;
        char* dlo = dhi + 18432;
        const int col0 = cc * 64 + aSeg * 4;
        float4 sc = *reinterpret_cast<const float4*>(&scl[col0]);
        float4 sh = *reinterpret_cast<const float4*>(&shf[col0]);
#pragma unroll
        for (int p = 0; p < 4; p++) {
            float4 v = aR[p];
            float4 r;
            r.x = fmaxf(fmaf(v.x, sc.x, sh.x), 0.f);
            r.y = fmaxf(fmaf(v.y, sc.y, sh.y), 0.f);
            r.z = fmaxf(fmaf(v.z, sc.z, sh.z), 0.f);
            r.w = fmaxf(fmaf(v.w, sc.w, sh.w), 0.f);
            __nv_bfloat16 h0 = __float2bfloat16(r.x), h1 = __float2bfloat16(r.y);
            __nv_bfloat16 h2 = __float2bfloat16(r.z), h3 = __float2bfloat16(r.w);
            uint2 hv, lv;
            hv.x = pack_bf16(r.x, r.y); hv.y = pack_bf16(r.z, r.w);
            lv.x = pack_bf16(r.x - __bfloat162float(h0), r.y - __bfloat162float(h1));
            lv.y = pack_bf16(r.z - __bfloat162float(h2), r.w - __bfloat162float(h3));
            *reinterpret_cast<uint2*>(dhi + aRow[p] * 144 + aSeg * 8) = hv;
            *reinterpret_cast<uint2*>(dlo + aRow[p] * 144 + aSeg * 8) = lv;
        }
    };

    // prologue
    issueB(0); CP_COMMIT();
    issueB(1); CP_COMMIT();
    loadA(0);                                      // LDG in flight during reduce

    // CTA-local BN finalize (deterministic fixed-order reduction)
    {
        float* rS = reinterpret_cast<float*>(smem + W2_RED);         // [4][128]
        float* rQ = rS + 4 * DD;
        const int col = tid & 127, grp = tid >> 7;
        float s = 0.f, q = 0.f;
        for (int p = grp; p < BN_BLOCKS; p += 4) {
            s += pSin[p * DD + col];
            q += pQin[p * DD + col];
        }
        rS[grp * DD + col] = s;
        rQ[grp * DD + col] = q;
        __syncthreads();
        if (tid < DD) {
            float S = rS[tid] + rS[DD + tid] + rS[2 * DD + tid] + rS[3 * DD + tid];
            float Q = rQ[tid] + rQ[DD + tid] + rQ[2 * DD + tid] + rQ[3 * DD + tid];
            const float inv_m = 1.0f / (float)MTOT;
            float mean = S * inv_m;
            float var  = Q * inv_m - mean * mean;
            float sc   = gamma[tid] * rsqrtf(var + BN_EPS);
            scl[tid] = sc;
            shf[tid] = beta[tid] - mean * sc;
        }
        __syncthreads();
    }

    convertBN(0);
    CP_WAIT1();            // B(0) ready
    __syncthreads();       // convert(0) visible

    loadA(1);

    // ---- MMA chunk 0 ----
    {
        const uint32_t stA = sbase;
        const uint32_t stB = sbase + W2_BOFF;
#pragma unroll
        for (int ks = 0; ks < 4; ks++) {
            uint32_t ah[2][4], al[2][4], bh[2][4], bl[2][4];
#pragma unroll
            for (int mb = 0; mb < 2; mb++) {
                uint32_t ad = stA + (rowA + mb * 16) * 144 + (ks * 16 + colA) * 2;
                ldsm_x4(ah[mb], ad);
                ldsm_x4(al[mb], ad + 18432);
            }
#pragma unroll
            for (int g = 0; g < 2; g++) {
                uint32_t bd = stB + (ks * 16 + rowB8) * 272 + (colB + g * 16) * 2;
                ldsm_x4_t(bh[g], bd);
                ldsm_x4_t(bl[g], bd + 17408);
            }
#pragma unroll
            for (int mb = 0; mb < 2; mb++)
#pragma unroll
                for (int nb = 0; nb < 4; nb++)
                    mma_bf16(acc[mb][nb], ah[mb], &bh[nb >> 1][(nb & 1) * 2]);
#pragma unroll
            for (int mb = 0; mb < 2; mb++)
#pragma unroll
                for (int nb = 0; nb < 4; nb++)
                    mma_bf16(acc[mb][nb], ah[mb], &bl[nb >> 1][(nb & 1) * 2]);
#pragma unroll
            for (int mb = 0; mb < 2; mb++)
#pragma unroll
                for (int nb = 0; nb < 4; nb++)
                    mma_bf16(acc[mb][nb], al[mb], &bh[nb >> 1][(nb & 1) * 2]);
        }
    }

    convertBN(1);
    CP_WAIT0();            // B(1) ready
    __syncthreads();       // convert(1) visible

    // ---- MMA chunk 1 ----
    {
        const uint32_t stA = sbase + W2_AB;
        const uint32_t stB = sbase + W2_BOFF + W2_BSTG;
#pragma unroll
        for (int ks = 0; ks < 4; ks++) {
            uint32_t ah[2][4], al[2][4], bh[2][4], bl[2][4];
#pragma unroll
            for (int mb = 0; mb < 2; mb++) {
                uint32_t ad = stA + (rowA + mb * 16) * 144 + (ks * 16 + colA) * 2;
                ldsm_x4(ah[mb], ad);
                ldsm_x4(al[mb], ad + 18432);
            }
#pragma unroll
            for (int g = 0; g < 2; g++) {
                uint32_t bd = stB + (ks * 16 + rowB8) * 272 + (colB + g * 16) * 2;
                ldsm_x4_t(bh[g], bd);
                ldsm_x4_t(bl[g], bd + 17408);
            }
#pragma unroll
            for (int mb = 0; mb < 2; mb++)
#pragma unroll
                for (int nb = 0; nb < 4; nb++)
                    mma_bf16(acc[mb][nb], ah[mb], &bh[nb >> 1][(nb & 1) * 2]);
#pragma unroll
            for (int mb = 0; mb < 2; mb++)
#pragma unroll
                for (int nb = 0; nb < 4; nb++)
                    mma_bf16(acc[mb][nb], ah[mb], &bl[nb >> 1][(nb & 1) * 2]);
#pragma unroll
            for (int mb = 0; mb < 2; mb++)
#pragma unroll
                for (int nb = 0; nb < 4; nb++)
                    mma_bf16(acc[mb][nb], al[mb], &bh[nb >> 1][(nb & 1) * 2]);
        }
    }
    __syncthreads();       // before reusing W2_RED as epilogue scratch

    // ---- epilogue: bias + fp32 out + BN partials ----
    const int er = lane >> 2;
    const int ec = (lane & 3) * 2;
    float s8[8], q8[8];
#pragma unroll
    for (int i = 0; i < 8; i++) { s8[i] = 0.f; q8[i] = 0.f; }
#pragma unroll
    for (int mb = 0; mb < 2; mb++)
#pragma unroll
        for (int nb = 0; nb < 4; nb++) {
            int row = wm * 32 + mb * 16 + er;
            int col = wn * 32 + nb * 8 + ec;
            float2 v0 = make_float2(acc[mb][nb][0], acc[mb][nb][1]);
            float2 v1 = make_float2(acc[mb][nb][2], acc[mb][nb][3]);
            float bx = bias[col], by = bias[col + 1];
            v0.x += bx; v0.y += by; v1.x += bx; v1.y += by;
            s8[nb * 2 + 0] += v0.x + v1.x;
            s8[nb * 2 + 1] += v0.y + v1.y;
            q8[nb * 2 + 0] += v0.x * v0.x + v1.x * v1.x;
            q8[nb * 2 + 1] += v0.y * v0.y + v1.y * v1.y;
            *reinterpret_cast<float2*>(outF + aOff + (size_t)row * DD + col) = v0;
            *reinterpret_cast<float2*>(outF + aOff + (size_t)(row + 8) * DD + col) = v1;
        }

#pragma unroll
    for (int off = 4; off < 32; off <<= 1) {
#pragma unroll
        for (int i = 0; i < 8; i++) {
            s8[i] += __shfl_xor_sync(0xFFFFFFFF, s8[i], off);
            q8[i] += __shfl_xor_sync(0xFFFFFFFF, q8[i], off);
        }
    }
    float* sBuf = reinterpret_cast<float*>(smem + W2_RED);
    float* qBuf = sBuf + 4 * DD;
    if (lane < 4) {
#pragma unroll
        for (int nb = 0; nb < 4; nb++) {
#pragma unroll
            for (int j = 0; j < 2; j++) {
                int col = wn * 32 + nb * 8 + lane * 2 + j;
                sBuf[wm * DD + col] = s8[nb * 2 + j];
                qBuf[wm * DD + col] = q8[nb * 2 + j];
            }
        }
    }
    __syncthreads();
    if (tid < DD) {
        float s = sBuf[tid] + sBuf[DD + tid] + sBuf[2 * DD + tid] + sBuf[3 * DD + tid];
        float q = qBuf[tid] + qBuf[DD + tid] + qBuf[2 * DD + tid] + qBuf[3 * DD + tid];
        pSout[blockIdx.x * DD + tid] = s;
        pQout[blockIdx.x * DD + tid] = q;
    }
}

// ---------------- elementwise fp32 -> (hi, lo) bf16 split ----------------
__global__ __launch_bounds__(256)
void split_kernel(const float* __restrict__ src,
                  __nv_bfloat16* __restrict__ hi, __nv_bfloat16* __restrict__ lo) {
    const size_t idx = (size_t)blockIdx.x * 256 + threadIdx.x;
    float4 v = reinterpret_cast<const float4*>(src)[idx];
    __nv_bfloat16 h0 = __float2bfloat16(v.x), h1 = __float2bfloat16(v.y);
    __nv_bfloat16 h2 = __float2bfloat16(v.z), h3 = __float2bfloat16(v.w);
    uint2 hv, lv;
    hv.x = pack_bf16(v.x, v.y); hv.y = pack_bf16(v.z, v.w);
    lv.x = pack_bf16(v.x - __bfloat162float(h0), v.y - __bfloat162float(h1));
    lv.y = pack_bf16(v.z - __bfloat162float(h2), v.w - __bfloat162float(h3));
    reinterpret_cast<uint2*>(hi)[idx] = hv;
    reinterpret_cast<uint2*>(lo)[idx] = lv;
}

// =================================================================
// Outer-BN stats+apply. MODE 0: bf16 hi only (feeds 1-term pool).
// MODE 1: fp32 final output.
// =================================================================
template <int MODE>
__global__ __launch_bounds__(256)
void bn_stats_apply(const float* __restrict__ gamma, const float* __restrict__ beta,
                    const float* __restrict__ pS, const float* __restrict__ pQ,
                    const float* __restrict__ x,
                    float* __restrict__ outF, __nv_bfloat16* __restrict__ yhi) {
    __shared__ float sS[2][DD], sQ[2][DD];
    __shared__ float scl[DD], shf[DD];
    const int tid  = threadIdx.x;
    const int col  = tid & 127;
    const int half = tid >> 7;

    float s = 0.f, q = 0.f;
    for (int p = half; p < BN_BLOCKS; p += 2) {
        s += pS[p * DD + col];
        q += pQ[p * DD + col];
    }
    sS[half][col] = s;
    sQ[half][col] = q;
    __syncthreads();
    if (tid < DD) {
        float S = sS[0][tid] + sS[1][tid];
        float Q = sQ[0][tid] + sQ[1][tid];
        const float inv_m = 1.0f / (float)MTOT;
        float mean = S * inv_m;
        float var  = Q * inv_m - mean * mean;
        float sc   = gamma[tid] * rsqrtf(var + BN_EPS);
        scl[tid] = sc;
        shf[tid] = beta[tid] - mean * sc;
    }
    __syncthreads();

    const int base = blockIdx.x * 8192;
#pragma unroll 8
    for (int i = 0; i < 32; i++) {
        int idx = base + i * 256 + tid;
        int c4  = idx & 31;
        float4 v = reinterpret_cast<const float4*>(x)[idx];
        float4 sc = *reinterpret_cast<const float4*>(&scl[c4 * 4]);
        float4 sh = *reinterpret_cast<const float4*>(&shf[c4 * 4]);
        float4 r;
        r.x = fmaxf(fmaf(v.x, sc.x, sh.x), 0.f);
        r.y = fmaxf(fmaf(v.y, sc.y, sh.y), 0.f);
        r.z = fmaxf(fmaf(v.z, sc.z, sh.z), 0.f);
        r.w = fmaxf(fmaf(v.w, sc.w, sh.w), 0.f);
        if (MODE == 1) {
            reinterpret_cast<float4*>(outF)[idx] = r;
        } else {
            uint2 hv;
            hv.x = pack_bf16(r.x, r.y); hv.y = pack_bf16(r.z, r.w);
            reinterpret_cast<uint2*>(yhi)[idx] = hv;
        }
    }
}

// ---------------- launch ----------------
extern "C" void kernel_launch(void* const* d_in, const int* in_sizes, int n_in,
                              void* d_out, int out_size) {
    const float* x     = (const float*)d_in[0];
    const float* adj   = (const float*)d_in[2];
    const float* W1    = (const float*)d_in[3];
    const float* b1    = (const float*)d_in[4];
    const float* W2    = (const float*)d_in[5];
    const float* b2    = (const float*)d_in[6];
    const float* g_in   = (const float*)d_in[7];
    const float* be_in  = (const float*)d_in[8];
    const float* g_out  = (const float*)d_in[9];
    const float* be_out = (const float*)d_in[10];
    float* out = (float*)d_out;

    __nv_bfloat16 *adjHi, *hHi, *hLo, *pHi, *pLo;
    __nv_bfloat16 *W1Hi, *W1Lo, *W2Hi, *W2Lo;
    float *z, *pS1, *pQ1, *pS2, *pQ2;
    cudaGetSymbolAddress((void**)&adjHi, g_adjHi);
    cudaGetSymbolAddress((void**)&hHi, g_hHi);
    cudaGetSymbolAddress((void**)&hLo, g_hLo);
    cudaGetSymbolAddress((void**)&pHi, g_pHi);
    cudaGetSymbolAddress((void**)&pLo, g_pLo);
    cudaGetSymbolAddress((void**)&W1Hi, g_W1Hi);
    cudaGetSymbolAddress((void**)&W1Lo, g_W1Lo);
    cudaGetSymbolAddress((void**)&W2Hi, g_W2Hi);
    cudaGetSymbolAddress((void**)&W2Lo, g_W2Lo);
    cudaGetSymbolAddress((void**)&z, g_z);
    cudaGetSymbolAddress((void**)&pS1, g_partS1);
    cudaGetSymbolAddress((void**)&pQ1, g_partQ1);
    cudaGetSymbolAddress((void**)&pS2, g_partS2);
    cudaGetSymbolAddress((void**)&pQ2, g_partQ2);

    constexpr int SMEM3B = 3 * (2 * 128 * 144 + 2 * 64 * 272) + 4096;  // 219136
    constexpr int SMEM1  = 3 * (128 * 144 + 64 * 272);                 // 107520
    cudaFuncSetAttribute((const void*)gemm_pool_convert,
                         cudaFuncAttributeMaxDynamicSharedMemorySize, POOL_SMEM);
    cudaFuncSetAttribute((const void*)gemm_bf16<NN, 1, false>,
                         cudaFuncAttributeMaxDynamicSharedMemorySize, SMEM1);
    cudaFuncSetAttribute((const void*)gemm_bf16<DD, 3, true>,
                         cudaFuncAttributeMaxDynamicSharedMemorySize, SMEM3B);
    cudaFuncSetAttribute((const void*)gemm_w2_fused,
                         cudaFuncAttributeMaxDynamicSharedMemorySize, W2_SMEM);

    split_kernel<<<MTOT * DD / 1024, 256>>>(x, hHi, hLo);
    split_kernel<<<LL * DD * DD / 1024, 256>>>(W1, W1Hi, W1Lo);
    split_kernel<<<LL * DD * DD / 1024, 256>>>(W2, W2Hi, W2Lo);

    const dim3 gridPool(NN / 128, BATCH);
    const int  gridW = MTOT / 128;

    for (int l = 0; l < LL; l++) {
        if (l == 0)
            gemm_pool_convert<<<gridPool, 512, POOL_SMEM>>>(
                adj, hHi, hLo, adjHi, pHi, pLo);
        else
            gemm_bf16<NN, 1, false><<<gridPool, 512, SMEM1>>>(
                adjHi, nullptr, hHi, nullptr, nullptr, nullptr, pHi, pLo,
                nullptr, nullptr);

        // z = p @ W1 + b1, with BN_in partials
        gemm_bf16<DD, 3, true><<<gridW, 512, SMEM3B>>>(
            pHi, pLo, W1Hi + (size_t)l * DD * DD, W1Lo + (size_t)l * DD * DD,
            b1 + (size_t)l * DD, z, nullptr, nullptr, pS1, pQ1);

        // z = BN_in(z).relu() @ W2 + b2, with BN_out partials (fused)
        gemm_w2_fused<<<gridW, 512, W2_SMEM>>>(
            z, W2Hi + (size_t)l * DD * DD, W2Lo + (size_t)l * DD * DD,
            b2 + (size_t)l * DD, g_in + (size_t)l * DD, be_in + (size_t)l * DD,
            pS1, pQ1, z, pS2, pQ2);

        if (l == LL - 1)
            bn_stats_apply<1><<<128, 256>>>(
                g_out + (size_t)l * DD, be_out + (size_t)l * DD, pS2, pQ2,
                z, out, nullptr);
        else
            bn_stats_apply<0><<<128, 256>>>(
                g_out + (size_t)l * DD, be_out + (size_t)l * DD, pS2, pQ2,
                z, nullptr, hHi);
    }
}

// round 10
// speedup vs baseline: 3.2902x; 1.0898x over previous
#include <cuda_runtime.h>
#include <cuda_bf16.h>
#include <cuda_fp16.h>
#include <cstdint>

#define BATCH 32
#define NN    1024
#define DD    128
#define LL    2
#define MTOT  (BATCH * NN)
#define BN_EPS 1e-5f
#define BN_BLOCKS 256

// ---------------- scratch ----------------
__device__ __half g_adjH[(size_t)BATCH * NN * NN];      // adj as fp16
__device__ __half g_hHi[MTOT * DD];                     // x / h hi (fp16)
__device__ __half g_hLo[MTOT * DD];                     // x lo (fp16)
__device__ __nv_bfloat16 g_pHi[MTOT * DD];
__device__ __nv_bfloat16 g_pLo[MTOT * DD];
__device__ __nv_bfloat16 g_W1Hi[LL * DD * DD];
__device__ __nv_bfloat16 g_W1Lo[LL * DD * DD];
__device__ __nv_bfloat16 g_W2Hi[LL * DD * DD];
__device__ __nv_bfloat16 g_W2Lo[LL * DD * DD];
__device__ float g_z[MTOT * DD];
__device__ float g_partS1[BN_BLOCKS * DD];
__device__ float g_partQ1[BN_BLOCKS * DD];
__device__ float g_partS2[BN_BLOCKS * DD];
__device__ float g_partQ2[BN_BLOCKS * DD];

// ---------------- helpers ----------------
__device__ __forceinline__ uint32_t smem_u32(const void* p) {
    uint32_t a;
    asm("{ .reg .u64 t; cvta.to.shared.u64 t, %1; cvt.u32.u64 %0, t; }" : "=r"(a) : "l"(p));
    return a;
}
__device__ __forceinline__ void ldsm_x4(uint32_t* r, uint32_t addr) {
    asm volatile("ldmatrix.sync.aligned.m8n8.x4.shared.b16 {%0,%1,%2,%3}, [%4];"
                 : "=r"(r[0]), "=r"(r[1]), "=r"(r[2]), "=r"(r[3]) : "r"(addr));
}
__device__ __forceinline__ void ldsm_x4_t(uint32_t* r, uint32_t addr) {
    asm volatile("ldmatrix.sync.aligned.m8n8.x4.trans.shared.b16 {%0,%1,%2,%3}, [%4];"
                 : "=r"(r[0]), "=r"(r[1]), "=r"(r[2]), "=r"(r[3]) : "r"(addr));
}
__device__ __forceinline__ void mma_bf16(float* c, const uint32_t* a, const uint32_t* b) {
    asm volatile(
        "mma.sync.aligned.m16n8k16.row.col.f32.bf16.bf16.f32 "
        "{%0,%1,%2,%3}, {%4,%5,%6,%7}, {%8,%9}, {%0,%1,%2,%3};"
        : "+f"(c[0]), "+f"(c[1]), "+f"(c[2]), "+f"(c[3])
        : "r"(a[0]), "r"(a[1]), "r"(a[2]), "r"(a[3]), "r"(b[0]), "r"(b[1]));
}
__device__ __forceinline__ void mma_fp16(float* c, const uint32_t* a, const uint32_t* b) {
    asm volatile(
        "mma.sync.aligned.m16n8k16.row.col.f32.f16.f16.f32 "
        "{%0,%1,%2,%3}, {%4,%5,%6,%7}, {%8,%9}, {%0,%1,%2,%3};"
        : "+f"(c[0]), "+f"(c[1]), "+f"(c[2]), "+f"(c[3])
        : "r"(a[0]), "r"(a[1]), "r"(a[2]), "r"(a[3]), "r"(b[0]), "r"(b[1]));
}
template <bool H16>
__device__ __forceinline__ void mma_any(float* c, const uint32_t* a, const uint32_t* b) {
    if constexpr (H16) mma_fp16(c, a, b); else mma_bf16(c, a, b);
}
__device__ __forceinline__ void cp_async16(uint32_t dst, const void* src) {
    asm volatile("cp.async.cg.shared.global [%0], [%1], 16;" :: "r"(dst), "l"(src));
}
#define CP_COMMIT() asm volatile("cp.async.commit_group;" ::: "memory")
#define CP_WAIT1()  asm volatile("cp.async.wait_group 1;"  ::: "memory")
#define CP_WAIT0()  asm volatile("cp.async.wait_group 0;"  ::: "memory")

__device__ __forceinline__ uint32_t pack_bf16(float x, float y) {
    __nv_bfloat162 t = __floats2bfloat162_rn(x, y);
    return *reinterpret_cast<uint32_t*>(&t);
}
__device__ __forceinline__ uint32_t pack_f16(float x, float y) {
    __half2 t = __floats2half2_rn(x, y);
    return *reinterpret_cast<uint32_t*>(&t);
}

// =================================================================
// Pool layer-1 GEMM (fp16, 2 terms): pooled = adj(fp16) @ (xhi + xlo).
// adj converted fp32->fp16 on the fly (register-staged), streamed to g_adjH.
// Output: pooled split to bf16 hi/lo (input to 3-term bf16 W1 GEMM).
// =================================================================
#define AH_BUF   18432
#define PB_OFF   36864
#define PB_STG   34816
#define POOL_SMEM 141312

__global__ __launch_bounds__(512)
void gemm_pool_convert(const float* __restrict__ A,
                       const __half* __restrict__ Bhi,
                       const __half* __restrict__ Blo,
                       __half* __restrict__ adjHOut,
                       __nv_bfloat16* __restrict__ outHi,
                       __nv_bfloat16* __restrict__ outLo) {
    constexpr int NC = NN / 64;

    const size_t aOff = (size_t)blockIdx.y * NN * NN + (size_t)blockIdx.x * 128 * NN;
    const size_t bOff = (size_t)blockIdx.y * NN * DD;
    const size_t oOff = (size_t)blockIdx.y * NN * DD + (size_t)blockIdx.x * 128 * DD;
    A += aOff;
    adjHOut += aOff;
    Bhi += bOff; Blo += bOff;

    extern __shared__ char smem[];
    const uint32_t sbase = smem_u32(smem);

    const int tid  = threadIdx.x;
    const int lane = tid & 31;
    const int wid  = tid >> 5;
    const int wm   = wid & 3;
    const int wn   = wid >> 2;
    const int sub  = lane >> 3;
    const int r8   = lane & 7;

    const uint32_t rowA  = wm * 32 + (sub & 1) * 8 + r8;
    const uint32_t colA  = (sub >> 1) * 8;
    const uint32_t rowB8 = (sub & 1) * 8 + r8;
    const uint32_t colB  = wn * 32 + (sub >> 1) * 8;

    const int aRow[4] = { (tid) >> 4, (tid + 512) >> 4, (tid + 1024) >> 4, (tid + 1536) >> 4 };
    const int aSeg = tid & 15;

    float acc[2][4][4];
#pragma unroll
    for (int i = 0; i < 2; i++)
#pragma unroll
        for (int j = 0; j < 4; j++)
#pragma unroll
            for (int k = 0; k < 4; k++) acc[i][j][k] = 0.f;

    auto issueB = [&](int c) {
        const uint32_t sb = sbase + PB_OFF + (uint32_t)(c % 3) * PB_STG;
#pragma unroll
        for (int p = 0; p < 4; p++) {
            int i = tid + p * 512;
            int half = i >> 10, rem = i & 1023, row = rem >> 4, ch = rem & 15;
            const __half* s = (half ? Blo : Bhi) + (size_t)(c * 64 + row) * DD + ch * 8;
            cp_async16(sb + half * 17408 + row * 272 + ch * 16, s);
        }
    };
    float4 aR[4];
    auto loadA = [&](int c) {
#pragma unroll
        for (int p = 0; p < 4; p++)
            aR[p] = *reinterpret_cast<const float4*>(A + (size_t)aRow[p] * NN + c * 64 + aSeg * 4);
    };
    auto convert = [&](int cc) {          // fp32 regs -> fp16 (hi only)
        char* dhi = smem + (cc & 1) * AH_BUF;
#pragma unroll
        for (int p = 0; p < 4; p++) {
            float4 v = aR[p];
            uint2 hv;
            hv.x = pack_f16(v.x, v.y);
            hv.y = pack_f16(v.z, v.w);
            *reinterpret_cast<uint2*>(dhi + aRow[p] * 144 + aSeg * 8) = hv;
            *reinterpret_cast<uint2*>(adjHOut + (size_t)aRow[p] * NN + cc * 64 + aSeg * 4) = hv;
        }
    };

    loadA(0);
    issueB(0); CP_COMMIT();
    issueB(1); CP_COMMIT();
    convert(0);
    CP_WAIT1();
    __syncthreads();

    for (int c = 0; c < NC; c++) {
        if (c + 1 < NC) loadA(c + 1);
        if (c + 2 < NC) issueB(c + 2);
        CP_COMMIT();

        const uint32_t stA = sbase + (uint32_t)(c & 1) * AH_BUF;
        const uint32_t stB = sbase + PB_OFF + (uint32_t)(c % 3) * PB_STG;
#pragma unroll
        for (int ks = 0; ks < 4; ks++) {
            uint32_t ah[2][4], bh[2][4], bl[2][4];
#pragma unroll
            for (int mb = 0; mb < 2; mb++) {
                uint32_t ad = stA + (rowA + mb * 16) * 144 + (ks * 16 + colA) * 2;
                ldsm_x4(ah[mb], ad);
            }
#pragma unroll
            for (int g = 0; g < 2; g++) {
                uint32_t bd = stB + (ks * 16 + rowB8) * 272 + (colB + g * 16) * 2;
                ldsm_x4_t(bh[g], bd);
                ldsm_x4_t(bl[g], bd + 17408);
            }
#pragma unroll
            for (int mb = 0; mb < 2; mb++)
#pragma unroll
                for (int nb = 0; nb < 4; nb++)
                    mma_fp16(acc[mb][nb], ah[mb], &bh[nb >> 1][(nb & 1) * 2]);
#pragma unroll
            for (int mb = 0; mb < 2; mb++)
#pragma unroll
                for (int nb = 0; nb < 4; nb++)
                    mma_fp16(acc[mb][nb], ah[mb], &bl[nb >> 1][(nb & 1) * 2]);
        }

        if (c + 1 < NC) convert(c + 1);

        CP_WAIT1();
        __syncthreads();
    }

    // epilogue: split to bf16 hi/lo
    const int er = lane >> 2;
    const int ec = (lane & 3) * 2;
#pragma unroll
    for (int mb = 0; mb < 2; mb++)
#pragma unroll
        for (int nb = 0; nb < 4; nb++) {
            int row = wm * 32 + mb * 16 + er;
            int col = wn * 32 + nb * 8 + ec;
            float2 v0 = make_float2(acc[mb][nb][0], acc[mb][nb][1]);
            float2 v1 = make_float2(acc[mb][nb][2], acc[mb][nb][3]);
            __nv_bfloat16 h0 = __float2bfloat16(v0.x), h1 = __float2bfloat16(v0.y);
            __nv_bfloat16 h2 = __float2bfloat16(v1.x), h3 = __float2bfloat16(v1.y);
            uint32_t hi0 = pack_bf16(v0.x, v0.y);
            uint32_t hi1 = pack_bf16(v1.x, v1.y);
            uint32_t lo0 = pack_bf16(v0.x - __bfloat162float(h0), v0.y - __bfloat162float(h1));
            uint32_t lo1 = pack_bf16(v1.x - __bfloat162float(h2), v1.y - __bfloat162float(h3));
            *reinterpret_cast<uint32_t*>(outHi + oOff + (size_t)row * DD + col) = hi0;
            *reinterpret_cast<uint32_t*>(outLo + oOff + (size_t)row * DD + col) = lo0;
            *reinterpret_cast<uint32_t*>(outHi + oOff + (size_t)(row + 8) * DD + col) = hi1;
            *reinterpret_cast<uint32_t*>(outLo + oOff + (size_t)(row + 8) * DD + col) = lo1;
        }
}

// =================================================================
// Unified split GEMM. NTERMS==1 path runs fp16 (pool layer-2);
// NTERMS==3 runs bf16 (weight GEMMs). BIASED fuses BN partials.
// =================================================================
template <int KA, int NTERMS, bool BIASED>
__global__ __launch_bounds__(512)
void gemm_bf16(const __nv_bfloat16* __restrict__ Ahi, const __nv_bfloat16* __restrict__ Alo,
               const __nv_bfloat16* __restrict__ Bhi, const __nv_bfloat16* __restrict__ Blo,
               const float* __restrict__ bias,
               float* __restrict__ outF,
               __nv_bfloat16* __restrict__ outHi, __nv_bfloat16* __restrict__ outLo,
               float* __restrict__ pS, float* __restrict__ pQ) {
    constexpr int NC  = KA / 64;
    constexpr int NH  = (NTERMS == 3) ? 2 : 1;
    constexpr bool H16 = (NTERMS == 1);
    constexpr int A_SEC = 128 * 144;
    constexpr int B_SEC = 64 * 272;
    constexpr int OFF_B = NH * A_SEC;
    constexpr int STAGE = OFF_B + NH * B_SEC;
    constexpr int SBUF_OFF = 3 * STAGE;

    size_t aOff, bOff, oOff;
    if (KA == NN) {
        aOff = (size_t)blockIdx.y * NN * NN + (size_t)blockIdx.x * 128 * NN;
        bOff = (size_t)blockIdx.y * NN * DD;
        oOff = (size_t)blockIdx.y * NN * DD + (size_t)blockIdx.x * 128 * DD;
    } else {
        aOff = (size_t)blockIdx.x * 128 * DD;
        bOff = 0;
        oOff = (size_t)blockIdx.x * 128 * DD;
    }
    Ahi += aOff; if (NTERMS == 3) Alo += aOff;
    Bhi += bOff; if (NTERMS == 3) Blo += bOff;

    extern __shared__ char smem[];
    const uint32_t sbase = smem_u32(smem);

    const int tid  = threadIdx.x;
    const int lane = tid & 31;
    const int wid  = tid >> 5;
    const int wm   = wid & 3;
    const int wn   = wid >> 2;
    const int sub  = lane >> 3;
    const int r8   = lane & 7;

    const uint32_t rowA  = wm * 32 + (sub & 1) * 8 + r8;
    const uint32_t colA  = (sub >> 1) * 8;
    const uint32_t rowB8 = (sub & 1) * 8 + r8;
    const uint32_t colB  = wn * 32 + (sub >> 1) * 8;

    float acc[2][4][4];
#pragma unroll
    for (int i = 0; i < 2; i++)
#pragma unroll
        for (int j = 0; j < 4; j++)
#pragma unroll
            for (int k = 0; k < 4; k++) acc[i][j][k] = 0.f;

    auto issue = [&](int c, int stg) {
        if (c < NC) {
            const uint32_t sb = sbase + (uint32_t)stg * STAGE;
            const int k0 = c * 64;
#pragma unroll
            for (int p = 0; p < 2 * NH; p++) {
                int i = tid + p * 512;
                int half = i >> 10, rem = i & 1023, row = rem >> 3, ch = rem & 7;
                const __nv_bfloat16* s = (half ? Alo : Ahi) + (size_t)row * KA + k0 + ch * 8;
                cp_async16(sb + half * A_SEC + row * 144 + ch * 16, s);
            }
#pragma unroll
            for (int p = 0; p < 2 * NH; p++) {
                int i = tid + p * 512;
                int half = i >> 10, rem = i & 1023, row = rem >> 4, ch = rem & 15;
                const __nv_bfloat16* s = (half ? Blo : Bhi) + (size_t)(k0 + row) * DD + ch * 8;
                cp_async16(sb + OFF_B + half * B_SEC + row * 272 + ch * 16, s);
            }
        }
        CP_COMMIT();
    };

    issue(0, 0);
    issue(1, 1);
    CP_WAIT1();
    __syncthreads();

    for (int c = 0; c < NC; c++) {
        issue(c + 2, (c + 2) % 3);
        const uint32_t st = sbase + (uint32_t)(c % 3) * STAGE;

#pragma unroll
        for (int ks = 0; ks < 4; ks++) {
            uint32_t ah[2][4], al[2][4], bh[2][4], bl[2][4];
#pragma unroll
            for (int mb = 0; mb < 2; mb++) {
                uint32_t ad = st + (rowA + mb * 16) * 144 + (ks * 16 + colA) * 2;
                ldsm_x4(ah[mb], ad);
                if (NTERMS == 3) ldsm_x4(al[mb], ad + A_SEC);
            }
#pragma unroll
            for (int g = 0; g < 2; g++) {
                uint32_t bd = st + OFF_B + (ks * 16 + rowB8) * 272 + (colB + g * 16) * 2;
                ldsm_x4_t(bh[g], bd);
                if (NTERMS == 3) ldsm_x4_t(bl[g], bd + B_SEC);
            }
#pragma unroll
            for (int mb = 0; mb < 2; mb++)
#pragma unroll
                for (int nb = 0; nb < 4; nb++)
                    mma_any<H16>(acc[mb][nb], ah[mb], &bh[nb >> 1][(nb & 1) * 2]);
            if (NTERMS == 3) {
#pragma unroll
                for (int mb = 0; mb < 2; mb++)
#pragma unroll
                    for (int nb = 0; nb < 4; nb++)
                        mma_any<H16>(acc[mb][nb], ah[mb], &bl[nb >> 1][(nb & 1) * 2]);
#pragma unroll
                for (int mb = 0; mb < 2; mb++)
#pragma unroll
                    for (int nb = 0; nb < 4; nb++)
                        mma_any<H16>(acc[mb][nb], al[mb], &bh[nb >> 1][(nb & 1) * 2]);
            }
        }
        CP_WAIT1();
        __syncthreads();
    }

    const int er = lane >> 2;
    const int ec = (lane & 3) * 2;
    float s8[8], q8[8];
    if (BIASED) {
#pragma unroll
        for (int i = 0; i < 8; i++) { s8[i] = 0.f; q8[i] = 0.f; }
    }
#pragma unroll
    for (int mb = 0; mb < 2; mb++)
#pragma unroll
        for (int nb = 0; nb < 4; nb++) {
            int row = wm * 32 + mb * 16 + er;
            int col = wn * 32 + nb * 8 + ec;
            float2 v0 = make_float2(acc[mb][nb][0], acc[mb][nb][1]);
            float2 v1 = make_float2(acc[mb][nb][2], acc[mb][nb][3]);
            if (BIASED) {
                float bx = bias[col], by = bias[col + 1];
                v0.x += bx; v0.y += by; v1.x += bx; v1.y += by;
                s8[nb * 2 + 0] += v0.x + v1.x;
                s8[nb * 2 + 1] += v0.y + v1.y;
                q8[nb * 2 + 0] += v0.x * v0.x + v1.x * v1.x;
                q8[nb * 2 + 1] += v0.y * v0.y + v1.y * v1.y;
                *reinterpret_cast<float2*>(outF + oOff + (size_t)row * DD + col) = v0;
                *reinterpret_cast<float2*>(outF + oOff + (size_t)(row + 8) * DD + col) = v1;
            } else {
                __nv_bfloat16 h0 = __float2bfloat16(v0.x), h1 = __float2bfloat16(v0.y);
                __nv_bfloat16 h2 = __float2bfloat16(v1.x), h3 = __float2bfloat16(v1.y);
                uint32_t hi0 = pack_bf16(v0.x, v0.y);
                uint32_t hi1 = pack_bf16(v1.x, v1.y);
                uint32_t lo0 = pack_bf16(v0.x - __bfloat162float(h0), v0.y - __bfloat162float(h1));
                uint32_t lo1 = pack_bf16(v1.x - __bfloat162float(h2), v1.y - __bfloat162float(h3));
                *reinterpret_cast<uint32_t*>(outHi + oOff + (size_t)row * DD + col) = hi0;
                *reinterpret_cast<uint32_t*>(outLo + oOff + (size_t)row * DD + col) = lo0;
                *reinterpret_cast<uint32_t*>(outHi + oOff + (size_t)(row + 8) * DD + col) = hi1;
                *reinterpret_cast<uint32_t*>(outLo + oOff + (size_t)(row + 8) * DD + col) = lo1;
            }
        }

    if (BIASED) {
#pragma unroll
        for (int off = 4; off < 32; off <<= 1) {
#pragma unroll
            for (int i = 0; i < 8; i++) {
                s8[i] += __shfl_xor_sync(0xFFFFFFFF, s8[i], off);
                q8[i] += __shfl_xor_sync(0xFFFFFFFF, q8[i], off);
            }
        }
        float* sBuf = reinterpret_cast<float*>(smem + SBUF_OFF);
        float* qBuf = sBuf + 4 * DD;
        if (lane < 4) {
#pragma unroll
            for (int nb = 0; nb < 4; nb++) {
#pragma unroll
                for (int j = 0; j < 2; j++) {
                    int col = wn * 32 + nb * 8 + lane * 2 + j;
                    sBuf[wm * DD + col] = s8[nb * 2 + j];
                    qBuf[wm * DD + col] = q8[nb * 2 + j];
                }
            }
        }
        __syncthreads();
        if (tid < DD) {
            float s = sBuf[tid] + sBuf[DD + tid] + sBuf[2 * DD + tid] + sBuf[3 * DD + tid];
            float q = qBuf[tid] + qBuf[DD + tid] + qBuf[2 * DD + tid] + qBuf[3 * DD + tid];
            pS[blockIdx.x * DD + tid] = s;
            pQ[blockIdx.x * DD + tid] = q;
        }
    }
}

// =================================================================
// W2 GEMM with fused inner-BN (R9, unchanged).
// =================================================================
#define W2_AB    36864
#define W2_BOFF  73728
#define W2_BSTG  34816
#define W2_AUX   143360
#define W2_RED   144384
#define W2_SMEM  148480

__global__ __launch_bounds__(512)
void gemm_w2_fused(const float* __restrict__ Az,
                   const __nv_bfloat16* __restrict__ Bhi,
                   const __nv_bfloat16* __restrict__ Blo,
                   const float* __restrict__ bias,
                   const float* __restrict__ gamma, const float* __restrict__ beta,
                   const float* __restrict__ pSin, const float* __restrict__ pQin,
                   float* __restrict__ outF,
                   float* __restrict__ pSout, float* __restrict__ pQout) {
    const size_t aOff = (size_t)blockIdx.x * 128 * DD;
    Az += aOff;

    extern __shared__ char smem[];
    const uint32_t sbase = smem_u32(smem);

    const int tid  = threadIdx.x;
    const int lane = tid & 31;
    const int wid  = tid >> 5;
    const int wm   = wid & 3;
    const int wn   = wid >> 2;
    const int sub  = lane >> 3;
    const int r8   = lane & 7;

    const uint32_t rowA  = wm * 32 + (sub & 1) * 8 + r8;
    const uint32_t colA  = (sub >> 1) * 8;
    const uint32_t rowB8 = (sub & 1) * 8 + r8;
    const uint32_t colB  = wn * 32 + (sub >> 1) * 8;

    const int aRow[4] = { (tid) >> 4, (tid + 512) >> 4, (tid + 1024) >> 4, (tid + 1536) >> 4 };
    const int aSeg = tid & 15;

    float acc[2][4][4];
#pragma unroll
    for (int i = 0; i < 2; i++)
#pragma unroll
        for (int j = 0; j < 4; j++)
#pragma unroll
            for (int k = 0; k < 4; k++) acc[i][j][k] = 0.f;

    auto issueB = [&](int c) {
        const uint32_t sb = sbase + W2_BOFF + (uint32_t)(c & 1) * W2_BSTG;
#pragma unroll
        for (int p = 0; p < 4; p++) {
            int i = tid + p * 512;
            int half = i >> 10, rem = i & 1023, row = rem >> 4, ch = rem & 15;
            const __nv_bfloat16* s = (half ? Blo : Bhi) + (size_t)(c * 64 + row) * DD + ch * 8;
            cp_async16(sb + half * 17408 + row * 272 + ch * 16, s);
        }
    };
    float4 aR[4];
    auto loadA = [&](int c) {
#pragma unroll
        for (int p = 0; p < 4; p++)
            aR[p] = *reinterpret_cast<const float4*>(Az + (size_t)aRow[p] * DD + c * 64 + aSeg * 4);
    };
    float* scl = reinterpret_cast<float*>(smem + W2_AUX);
    float* shf = scl + DD;
    auto convertBN = [&](int cc) {
        char* dhi = smem + (cc & 1) * W2_AB;
        char* dlo = dhi + 18432;
        const int col0 = cc * 64 + aSeg * 4;
        float4 sc = *reinterpret_cast<const float4*>(&scl[col0]);
        float4 sh = *reinterpret_cast<const float4*>(&shf[col0]);
#pragma unroll
        for (int p = 0; p < 4; p++) {
            float4 v = aR[p];
            float4 r;
            r.x = fmaxf(fmaf(v.x, sc.x, sh.x), 0.f);
            r.y = fmaxf(fmaf(v.y, sc.y, sh.y), 0.f);
            r.z = fmaxf(fmaf(v.z, sc.z, sh.z), 0.f);
            r.w = fmaxf(fmaf(v.w, sc.w, sh.w), 0.f);
            __nv_bfloat16 h0 = __float2bfloat16(r.x), h1 = __float2bfloat16(r.y);
            __nv_bfloat16 h2 = __float2bfloat16(r.z), h3 = __float2bfloat16(r.w);
            uint2 hv, lv;
            hv.x = pack_bf16(r.x, r.y); hv.y = pack_bf16(r.z, r.w);
            lv.x = pack_bf16(r.x - __bfloat162float(h0), r.y - __bfloat162float(h1));
            lv.y = pack_bf16(r.z - __bfloat162float(h2), r.w - __bfloat162float(h3));
            *reinterpret_cast<uint2*>(dhi + aRow[p] * 144 + aSeg * 8) = hv;
            *reinterpret_cast<uint2*>(dlo + aRow[p] * 144 + aSeg * 8) = lv;
        }
    };

    issueB(0); CP_COMMIT();
    issueB(1); CP_COMMIT();
    loadA(0);

    {
        float* rS = reinterpret_cast<float*>(smem + W2_RED);
        float* rQ = rS + 4 * DD;
        const int col = tid & 127, grp = tid >> 7;
        float s = 0.f, q = 0.f;
        for (int p = grp; p < BN_BLOCKS; p += 4) {
            s += pSin[p * DD + col];
            q += pQin[p * DD + col];
        }
        rS[grp * DD + col] = s;
        rQ[grp * DD + col] = q;
        __syncthreads();
        if (tid < DD) {
            float S = rS[tid] + rS[DD + tid] + rS[2 * DD + tid] + rS[3 * DD + tid];
            float Q = rQ[tid] + rQ[DD + tid] + rQ[2 * DD + tid] + rQ[3 * DD + tid];
            const float inv_m = 1.0f / (float)MTOT;
            float mean = S * inv_m;
            float var  = Q * inv_m - mean * mean;
            float sc   = gamma[tid] * rsqrtf(var + BN_EPS);
            scl[tid] = sc;
            shf[tid] = beta[tid] - mean * sc;
        }
        __syncthreads();
    }

    convertBN(0);
    CP_WAIT1();
    __syncthreads();

    loadA(1);

    {
        const uint32_t stA = sbase;
        const uint32_t stB = sbase + W2_BOFF;
#pragma unroll
        for (int ks = 0; ks < 4; ks++) {
            uint32_t ah[2][4], al[2][4], bh[2][4], bl[2][4];
#pragma unroll
            for (int mb = 0; mb < 2; mb++) {
                uint32_t ad = stA + (rowA + mb * 16) * 144 + (ks * 16 + colA) * 2;
                ldsm_x4(ah[mb], ad);
                ldsm_x4(al[mb], ad + 18432);
            }
#pragma unroll
            for (int g = 0; g < 2; g++) {
                uint32_t bd = stB + (ks * 16 + rowB8) * 272 + (colB + g * 16) * 2;
                ldsm_x4_t(bh[g], bd);
                ldsm_x4_t(bl[g], bd + 17408);
            }
#pragma unroll
            for (int mb = 0; mb < 2; mb++)
#pragma unroll
                for (int nb = 0; nb < 4; nb++)
                    mma_bf16(acc[mb][nb], ah[mb], &bh[nb >> 1][(nb & 1) * 2]);
#pragma unroll
            for (int mb = 0; mb < 2; mb++)
#pragma unroll
                for (int nb = 0; nb < 4; nb++)
                    mma_bf16(acc[mb][nb], ah[mb], &bl[nb >> 1][(nb & 1) * 2]);
#pragma unroll
            for (int mb = 0; mb < 2; mb++)
#pragma unroll
                for (int nb = 0; nb < 4; nb++)
                    mma_bf16(acc[mb][nb], al[mb], &bh[nb >> 1][(nb & 1) * 2]);
        }
    }

    convertBN(1);
    CP_WAIT0();
    __syncthreads();

    {
        const uint32_t stA = sbase + W2_AB;
        const uint32_t stB = sbase + W2_BOFF + W2_BSTG;
#pragma unroll
        for (int ks = 0; ks < 4; ks++) {
            uint32_t ah[2][4], al[2][4], bh[2][4], bl[2][4];
#pragma unroll
            for (int mb = 0; mb < 2; mb++) {
                uint32_t ad = stA + (rowA + mb * 16) * 144 + (ks * 16 + colA) * 2;
                ldsm_x4(ah[mb], ad);
                ldsm_x4(al[mb], ad + 18432);
            }
#pragma unroll
            for (int g = 0; g < 2; g++) {
                uint32_t bd = stB + (ks * 16 + rowB8) * 272 + (colB + g * 16) * 2;
                ldsm_x4_t(bh[g], bd);
                ldsm_x4_t(bl[g], bd + 17408);
            }
#pragma unroll
            for (int mb = 0; mb < 2; mb++)
#pragma unroll
                for (int nb = 0; nb < 4; nb++)
                    mma_bf16(acc[mb][nb], ah[mb], &bh[nb >> 1][(nb & 1) * 2]);
#pragma unroll
            for (int mb = 0; mb < 2; mb++)
#pragma unroll
                for (int nb = 0; nb < 4; nb++)
                    mma_bf16(acc[mb][nb], ah[mb], &bl[nb >> 1][(nb & 1) * 2]);
#pragma unroll
            for (int mb = 0; mb < 2; mb++)
#pragma unroll
                for (int nb = 0; nb < 4; nb++)
                    mma_bf16(acc[mb][nb], al[mb], &bh[nb >> 1][(nb & 1) * 2]);
        }
    }
    __syncthreads();

    const int er = lane >> 2;
    const int ec = (lane & 3) * 2;
    float s8[8], q8[8];
#pragma unroll
    for (int i = 0; i < 8; i++) { s8[i] = 0.f; q8[i] = 0.f; }
#pragma unroll
    for (int mb = 0; mb < 2; mb++)
#pragma unroll
        for (int nb = 0; nb < 4; nb++) {
            int row = wm * 32 + mb * 16 + er;
            int col = wn * 32 + nb * 8 + ec;
            float2 v0 = make_float2(acc[mb][nb][0], acc[mb][nb][1]);
            float2 v1 = make_float2(acc[mb][nb][2], acc[mb][nb][3]);
            float bx = bias[col], by = bias[col + 1];
            v0.x += bx; v0.y += by; v1.x += bx; v1.y += by;
            s8[nb * 2 + 0] += v0.x + v1.x;
            s8[nb * 2 + 1] += v0.y + v1.y;
            q8[nb * 2 + 0] += v0.x * v0.x + v1.x * v1.x;
            q8[nb * 2 + 1] += v0.y * v0.y + v1.y * v1.y;
            *reinterpret_cast<float2*>(outF + aOff + (size_t)row * DD + col) = v0;
            *reinterpret_cast<float2*>(outF + aOff + (size_t)(row + 8) * DD + col) = v1;
        }

#pragma unroll
    for (int off = 4; off < 32; off <<= 1) {
#pragma unroll
        for (int i = 0; i < 8; i++) {
            s8[i] += __shfl_xor_sync(0xFFFFFFFF, s8[i], off);
            q8[i] += __shfl_xor_sync(0xFFFFFFFF, q8[i], off);
        }
    }
    float* sBuf = reinterpret_cast<float*>(smem + W2_RED);
    float* qBuf = sBuf + 4 * DD;
    if (lane < 4) {
#pragma unroll
        for (int nb = 0; nb < 4; nb++) {
#pragma unroll
            for (int j = 0; j < 2; j++) {
                int col = wn * 32 + nb * 8 + lane * 2 + j;
                sBuf[wm * DD + col] = s8[nb * 2 + j];
                qBuf[wm * DD + col] = q8[nb * 2 + j];
            }
        }
    }
    __syncthreads();
    if (tid < DD) {
        float s = sBuf[tid] + sBuf[DD + tid] + sBuf[2 * DD + tid] + sBuf[3 * DD + tid];
        float q = qBuf[tid] + qBuf[DD + tid] + qBuf[2 * DD + tid] + qBuf[3 * DD + tid];
        pSout[blockIdx.x * DD + tid] = s;
        pQout[blockIdx.x * DD + tid] = q;
    }
}

// ---------------- fp32 -> (hi, lo) bf16 split (weights) ----------------
__global__ __launch_bounds__(256)
void split_kernel(const float* __restrict__ src,
                  __nv_bfloat16* __restrict__ hi, __nv_bfloat16* __restrict__ lo) {
    const size_t idx = (size_t)blockIdx.x * 256 + threadIdx.x;
    float4 v = reinterpret_cast<const float4*>(src)[idx];
    __nv_bfloat16 h0 = __float2bfloat16(v.x), h1 = __float2bfloat16(v.y);
    __nv_bfloat16 h2 = __float2bfloat16(v.z), h3 = __float2bfloat16(v.w);
    uint2 hv, lv;
    hv.x = pack_bf16(v.x, v.y); hv.y = pack_bf16(v.z, v.w);
    lv.x = pack_bf16(v.x - __bfloat162float(h0), v.y - __bfloat162float(h1));
    lv.y = pack_bf16(v.z - __bfloat162float(h2), v.w - __bfloat162float(h3));
    reinterpret_cast<uint2*>(hi)[idx] = hv;
    reinterpret_cast<uint2*>(lo)[idx] = lv;
}

// ---------------- fp32 -> (hi, lo) fp16 split (x) ----------------
__global__ __launch_bounds__(256)
void split_half_kernel(const float* __restrict__ src,
                       __half* __restrict__ hi, __half* __restrict__ lo) {
    const size_t idx = (size_t)blockIdx.x * 256 + threadIdx.x;
    float4 v = reinterpret_cast<const float4*>(src)[idx];
    __half h0 = __float2half_rn(v.x), h1 = __float2half_rn(v.y);
    __half h2 = __float2half_rn(v.z), h3 = __float2half_rn(v.w);
    uint2 hv, lv;
    hv.x = pack_f16(v.x, v.y); hv.y = pack_f16(v.z, v.w);
    lv.x = pack_f16(v.x - __half2float(h0), v.y - __half2float(h1));
    lv.y = pack_f16(v.z - __half2float(h2), v.w - __half2float(h3));
    reinterpret_cast<uint2*>(hi)[idx] = hv;
    reinterpret_cast<uint2*>(lo)[idx] = lv;
}

// =================================================================
// Outer-BN stats+apply. MODE 0: fp16 hi only (feeds fp16 1-term pool).
// MODE 1: fp32 final output.
// =================================================================
template <int MODE>
__global__ __launch_bounds__(256)
void bn_stats_apply(const float* __restrict__ gamma, const float* __restrict__ beta,
                    const float* __restrict__ pS, const float* __restrict__ pQ,
                    const float* __restrict__ x,
                    float* __restrict__ outF, __half* __restrict__ yhi) {
    __shared__ float sS[2][DD], sQ[2][DD];
    __shared__ float scl[DD], shf[DD];
    const int tid  = threadIdx.x;
    const int col  = tid & 127;
    const int half = tid >> 7;

    float s = 0.f, q = 0.f;
    for (int p = half; p < BN_BLOCKS; p += 2) {
        s += pS[p * DD + col];
        q += pQ[p * DD + col];
    }
    sS[half][col] = s;
    sQ[half][col] = q;
    __syncthreads();
    if (tid < DD) {
        float S = sS[0][tid] + sS[1][tid];
        float Q = sQ[0][tid] + sQ[1][tid];
        const float inv_m = 1.0f / (float)MTOT;
        float mean = S * inv_m;
        float var  = Q * inv_m - mean * mean;
        float sc   = gamma[tid] * rsqrtf(var + BN_EPS);
        scl[tid] = sc;
        shf[tid] = beta[tid] - mean * sc;
    }
    __syncthreads();

    const int base = blockIdx.x * 8192;
#pragma unroll 8
    for (int i = 0; i < 32; i++) {
        int idx = base + i * 256 + tid;
        int c4  = idx & 31;
        float4 v = reinterpret_cast<const float4*>(x)[idx];
        float4 sc = *reinterpret_cast<const float4*>(&scl[c4 * 4]);
        float4 sh = *reinterpret_cast<const float4*>(&shf[c4 * 4]);
        float4 r;
        r.x = fmaxf(fmaf(v.x, sc.x, sh.x), 0.f);
        r.y = fmaxf(fmaf(v.y, sc.y, sh.y), 0.f);
        r.z = fmaxf(fmaf(v.z, sc.z, sh.z), 0.f);
        r.w = fmaxf(fmaf(v.w, sc.w, sh.w), 0.f);
        if (MODE == 1) {
            reinterpret_cast<float4*>(outF)[idx] = r;
        } else {
            uint2 hv;
            hv.x = pack_f16(r.x, r.y); hv.y = pack_f16(r.z, r.w);
            reinterpret_cast<uint2*>(yhi)[idx] = hv;
        }
    }
}

// ---------------- launch ----------------
extern "C" void kernel_launch(void* const* d_in, const int* in_sizes, int n_in,
                              void* d_out, int out_size) {
    const float* x     = (const float*)d_in[0];
    const float* adj   = (const float*)d_in[2];
    const float* W1    = (const float*)d_in[3];
    const float* b1    = (const float*)d_in[4];
    const float* W2    = (const float*)d_in[5];
    const float* b2    = (const float*)d_in[6];
    const float* g_in   = (const float*)d_in[7];
    const float* be_in  = (const float*)d_in[8];
    const float* g_out  = (const float*)d_in[9];
    const float* be_out = (const float*)d_in[10];
    float* out = (float*)d_out;

    __half *adjH, *hHi, *hLo;
    __nv_bfloat16 *pHi, *pLo, *W1Hi, *W1Lo, *W2Hi, *W2Lo;
    float *z, *pS1, *pQ1, *pS2, *pQ2;
    cudaGetSymbolAddress((void**)&adjH, g_adjH);
    cudaGetSymbolAddress((void**)&hHi, g_hHi);
    cudaGetSymbolAddress((void**)&hLo, g_hLo);
    cudaGetSymbolAddress((void**)&pHi, g_pHi);
    cudaGetSymbolAddress((void**)&pLo, g_pLo);
    cudaGetSymbolAddress((void**)&W1Hi, g_W1Hi);
    cudaGetSymbolAddress((void**)&W1Lo, g_W1Lo);
    cudaGetSymbolAddress((void**)&W2Hi, g_W2Hi);
    cudaGetSymbolAddress((void**)&W2Lo, g_W2Lo);
    cudaGetSymbolAddress((void**)&z, g_z);
    cudaGetSymbolAddress((void**)&pS1, g_partS1);
    cudaGetSymbolAddress((void**)&pQ1, g_partQ1);
    cudaGetSymbolAddress((void**)&pS2, g_partS2);
    cudaGetSymbolAddress((void**)&pQ2, g_partQ2);

    constexpr int SMEM3B = 3 * (2 * 128 * 144 + 2 * 64 * 272) + 4096;  // 219136
    constexpr int SMEM1  = 3 * (128 * 144 + 64 * 272);                 // 107520
    cudaFuncSetAttribute((const void*)gemm_pool_convert,
                         cudaFuncAttributeMaxDynamicSharedMemorySize, POOL_SMEM);
    cudaFuncSetAttribute((const void*)gemm_bf16<NN, 1, false>,
                         cudaFuncAttributeMaxDynamicSharedMemorySize, SMEM1);
    cudaFuncSetAttribute((const void*)gemm_bf16<DD, 3, true>,
                         cudaFuncAttributeMaxDynamicSharedMemorySize, SMEM3B);
    cudaFuncSetAttribute((const void*)gemm_w2_fused,
                         cudaFuncAttributeMaxDynamicSharedMemorySize, W2_SMEM);

    split_half_kernel<<<MTOT * DD / 1024, 256>>>(x, hHi, hLo);
    split_kernel<<<LL * DD * DD / 1024, 256>>>(W1, W1Hi, W1Lo);
    split_kernel<<<LL * DD * DD / 1024, 256>>>(W2, W2Hi, W2Lo);

    const dim3 gridPool(NN / 128, BATCH);
    const int  gridW = MTOT / 128;

    for (int l = 0; l < LL; l++) {
        if (l == 0)
            gemm_pool_convert<<<gridPool, 512, POOL_SMEM>>>(
                adj, hHi, hLo, adjH, pHi, pLo);
        else
            gemm_bf16<NN, 1, false><<<gridPool, 512, SMEM1>>>(
                reinterpret_cast<const __nv_bfloat16*>(adjH), nullptr,
                reinterpret_cast<const __nv_bfloat16*>(hHi), nullptr,
                nullptr, nullptr, pHi, pLo, nullptr, nullptr);

        gemm_bf16<DD, 3, true><<<gridW, 512, SMEM3B>>>(
            pHi, pLo, W1Hi + (size_t)l * DD * DD, W1Lo + (size_t)l * DD * DD,
            b1 + (size_t)l * DD, z, nullptr, nullptr, pS1, pQ1);

        gemm_w2_fused<<<gridW, 512, W2_SMEM>>>(
            z, W2Hi + (size_t)l * DD * DD, W2Lo + (size_t)l * DD * DD,
            b2 + (size_t)l * DD, g_in + (size_t)l * DD, be_in + (size_t)l * DD,
            pS1, pQ1, z, pS2, pQ2);

        if (l == LL - 1)
            bn_stats_apply<1><<<128, 256>>>(
                g_out + (size_t)l * DD, be_out + (size_t)l * DD, pS2, pQ2,
                z, out, nullptr);
        else
            bn_stats_apply<0><<<128, 256>>>(
                g_out + (size_t)l * DD, be_out + (size_t)l * DD, pS2, pQ2,
                z, nullptr, hHi);
    }
}

// round 11
// speedup vs baseline: 3.4894x; 1.0605x over previous
#include <cuda_runtime.h>
#include <cuda_fp16.h>
#include <cstdint>

#define BATCH 32
#define NN    1024
#define DD    128
#define LL    2
#define MTOT  (BATCH * NN)
#define BN_EPS 1e-5f
#define BN_BLOCKS 256

// ---------------- scratch ----------------
__device__ __half g_adjH[(size_t)BATCH * NN * NN];
__device__ __half g_hHi[MTOT * DD];
__device__ __half g_pHi[MTOT * DD];
__device__ __half g_pLo[MTOT * DD];
__device__ __half g_W1Hi[LL * DD * DD];
__device__ __half g_W1Lo[LL * DD * DD];
__device__ __half g_W2Hi[LL * DD * DD];
__device__ __half g_W2Lo[LL * DD * DD];
__device__ float g_z[MTOT * DD];
__device__ float g_partS1[BN_BLOCKS * DD];
__device__ float g_partQ1[BN_BLOCKS * DD];
__device__ float g_partS2[BN_BLOCKS * DD];
__device__ float g_partQ2[BN_BLOCKS * DD];

// ---------------- helpers ----------------
__device__ __forceinline__ uint32_t smem_u32(const void* p) {
    uint32_t a;
    asm("{ .reg .u64 t; cvta.to.shared.u64 t, %1; cvt.u32.u64 %0, t; }" : "=r"(a) : "l"(p));
    return a;
}
__device__ __forceinline__ void ldsm_x4(uint32_t* r, uint32_t addr) {
    asm volatile("ldmatrix.sync.aligned.m8n8.x4.shared.b16 {%0,%1,%2,%3}, [%4];"
                 : "=r"(r[0]), "=r"(r[1]), "=r"(r[2]), "=r"(r[3]) : "r"(addr));
}
__device__ __forceinline__ void ldsm_x4_t(uint32_t* r, uint32_t addr) {
    asm volatile("ldmatrix.sync.aligned.m8n8.x4.trans.shared.b16 {%0,%1,%2,%3}, [%4];"
                 : "=r"(r[0]), "=r"(r[1]), "=r"(r[2]), "=r"(r[3]) : "r"(addr));
}
__device__ __forceinline__ void mma_fp16(float* c, const uint32_t* a, const uint32_t* b) {
    asm volatile(
        "mma.sync.aligned.m16n8k16.row.col.f32.f16.f16.f32 "
        "{%0,%1,%2,%3}, {%4,%5,%6,%7}, {%8,%9}, {%0,%1,%2,%3};"
        : "+f"(c[0]), "+f"(c[1]), "+f"(c[2]), "+f"(c[3])
        : "r"(a[0]), "r"(a[1]), "r"(a[2]), "r"(a[3]), "r"(b[0]), "r"(b[1]));
}
__device__ __forceinline__ void cp_async16(uint32_t dst, const void* src) {
    asm volatile("cp.async.cg.shared.global [%0], [%1], 16;" :: "r"(dst), "l"(src));
}
#define CP_COMMIT() asm volatile("cp.async.commit_group;" ::: "memory")
#define CP_WAIT1()  asm volatile("cp.async.wait_group 1;"  ::: "memory")
#define CP_WAIT0()  asm volatile("cp.async.wait_group 0;"  ::: "memory")

__device__ __forceinline__ uint32_t pack_f16(float x, float y) {
    __half2 t = __floats2half2_rn(x, y);
    return *reinterpret_cast<uint32_t*>(&t);
}

// =================================================================
// Pool layer-1 GEMM (fp16, 1 term): pooled = adj(fp16) @ x(fp16).
// adj converted fp32->fp16 on the fly, streamed to g_adjH for layer 2.
// Output: pooled split to fp16 hi/lo (input to 3-term fp16 W1 GEMM).
// =================================================================
#define AH_BUF   18432
#define PB_OFF   36864
#define PB_STG   17408
#define POOL_SMEM 89088

__global__ __launch_bounds__(512)
void gemm_pool_convert(const float* __restrict__ A,
                       const __half* __restrict__ Bhi,
                       __half* __restrict__ adjHOut,
                       __half* __restrict__ outHi,
                       __half* __restrict__ outLo) {
    constexpr int NC = NN / 64;

    const size_t aOff = (size_t)blockIdx.y * NN * NN + (size_t)blockIdx.x * 128 * NN;
    const size_t bOff = (size_t)blockIdx.y * NN * DD;
    const size_t oOff = (size_t)blockIdx.y * NN * DD + (size_t)blockIdx.x * 128 * DD;
    A += aOff;
    adjHOut += aOff;
    Bhi += bOff;

    extern __shared__ char smem[];
    const uint32_t sbase = smem_u32(smem);

    const int tid  = threadIdx.x;
    const int lane = tid & 31;
    const int wid  = tid >> 5;
    const int wm   = wid & 3;
    const int wn   = wid >> 2;
    const int sub  = lane >> 3;
    const int r8   = lane & 7;

    const uint32_t rowA  = wm * 32 + (sub & 1) * 8 + r8;
    const uint32_t colA  = (sub >> 1) * 8;
    const uint32_t rowB8 = (sub & 1) * 8 + r8;
    const uint32_t colB  = wn * 32 + (sub >> 1) * 8;

    const int aRow[4] = { (tid) >> 4, (tid + 512) >> 4, (tid + 1024) >> 4, (tid + 1536) >> 4 };
    const int aSeg = tid & 15;

    float acc[2][4][4];
#pragma unroll
    for (int i = 0; i < 2; i++)
#pragma unroll
        for (int j = 0; j < 4; j++)
#pragma unroll
            for (int k = 0; k < 4; k++) acc[i][j][k] = 0.f;

    auto issueB = [&](int c) {
        const uint32_t sb = sbase + PB_OFF + (uint32_t)(c % 3) * PB_STG;
#pragma unroll
        for (int p = 0; p < 2; p++) {
            int i = tid + p * 512;
            int row = i >> 4, ch = i & 15;
            cp_async16(sb + row * 272 + ch * 16, Bhi + (size_t)(c * 64 + row) * DD + ch * 8);
        }
    };
    float4 aR[4];
    auto loadA = [&](int c) {
#pragma unroll
        for (int p = 0; p < 4; p++)
            aR[p] = *reinterpret_cast<const float4*>(A + (size_t)aRow[p] * NN + c * 64 + aSeg * 4);
    };
    auto convert = [&](int cc) {
        char* dhi = smem + (cc & 1) * AH_BUF;
#pragma unroll
        for (int p = 0; p < 4; p++) {
            float4 v = aR[p];
            uint2 hv;
            hv.x = pack_f16(v.x, v.y);
            hv.y = pack_f16(v.z, v.w);
            *reinterpret_cast<uint2*>(dhi + aRow[p] * 144 + aSeg * 8) = hv;
            *reinterpret_cast<uint2*>(adjHOut + (size_t)aRow[p] * NN + cc * 64 + aSeg * 4) = hv;
        }
    };

    loadA(0);
    issueB(0); CP_COMMIT();
    issueB(1); CP_COMMIT();
    convert(0);
    CP_WAIT1();
    __syncthreads();

    for (int c = 0; c < NC; c++) {
        if (c + 1 < NC) loadA(c + 1);
        if (c + 2 < NC) issueB(c + 2);
        CP_COMMIT();

        const uint32_t stA = sbase + (uint32_t)(c & 1) * AH_BUF;
        const uint32_t stB = sbase + PB_OFF + (uint32_t)(c % 3) * PB_STG;
#pragma unroll
        for (int ks = 0; ks < 4; ks++) {
            uint32_t ah[2][4], bh[2][4];
#pragma unroll
            for (int mb = 0; mb < 2; mb++) {
                uint32_t ad = stA + (rowA + mb * 16) * 144 + (ks * 16 + colA) * 2;
                ldsm_x4(ah[mb], ad);
            }
#pragma unroll
            for (int g = 0; g < 2; g++) {
                uint32_t bd = stB + (ks * 16 + rowB8) * 272 + (colB + g * 16) * 2;
                ldsm_x4_t(bh[g], bd);
            }
#pragma unroll
            for (int mb = 0; mb < 2; mb++)
#pragma unroll
                for (int nb = 0; nb < 4; nb++)
                    mma_fp16(acc[mb][nb], ah[mb], &bh[nb >> 1][(nb & 1) * 2]);
        }

        if (c + 1 < NC) convert(c + 1);

        CP_WAIT1();
        __syncthreads();
    }

    // epilogue: split to fp16 hi/lo
    const int er = lane >> 2;
    const int ec = (lane & 3) * 2;
#pragma unroll
    for (int mb = 0; mb < 2; mb++)
#pragma unroll
        for (int nb = 0; nb < 4; nb++) {
            int row = wm * 32 + mb * 16 + er;
            int col = wn * 32 + nb * 8 + ec;
            float2 v0 = make_float2(acc[mb][nb][0], acc[mb][nb][1]);
            float2 v1 = make_float2(acc[mb][nb][2], acc[mb][nb][3]);
            __half h0 = __float2half_rn(v0.x), h1 = __float2half_rn(v0.y);
            __half h2 = __float2half_rn(v1.x), h3 = __float2half_rn(v1.y);
            uint32_t hi0 = pack_f16(v0.x, v0.y);
            uint32_t hi1 = pack_f16(v1.x, v1.y);
            uint32_t lo0 = pack_f16(v0.x - __half2float(h0), v0.y - __half2float(h1));
            uint32_t lo1 = pack_f16(v1.x - __half2float(h2), v1.y - __half2float(h3));
            *reinterpret_cast<uint32_t*>(outHi + oOff + (size_t)row * DD + col) = hi0;
            *reinterpret_cast<uint32_t*>(outLo + oOff + (size_t)row * DD + col) = lo0;
            *reinterpret_cast<uint32_t*>(outHi + oOff + (size_t)(row + 8) * DD + col) = hi1;
            *reinterpret_cast<uint32_t*>(outLo + oOff + (size_t)(row + 8) * DD + col) = lo1;
        }
}

// =================================================================
// Unified fp16 GEMM. NTERMS==1: single-term (pool L2). NTERMS==3:
// split 3-term (W1 GEMM). BIASED fuses BN partials + fp32 out.
// =================================================================
template <int KA, int NTERMS, bool BIASED>
__global__ __launch_bounds__(512)
void gemm_f16(const __half* __restrict__ Ahi, const __half* __restrict__ Alo,
              const __half* __restrict__ Bhi, const __half* __restrict__ Blo,
              const float* __restrict__ bias,
              float* __restrict__ outF,
              __half* __restrict__ outHi, __half* __restrict__ outLo,
              float* __restrict__ pS, float* __restrict__ pQ) {
    constexpr int NC  = KA / 64;
    constexpr int NH  = (NTERMS == 3) ? 2 : 1;
    constexpr int A_SEC = 128 * 144;
    constexpr int B_SEC = 64 * 272;
    constexpr int OFF_B = NH * A_SEC;
    constexpr int STAGE = OFF_B + NH * B_SEC;
    constexpr int SBUF_OFF = 3 * STAGE;

    size_t aOff, bOff, oOff;
    if (KA == NN) {
        aOff = (size_t)blockIdx.y * NN * NN + (size_t)blockIdx.x * 128 * NN;
        bOff = (size_t)blockIdx.y * NN * DD;
        oOff = (size_t)blockIdx.y * NN * DD + (size_t)blockIdx.x * 128 * DD;
    } else {
        aOff = (size_t)blockIdx.x * 128 * DD;
        bOff = 0;
        oOff = (size_t)blockIdx.x * 128 * DD;
    }
    Ahi += aOff; if (NTERMS == 3) Alo += aOff;
    Bhi += bOff; if (NTERMS == 3) Blo += bOff;

    extern __shared__ char smem[];
    const uint32_t sbase = smem_u32(smem);

    const int tid  = threadIdx.x;
    const int lane = tid & 31;
    const int wid  = tid >> 5;
    const int wm   = wid & 3;
    const int wn   = wid >> 2;
    const int sub  = lane >> 3;
    const int r8   = lane & 7;

    const uint32_t rowA  = wm * 32 + (sub & 1) * 8 + r8;
    const uint32_t colA  = (sub >> 1) * 8;
    const uint32_t rowB8 = (sub & 1) * 8 + r8;
    const uint32_t colB  = wn * 32 + (sub >> 1) * 8;

    float acc[2][4][4];
#pragma unroll
    for (int i = 0; i < 2; i++)
#pragma unroll
        for (int j = 0; j < 4; j++)
#pragma unroll
            for (int k = 0; k < 4; k++) acc[i][j][k] = 0.f;

    auto issue = [&](int c, int stg) {
        if (c < NC) {
            const uint32_t sb = sbase + (uint32_t)stg * STAGE;
            const int k0 = c * 64;
#pragma unroll
            for (int p = 0; p < 2 * NH; p++) {
                int i = tid + p * 512;
                int half = i >> 10, rem = i & 1023, row = rem >> 3, ch = rem & 7;
                const __half* s = (half ? Alo : Ahi) + (size_t)row * KA + k0 + ch * 8;
                cp_async16(sb + half * A_SEC + row * 144 + ch * 16, s);
            }
#pragma unroll
            for (int p = 0; p < 2 * NH; p++) {
                int i = tid + p * 512;
                int half = i >> 10, rem = i & 1023, row = rem >> 4, ch = rem & 15;
                const __half* s = (half ? Blo : Bhi) + (size_t)(k0 + row) * DD + ch * 8;
                cp_async16(sb + OFF_B + half * B_SEC + row * 272 + ch * 16, s);
            }
        }
        CP_COMMIT();
    };

    issue(0, 0);
    issue(1, 1);
    CP_WAIT1();
    __syncthreads();

    for (int c = 0; c < NC; c++) {
        issue(c + 2, (c + 2) % 3);
        const uint32_t st = sbase + (uint32_t)(c % 3) * STAGE;

#pragma unroll
        for (int ks = 0; ks < 4; ks++) {
            uint32_t ah[2][4], al[2][4], bh[2][4], bl[2][4];
#pragma unroll
            for (int mb = 0; mb < 2; mb++) {
                uint32_t ad = st + (rowA + mb * 16) * 144 + (ks * 16 + colA) * 2;
                ldsm_x4(ah[mb], ad);
                if (NTERMS == 3) ldsm_x4(al[mb], ad + A_SEC);
            }
#pragma unroll
            for (int g = 0; g < 2; g++) {
                uint32_t bd = st + OFF_B + (ks * 16 + rowB8) * 272 + (colB + g * 16) * 2;
                ldsm_x4_t(bh[g], bd);
                if (NTERMS == 3) ldsm_x4_t(bl[g], bd + B_SEC);
            }
#pragma unroll
            for (int mb = 0; mb < 2; mb++)
#pragma unroll
                for (int nb = 0; nb < 4; nb++)
                    mma_fp16(acc[mb][nb], ah[mb], &bh[nb >> 1][(nb & 1) * 2]);
            if (NTERMS == 3) {
#pragma unroll
                for (int mb = 0; mb < 2; mb++)
#pragma unroll
                    for (int nb = 0; nb < 4; nb++)
                        mma_fp16(acc[mb][nb], ah[mb], &bl[nb >> 1][(nb & 1) * 2]);
#pragma unroll
                for (int mb = 0; mb < 2; mb++)
#pragma unroll
                    for (int nb = 0; nb < 4; nb++)
                        mma_fp16(acc[mb][nb], al[mb], &bh[nb >> 1][(nb & 1) * 2]);
            }
        }
        CP_WAIT1();
        __syncthreads();
    }

    const int er = lane >> 2;
    const int ec = (lane & 3) * 2;
    float s8[8], q8[8];
    if (BIASED) {
#pragma unroll
        for (int i = 0; i < 8; i++) { s8[i] = 0.f; q8[i] = 0.f; }
    }
#pragma unroll
    for (int mb = 0; mb < 2; mb++)
#pragma unroll
        for (int nb = 0; nb < 4; nb++) {
            int row = wm * 32 + mb * 16 + er;
            int col = wn * 32 + nb * 8 + ec;
            float2 v0 = make_float2(acc[mb][nb][0], acc[mb][nb][1]);
            float2 v1 = make_float2(acc[mb][nb][2], acc[mb][nb][3]);
            if (BIASED) {
                float bx = bias[col], by = bias[col + 1];
                v0.x += bx; v0.y += by; v1.x += bx; v1.y += by;
                s8[nb * 2 + 0] += v0.x + v1.x;
                s8[nb * 2 + 1] += v0.y + v1.y;
                q8[nb * 2 + 0] += v0.x * v0.x + v1.x * v1.x;
                q8[nb * 2 + 1] += v0.y * v0.y + v1.y * v1.y;
                *reinterpret_cast<float2*>(outF + oOff + (size_t)row * DD + col) = v0;
                *reinterpret_cast<float2*>(outF + oOff + (size_t)(row + 8) * DD + col) = v1;
            } else {
                __half h0 = __float2half_rn(v0.x), h1 = __float2half_rn(v0.y);
                __half h2 = __float2half_rn(v1.x), h3 = __float2half_rn(v1.y);
                uint32_t hi0 = pack_f16(v0.x, v0.y);
                uint32_t hi1 = pack_f16(v1.x, v1.y);
                uint32_t lo0 = pack_f16(v0.x - __half2float(h0), v0.y - __half2float(h1));
                uint32_t lo1 = pack_f16(v1.x - __half2float(h2), v1.y - __half2float(h3));
                *reinterpret_cast<uint32_t*>(outHi + oOff + (size_t)row * DD + col) = hi0;
                *reinterpret_cast<uint32_t*>(outLo + oOff + (size_t)row * DD + col) = lo0;
                *reinterpret_cast<uint32_t*>(outHi + oOff + (size_t)(row + 8) * DD + col) = hi1;
                *reinterpret_cast<uint32_t*>(outLo + oOff + (size_t)(row + 8) * DD + col) = lo1;
            }
        }

    if (BIASED) {
#pragma unroll
        for (int off = 4; off < 32; off <<= 1) {
#pragma unroll
            for (int i = 0; i < 8; i++) {
                s8[i] += __shfl_xor_sync(0xFFFFFFFF, s8[i], off);
                q8[i] += __shfl_xor_sync(0xFFFFFFFF, q8[i], off);
            }
        }
        float* sBuf = reinterpret_cast<float*>(smem + SBUF_OFF);
        float* qBuf = sBuf + 4 * DD;
        if (lane < 4) {
#pragma unroll
            for (int nb = 0; nb < 4; nb++) {
#pragma unroll
                for (int j = 0; j < 2; j++) {
                    int col = wn * 32 + nb * 8 + lane * 2 + j;
                    sBuf[wm * DD + col] = s8[nb * 2 + j];
                    qBuf[wm * DD + col] = q8[nb * 2 + j];
                }
            }
        }
        __syncthreads();
        if (tid < DD) {
            float s = sBuf[tid] + sBuf[DD + tid] + sBuf[2 * DD + tid] + sBuf[3 * DD + tid];
            float q = qBuf[tid] + qBuf[DD + tid] + qBuf[2 * DD + tid] + qBuf[3 * DD + tid];
            pS[blockIdx.x * DD + tid] = s;
            pQ[blockIdx.x * DD + tid] = q;
        }
    }
}

// =================================================================
// W2 GEMM with fused inner-BN (fp16 version of R9).
// =================================================================
#define W2_AB    36864
#define W2_BOFF  73728
#define W2_BSTG  34816
#define W2_AUX   143360
#define W2_RED   144384
#define W2_SMEM  148480

__global__ __launch_bounds__(512)
void gemm_w2_fused(const float* __restrict__ Az,
                   const __half* __restrict__ Bhi,
                   const __half* __restrict__ Blo,
                   const float* __restrict__ bias,
                   const float* __restrict__ gamma, const float* __restrict__ beta,
                   const float* __restrict__ pSin, const float* __restrict__ pQin,
                   float* __restrict__ outF,
                   float* __restrict__ pSout, float* __restrict__ pQout) {
    const size_t aOff = (size_t)blockIdx.x * 128 * DD;
    Az += aOff;

    extern __shared__ char smem[];
    const uint32_t sbase = smem_u32(smem);

    const int tid  = threadIdx.x;
    const int lane = tid & 31;
    const int wid  = tid >> 5;
    const int wm   = wid & 3;
    const int wn   = wid >> 2;
    const int sub  = lane >> 3;
    const int r8   = lane & 7;

    const uint32_t rowA  = wm * 32 + (sub & 1) * 8 + r8;
    const uint32_t colA  = (sub >> 1) * 8;
    const uint32_t rowB8 = (sub & 1) * 8 + r8;
    const uint32_t colB  = wn * 32 + (sub >> 1) * 8;

    const int aRow[4] = { (tid) >> 4, (tid + 512) >> 4, (tid + 1024) >> 4, (tid + 1536) >> 4 };
    const int aSeg = tid & 15;

    float acc[2][4][4];
#pragma unroll
    for (int i = 0; i < 2; i++)
#pragma unroll
        for (int j = 0; j < 4; j++)
#pragma unroll
            for (int k = 0; k < 4; k++) acc[i][j][k] = 0.f;

    auto issueB = [&](int c) {
        const uint32_t sb = sbase + W2_BOFF + (uint32_t)(c & 1) * W2_BSTG;
#pragma unroll
        for (int p = 0; p < 4; p++) {
            int i = tid + p * 512;
            int half = i >> 10, rem = i & 1023, row = rem >> 4, ch = rem & 15;
            const __half* s = (half ? Blo : Bhi) + (size_t)(c * 64 + row) * DD + ch * 8;
            cp_async16(sb + half * 17408 + row * 272 + ch * 16, s);
        }
    };
    float4 aR[4];
    auto loadA = [&](int c) {
#pragma unroll
        for (int p = 0; p < 4; p++)
            aR[p] = *reinterpret_cast<const float4*>(Az + (size_t)aRow[p] * DD + c * 64 + aSeg * 4);
    };
    float* scl = reinterpret_cast<float*>(smem + W2_AUX);
    float* shf = scl + DD;
    auto convertBN = [&](int cc) {
        char* dhi = smem + (cc & 1) * W2_AB;
        char* dlo = dhi + 18432;
        const int col0 = cc * 64 + aSeg * 4;
        float4 sc = *reinterpret_cast<const float4*>(&scl[col0]);
        float4 sh = *reinterpret_cast<const float4*>(&shf[col0]);
#pragma unroll
        for (int p = 0; p < 4; p++) {
            float4 v = aR[p];
            float4 r;
            r.x = fmaxf(fmaf(v.x, sc.x, sh.x), 0.f);
            r.y = fmaxf(fmaf(v.y, sc.y, sh.y), 0.f);
            r.z = fmaxf(fmaf(v.z, sc.z, sh.z), 0.f);
            r.w = fmaxf(fmaf(v.w, sc.w, sh.w), 0.f);
            __half h0 = __float2half_rn(r.x), h1 = __float2half_rn(r.y);
            __half h2 = __float2half_rn(r.z), h3 = __float2half_rn(r.w);
            uint2 hv, lv;
            hv.x = pack_f16(r.x, r.y); hv.y = pack_f16(r.z, r.w);
            lv.x = pack_f16(r.x - __half2float(h0), r.y - __half2float(h1));
            lv.y = pack_f16(r.z - __half2float(h2), r.w - __half2float(h3));
            *reinterpret_cast<uint2*>(dhi + aRow[p] * 144 + aSeg * 8) = hv;
            *reinterpret_cast<uint2*>(dlo + aRow[p] * 144 + aSeg * 8) = lv;
        }
    };

    issueB(0); CP_COMMIT();
    issueB(1); CP_COMMIT();
    loadA(0);

    {
        float* rS = reinterpret_cast<float*>(smem + W2_RED);
        float* rQ = rS + 4 * DD;
        const int col = tid & 127, grp = tid >> 7;
        float s = 0.f, q = 0.f;
        for (int p = grp; p < BN_BLOCKS; p += 4) {
            s += pSin[p * DD + col];
            q += pQin[p * DD + col];
        }
        rS[grp * DD + col] = s;
        rQ[grp * DD + col] = q;
        __syncthreads();
        if (tid < DD) {
            float S = rS[tid] + rS[DD + tid] + rS[2 * DD + tid] + rS[3 * DD + tid];
            float Q = rQ[tid] + rQ[DD + tid] + rQ[2 * DD + tid] + rQ[3 * DD + tid];
            const float inv_m = 1.0f / (float)MTOT;
            float mean = S * inv_m;
            float var  = Q * inv_m - mean * mean;
            float sc   = gamma[tid] * rsqrtf(var + BN_EPS);
            scl[tid] = sc;
            shf[tid] = beta[tid] - mean * sc;
        }
        __syncthreads();
    }

    convertBN(0);
    CP_WAIT1();
    __syncthreads();

    loadA(1);

    {
        const uint32_t stA = sbase;
        const uint32_t stB = sbase + W2_BOFF;
#pragma unroll
        for (int ks = 0; ks < 4; ks++) {
            uint32_t ah[2][4], al[2][4], bh[2][4], bl[2][4];
#pragma unroll
            for (int mb = 0; mb < 2; mb++) {
                uint32_t ad = stA + (rowA + mb * 16) * 144 + (ks * 16 + colA) * 2;
                ldsm_x4(ah[mb], ad);
                ldsm_x4(al[mb], ad + 18432);
            }
#pragma unroll
            for (int g = 0; g < 2; g++) {
                uint32_t bd = stB + (ks * 16 + rowB8) * 272 + (colB + g * 16) * 2;
                ldsm_x4_t(bh[g], bd);
                ldsm_x4_t(bl[g], bd + 17408);
            }
#pragma unroll
            for (int mb = 0; mb < 2; mb++)
#pragma unroll
                for (int nb = 0; nb < 4; nb++)
                    mma_fp16(acc[mb][nb], ah[mb], &bh[nb >> 1][(nb & 1) * 2]);
#pragma unroll
            for (int mb = 0; mb < 2; mb++)
#pragma unroll
                for (int nb = 0; nb < 4; nb++)
                    mma_fp16(acc[mb][nb], ah[mb], &bl[nb >> 1][(nb & 1) * 2]);
#pragma unroll
            for (int mb = 0; mb < 2; mb++)
#pragma unroll
                for (int nb = 0; nb < 4; nb++)
                    mma_fp16(acc[mb][nb], al[mb], &bh[nb >> 1][(nb & 1) * 2]);
        }
    }

    convertBN(1);
    CP_WAIT0();
    __syncthreads();

    {
        const uint32_t stA = sbase + W2_AB;
        const uint32_t stB = sbase + W2_BOFF + W2_BSTG;
#pragma unroll
        for (int ks = 0; ks < 4; ks++) {
            uint32_t ah[2][4], al[2][4], bh[2][4], bl[2][4];
#pragma unroll
            for (int mb = 0; mb < 2; mb++) {
                uint32_t ad = stA + (rowA + mb * 16) * 144 + (ks * 16 + colA) * 2;
                ldsm_x4(ah[mb], ad);
                ldsm_x4(al[mb], ad + 18432);
            }
#pragma unroll
            for (int g = 0; g < 2; g++) {
                uint32_t bd = stB + (ks * 16 + rowB8) * 272 + (colB + g * 16) * 2;
                ldsm_x4_t(bh[g], bd);
                ldsm_x4_t(bl[g], bd + 17408);
            }
#pragma unroll
            for (int mb = 0; mb < 2; mb++)
#pragma unroll
                for (int nb = 0; nb < 4; nb++)
                    mma_fp16(acc[mb][nb], ah[mb], &bh[nb >> 1][(nb & 1) * 2]);
#pragma unroll
            for (int mb = 0; mb < 2; mb++)
#pragma unroll
                for (int nb = 0; nb < 4; nb++)
                    mma_fp16(acc[mb][nb], ah[mb], &bl[nb >> 1][(nb & 1) * 2]);
#pragma unroll
            for (int mb = 0; mb < 2; mb++)
#pragma unroll
                for (int nb = 0; nb < 4; nb++)
                    mma_fp16(acc[mb][nb], al[mb], &bh[nb >> 1][(nb & 1) * 2]);
        }
    }
    __syncthreads();

    const int er = lane >> 2;
    const int ec = (lane & 3) * 2;
    float s8[8], q8[8];
#pragma unroll
    for (int i = 0; i < 8; i++) { s8[i] = 0.f; q8[i] = 0.f; }
#pragma unroll
    for (int mb = 0; mb < 2; mb++)
#pragma unroll
        for (int nb = 0; nb < 4; nb++) {
            int row = wm * 32 + mb * 16 + er;
            int col = wn * 32 + nb * 8 + ec;
            float2 v0 = make_float2(acc[mb][nb][0], acc[mb][nb][1]);
            float2 v1 = make_float2(acc[mb][nb][2], acc[mb][nb][3]);
            float bx = bias[col], by = bias[col + 1];
            v0.x += bx; v0.y += by; v1.x += bx; v1.y += by;
            s8[nb * 2 + 0] += v0.x + v1.x;
            s8[nb * 2 + 1] += v0.y + v1.y;
            q8[nb * 2 + 0] += v0.x * v0.x + v1.x * v1.x;
            q8[nb * 2 + 1] += v0.y * v0.y + v1.y * v1.y;
            *reinterpret_cast<float2*>(outF + aOff + (size_t)row * DD + col) = v0;
            *reinterpret_cast<float2*>(outF + aOff + (size_t)(row + 8) * DD + col) = v1;
        }

#pragma unroll
    for (int off = 4; off < 32; off <<= 1) {
#pragma unroll
        for (int i = 0; i < 8; i++) {
            s8[i] += __shfl_xor_sync(0xFFFFFFFF, s8[i], off);
            q8[i] += __shfl_xor_sync(0xFFFFFFFF, q8[i], off);
        }
    }
    float* sBuf = reinterpret_cast<float*>(smem + W2_RED);
    float* qBuf = sBuf + 4 * DD;
    if (lane < 4) {
#pragma unroll
        for (int nb = 0; nb < 4; nb++) {
#pragma unroll
            for (int j = 0; j < 2; j++) {
                int col = wn * 32 + nb * 8 + lane * 2 + j;
                sBuf[wm * DD + col] = s8[nb * 2 + j];
                qBuf[wm * DD + col] = q8[nb * 2 + j];
            }
        }
    }
    __syncthreads();
    if (tid < DD) {
        float s = sBuf[tid] + sBuf[DD + tid] + sBuf[2 * DD + tid] + sBuf[3 * DD + tid];
        float q = qBuf[tid] + qBuf[DD + tid] + qBuf[2 * DD + tid] + qBuf[3 * DD + tid];
        pSout[blockIdx.x * DD + tid] = s;
        pQout[blockIdx.x * DD + tid] = q;
    }
}

// ---------------- fp32 -> (hi, lo) fp16 split (weights) ----------------
__global__ __launch_bounds__(256)
void split_half_kernel(const float* __restrict__ src,
                       __half* __restrict__ hi, __half* __restrict__ lo) {
    const size_t idx = (size_t)blockIdx.x * 256 + threadIdx.x;
    float4 v = reinterpret_cast<const float4*>(src)[idx];
    __half h0 = __float2half_rn(v.x), h1 = __float2half_rn(v.y);
    __half h2 = __float2half_rn(v.z), h3 = __float2half_rn(v.w);
    uint2 hv, lv;
    hv.x = pack_f16(v.x, v.y); hv.y = pack_f16(v.z, v.w);
    lv.x = pack_f16(v.x - __half2float(h0), v.y - __half2float(h1));
    lv.y = pack_f16(v.z - __half2float(h2), v.w - __half2float(h3));
    reinterpret_cast<uint2*>(hi)[idx] = hv;
    reinterpret_cast<uint2*>(lo)[idx] = lv;
}

// ---------------- fp32 -> fp16 convert (x, hi only) ----------------
__global__ __launch_bounds__(256)
void convert_half_kernel(const float* __restrict__ src, __half* __restrict__ hi) {
    const size_t idx = (size_t)blockIdx.x * 256 + threadIdx.x;
    float4 v = reinterpret_cast<const float4*>(src)[idx];
    uint2 hv;
    hv.x = pack_f16(v.x, v.y); hv.y = pack_f16(v.z, v.w);
    reinterpret_cast<uint2*>(hi)[idx] = hv;
}

// =================================================================
// Outer-BN stats+apply. MODE 0: fp16 hi (feeds 1-term fp16 pool).
// MODE 1: fp32 final output.
// =================================================================
template <int MODE>
__global__ __launch_bounds__(256)
void bn_stats_apply(const float* __restrict__ gamma, const float* __restrict__ beta,
                    const float* __restrict__ pS, const float* __restrict__ pQ,
                    const float* __restrict__ x,
                    float* __restrict__ outF, __half* __restrict__ yhi) {
    __shared__ float sS[2][DD], sQ[2][DD];
    __shared__ float scl[DD], shf[DD];
    const int tid  = threadIdx.x;
    const int col  = tid & 127;
    const int half = tid >> 7;

    float s = 0.f, q = 0.f;
    for (int p = half; p < BN_BLOCKS; p += 2) {
        s += pS[p * DD + col];
        q += pQ[p * DD + col];
    }
    sS[half][col] = s;
    sQ[half][col] = q;
    __syncthreads();
    if (tid < DD) {
        float S = sS[0][tid] + sS[1][tid];
        float Q = sQ[0][tid] + sQ[1][tid];
        const float inv_m = 1.0f / (float)MTOT;
        float mean = S * inv_m;
        float var  = Q * inv_m - mean * mean;
        float sc   = gamma[tid] * rsqrtf(var + BN_EPS);
        scl[tid] = sc;
        shf[tid] = beta[tid] - mean * sc;
    }
    __syncthreads();

    const int base = blockIdx.x * 8192;
#pragma unroll 8
    for (int i = 0; i < 32; i++) {
        int idx = base + i * 256 + tid;
        int c4  = idx & 31;
        float4 v = reinterpret_cast<const float4*>(x)[idx];
        float4 sc = *reinterpret_cast<const float4*>(&scl[c4 * 4]);
        float4 sh = *reinterpret_cast<const float4*>(&shf[c4 * 4]);
        float4 r;
        r.x = fmaxf(fmaf(v.x, sc.x, sh.x), 0.f);
        r.y = fmaxf(fmaf(v.y, sc.y, sh.y), 0.f);
        r.z = fmaxf(fmaf(v.z, sc.z, sh.z), 0.f);
        r.w = fmaxf(fmaf(v.w, sc.w, sh.w), 0.f);
        if (MODE == 1) {
            reinterpret_cast<float4*>(outF)[idx] = r;
        } else {
            uint2 hv;
            hv.x = pack_f16(r.x, r.y); hv.y = pack_f16(r.z, r.w);
            reinterpret_cast<uint2*>(yhi)[idx] = hv;
        }
    }
}

// ---------------- launch ----------------
extern "C" void kernel_launch(void* const* d_in, const int* in_sizes, int n_in,
                              void* d_out, int out_size) {
    const float* x     = (const float*)d_in[0];
    const float* adj   = (const float*)d_in[2];
    const float* W1    = (const float*)d_in[3];
    const float* b1    = (const float*)d_in[4];
    const float* W2    = (const float*)d_in[5];
    const float* b2    = (const float*)d_in[6];
    const float* g_in   = (const float*)d_in[7];
    const float* be_in  = (const float*)d_in[8];
    const float* g_out  = (const float*)d_in[9];
    const float* be_out = (const float*)d_in[10];
    float* out = (float*)d_out;

    __half *adjH, *hHi, *pHi, *pLo, *W1Hi, *W1Lo, *W2Hi, *W2Lo;
    float *z, *pS1, *pQ1, *pS2, *pQ2;
    cudaGetSymbolAddress((void**)&adjH, g_adjH);
    cudaGetSymbolAddress((void**)&hHi, g_hHi);
    cudaGetSymbolAddress((void**)&pHi, g_pHi);
    cudaGetSymbolAddress((void**)&pLo, g_pLo);
    cudaGetSymbolAddress((void**)&W1Hi, g_W1Hi);
    cudaGetSymbolAddress((void**)&W1Lo, g_W1Lo);
    cudaGetSymbolAddress((void**)&W2Hi, g_W2Hi);
    cudaGetSymbolAddress((void**)&W2Lo, g_W2Lo);
    cudaGetSymbolAddress((void**)&z, g_z);
    cudaGetSymbolAddress((void**)&pS1, g_partS1);
    cudaGetSymbolAddress((void**)&pQ1, g_partQ1);
    cudaGetSymbolAddress((void**)&pS2, g_partS2);
    cudaGetSymbolAddress((void**)&pQ2, g_partQ2);

    constexpr int SMEM3B = 3 * (2 * 128 * 144 + 2 * 64 * 272) + 4096;  // 219136
    constexpr int SMEM1  = 3 * (128 * 144 + 64 * 272);                 // 107520
    cudaFuncSetAttribute((const void*)gemm_pool_convert,
                         cudaFuncAttributeMaxDynamicSharedMemorySize, POOL_SMEM);
    cudaFuncSetAttribute((const void*)gemm_f16<NN, 1, false>,
                         cudaFuncAttributeMaxDynamicSharedMemorySize, SMEM1);
    cudaFuncSetAttribute((const void*)gemm_f16<DD, 3, true>,
                         cudaFuncAttributeMaxDynamicSharedMemorySize, SMEM3B);
    cudaFuncSetAttribute((const void*)gemm_w2_fused,
                         cudaFuncAttributeMaxDynamicSharedMemorySize, W2_SMEM);

    convert_half_kernel<<<MTOT * DD / 1024, 256>>>(x, hHi);
    split_half_kernel<<<LL * DD * DD / 1024, 256>>>(W1, W1Hi, W1Lo);
    split_half_kernel<<<LL * DD * DD / 1024, 256>>>(W2, W2Hi, W2Lo);

    const dim3 gridPool(NN / 128, BATCH);
    const int  gridW = MTOT / 128;

    for (int l = 0; l < LL; l++) {
        if (l == 0)
            gemm_pool_convert<<<gridPool, 512, POOL_SMEM>>>(
                adj, hHi, adjH, pHi, pLo);
        else
            gemm_f16<NN, 1, false><<<gridPool, 512, SMEM1>>>(
                adjH, nullptr, hHi, nullptr,
                nullptr, nullptr, pHi, pLo, nullptr, nullptr);

        gemm_f16<DD, 3, true><<<gridW, 512, SMEM3B>>>(
            pHi, pLo, W1Hi + (size_t)l * DD * DD, W1Lo + (size_t)l * DD * DD,
            b1 + (size_t)l * DD, z, nullptr, nullptr, pS1, pQ1);

        gemm_w2_fused<<<gridW, 512, W2_SMEM>>>(
            z, W2Hi + (size_t)l * DD * DD, W2Lo + (size_t)l * DD * DD,
            b2 + (size_t)l * DD, g_in + (size_t)l * DD, be_in + (size_t)l * DD,
            pS1, pQ1, z, pS2, pQ2);

        if (l == LL - 1)
            bn_stats_apply<1><<<128, 256>>>(
                g_out + (size_t)l * DD, be_out + (size_t)l * DD, pS2, pQ2,
                z, out, nullptr);
        else
            bn_stats_apply<0><<<128, 256>>>(
                g_out + (size_t)l * DD, be_out + (size_t)l * DD, pS2, pQ2,
                z, nullptr, hHi);
    }
}